// round 1
// baseline (speedup 1.0000x reference)
#include <cuda_runtime.h>
#include <math.h>

#define LQ   2048
#define CD   2048
#define HN   16
#define DD   128
#define KVL  4096

// ---------------- scratch (device globals; no allocation) ----------------
__device__ float gQ [LQ  * CD];   // Q projection, then normed+roped
__device__ float gK [KVL * CD];   // K concat [h0-proj | h1-proj], normed+roped
__device__ float gV [KVL * CD];   // V concat
__device__ float gAO[LQ  * CD];   // attention output
__device__ float gO [LQ  * CD];   // Wo projection
__device__ float gPH[LQ  * CD];   // sin position features
__device__ float gPS[LQ  * CD];   // position embedding (PH @ sw2 + sb2)

// ---------------- generic SGEMM ----------------
// C[m,n] = sum_k A[m,k] * (BT ? B[n,k] : B[k,n])   (+ bias[n] if BIAS)
// 128x128 tile, BK=8, 8x8 per thread, 256 threads.
template<bool BT, bool BIAS>
__global__ __launch_bounds__(256) void sgemm(
    const float* __restrict__ A, const float* __restrict__ B,
    const float* __restrict__ bias, float* __restrict__ Cc,
    int M, int N, int K)
{
    __shared__ float As[8][128];
    __shared__ float Bs[8][128];
    const int tid = threadIdx.x;
    const int tx = tid & 15, ty = tid >> 4;
    const int bm = blockIdx.y * 128, bn = blockIdx.x * 128;

    float acc[8][8];
#pragma unroll
    for (int i = 0; i < 8; i++)
#pragma unroll
        for (int j = 0; j < 8; j++) acc[i][j] = 0.f;

    const int lrow = tid >> 1;         // 0..127
    const int lcol = (tid & 1) * 4;    // 0 / 4
    const int bkr  = tid >> 5;         // 0..7   (NN path)
    const int bnc  = (tid & 31) * 4;   // 0..124 (NN path)

    for (int k0 = 0; k0 < K; k0 += 8) {
        float4 av = *(const float4*)(A + (size_t)(bm + lrow) * K + k0 + lcol);
        As[lcol + 0][lrow] = av.x; As[lcol + 1][lrow] = av.y;
        As[lcol + 2][lrow] = av.z; As[lcol + 3][lrow] = av.w;
        if (BT) {
            float4 bv = *(const float4*)(B + (size_t)(bn + lrow) * K + k0 + lcol);
            Bs[lcol + 0][lrow] = bv.x; Bs[lcol + 1][lrow] = bv.y;
            Bs[lcol + 2][lrow] = bv.z; Bs[lcol + 3][lrow] = bv.w;
        } else {
            float4 bv = *(const float4*)(B + (size_t)(k0 + bkr) * N + bn + bnc);
            *(float4*)&Bs[bkr][bnc] = bv;
        }
        __syncthreads();
#pragma unroll
        for (int k = 0; k < 8; k++) {
            float ra[8], rb[8];
            *(float4*)&ra[0] = *(float4*)&As[k][ty * 8];
            *(float4*)&ra[4] = *(float4*)&As[k][ty * 8 + 4];
            *(float4*)&rb[0] = *(float4*)&Bs[k][tx * 4];        // cols tx*4..+3
            *(float4*)&rb[4] = *(float4*)&Bs[k][64 + tx * 4];   // cols 64+tx*4..+3
#pragma unroll
            for (int i = 0; i < 8; i++)
#pragma unroll
                for (int j = 0; j < 8; j++)
                    acc[i][j] += ra[i] * rb[j];
        }
        __syncthreads();
    }
#pragma unroll
    for (int i = 0; i < 8; i++) {
        const int row = bm + ty * 8 + i;
        float4 v0 = make_float4(acc[i][0], acc[i][1], acc[i][2], acc[i][3]);
        float4 v1 = make_float4(acc[i][4], acc[i][5], acc[i][6], acc[i][7]);
        if (BIAS) {
            float4 b0 = *(const float4*)(bias + bn + tx * 4);
            float4 b1 = *(const float4*)(bias + bn + 64 + tx * 4);
            v0.x += b0.x; v0.y += b0.y; v0.z += b0.z; v0.w += b0.w;
            v1.x += b1.x; v1.y += b1.y; v1.z += b1.z; v1.w += b1.w;
        }
        *(float4*)(Cc + (size_t)row * N + bn + tx * 4)      = v0;
        *(float4*)(Cc + (size_t)row * N + bn + 64 + tx * 4) = v1;
    }
}

// ---------------- per-(row,head) rmsnorm + depth rope ----------------
__global__ __launch_bounds__(128) void normrope(
    float* __restrict__ buf, const float* __restrict__ w, float depth)
{
    const int row = blockIdx.x;
    const int h   = blockIdx.y;
    float* p = buf + (size_t)row * CD + h * DD;
    const int d = threadIdx.x;

    float v  = p[d];
    float sq = v * v;
#pragma unroll
    for (int o = 16; o > 0; o >>= 1) sq += __shfl_xor_sync(0xffffffffu, sq, o);
    __shared__ float ws[4];
    if ((d & 31) == 0) ws[d >> 5] = sq;
    __syncthreads();
    const float total = ws[0] + ws[1] + ws[2] + ws[3];
    const float rn = rsqrtf(total * (1.f / 128.f) + 1e-6f);

    __shared__ float sn[128];
    sn[d] = v * rn * w[d];
    __syncthreads();

    float out;
    if (d < 64) {
        float ang = depth * powf(10000.f, -(float)d * (1.f / 64.f));
        out = sn[d] * cosf(ang) - sn[d + 64] * sinf(ang);
    } else {
        int i = d - 64;
        float ang = depth * powf(10000.f, -(float)i * (1.f / 64.f));
        out = sn[i] * sinf(ang) + sn[d] * cosf(ang);
    }
    p[d] = out;
}

// ---------------- flash attention (fp32, online softmax) ----------------
// Block = (q-tile of 64, head). 256 threads (16x16), 4x4 scores, 4x8 output
// per thread. Qs/Ks stored transposed [d][m] for conflict-free S GEMM.
__global__ __launch_bounds__(256) void flash(
    const float* __restrict__ Qg, const float* __restrict__ Kg,
    const float* __restrict__ Vg, float* __restrict__ Og)
{
    extern __shared__ float sm[];
    float* Qs = sm;                  // [128][68] transposed
    float* Ks = Qs + 128 * 68;       // [128][68] transposed
    float* Vs = Ks + 128 * 68;       // [64][132] natural
    float* Ps = Vs + 64 * 132;       // [64][68]  probs [m][n]

    const int tid = threadIdx.x;
    const int tx = tid & 15, ty = tid >> 4;
    const int h  = blockIdx.y;
    const int q0 = blockIdx.x * 64;
    const int hD = h * DD;
    const float scale = 0.08838834764831845f;   // 1/sqrt(128)

    // load Q tile transposed (scaled)
    {
        const int m  = tid >> 2;
        const int dl = (tid & 3) << 2;
#pragma unroll
        for (int pp = 0; pp < 8; pp++) {
            const int d = pp * 16 + dl;
            float4 v = *(const float4*)(Qg + (size_t)(q0 + m) * CD + hD + d);
            Qs[(d + 0) * 68 + m] = v.x * scale;
            Qs[(d + 1) * 68 + m] = v.y * scale;
            Qs[(d + 2) * 68 + m] = v.z * scale;
            Qs[(d + 3) * 68 + m] = v.w * scale;
        }
    }

    float mI[4], lI[4], acc[4][8];
#pragma unroll
    for (int i = 0; i < 4; i++) {
        mI[i] = -1e30f; lI[i] = 0.f;
#pragma unroll
        for (int c = 0; c < 8; c++) acc[i][c] = 0.f;
    }

    for (int k0 = 0; k0 < KVL; k0 += 64) {
        __syncthreads();   // previous iteration done with Ks/Vs/Ps
        {
            const int n  = tid >> 2;
            const int dl = (tid & 3) << 2;
#pragma unroll
            for (int pp = 0; pp < 8; pp++) {
                const int d = pp * 16 + dl;
                float4 v = *(const float4*)(Kg + (size_t)(k0 + n) * CD + hD + d);
                Ks[(d + 0) * 68 + n] = v.x;
                Ks[(d + 1) * 68 + n] = v.y;
                Ks[(d + 2) * 68 + n] = v.z;
                Ks[(d + 3) * 68 + n] = v.w;
                float4 w = *(const float4*)(Vg + (size_t)(k0 + n) * CD + hD + d);
                *(float4*)&Vs[n * 132 + d] = w;
            }
        }
        __syncthreads();

        // S = Qs^T * Ks : 4x4 per thread
        float s[4][4];
#pragma unroll
        for (int i = 0; i < 4; i++)
#pragma unroll
            for (int j = 0; j < 4; j++) s[i][j] = 0.f;
#pragma unroll 16
        for (int d = 0; d < 128; d++) {
            float4 qv = *(const float4*)&Qs[d * 68 + ty * 4];
            float4 kv = *(const float4*)&Ks[d * 68 + tx * 4];
            s[0][0] += qv.x * kv.x; s[0][1] += qv.x * kv.y; s[0][2] += qv.x * kv.z; s[0][3] += qv.x * kv.w;
            s[1][0] += qv.y * kv.x; s[1][1] += qv.y * kv.y; s[1][2] += qv.y * kv.z; s[1][3] += qv.y * kv.w;
            s[2][0] += qv.z * kv.x; s[2][1] += qv.z * kv.y; s[2][2] += qv.z * kv.z; s[2][3] += qv.z * kv.w;
            s[3][0] += qv.w * kv.x; s[3][1] += qv.w * kv.y; s[3][2] += qv.w * kv.z; s[3][3] += qv.w * kv.w;
        }

        // online softmax (row reduce over 16 lanes sharing ty)
        float pr[4][4];
#pragma unroll
        for (int i = 0; i < 4; i++) {
            float rmax = fmaxf(fmaxf(s[i][0], s[i][1]), fmaxf(s[i][2], s[i][3]));
            rmax = fmaxf(rmax, __shfl_xor_sync(0xffffffffu, rmax, 1));
            rmax = fmaxf(rmax, __shfl_xor_sync(0xffffffffu, rmax, 2));
            rmax = fmaxf(rmax, __shfl_xor_sync(0xffffffffu, rmax, 4));
            rmax = fmaxf(rmax, __shfl_xor_sync(0xffffffffu, rmax, 8));
            const float mn    = fmaxf(mI[i], rmax);
            const float alpha = __expf(mI[i] - mn);
            float rsum = 0.f;
#pragma unroll
            for (int j = 0; j < 4; j++) { pr[i][j] = __expf(s[i][j] - mn); rsum += pr[i][j]; }
            rsum += __shfl_xor_sync(0xffffffffu, rsum, 1);
            rsum += __shfl_xor_sync(0xffffffffu, rsum, 2);
            rsum += __shfl_xor_sync(0xffffffffu, rsum, 4);
            rsum += __shfl_xor_sync(0xffffffffu, rsum, 8);
            lI[i] = lI[i] * alpha + rsum;
            mI[i] = mn;
#pragma unroll
            for (int c = 0; c < 8; c++) acc[i][c] *= alpha;
        }
#pragma unroll
        for (int i = 0; i < 4; i++)
#pragma unroll
            for (int j = 0; j < 4; j++)
                Ps[(ty * 4 + i) * 68 + tx * 4 + j] = pr[i][j];
        __syncthreads();

        // O += P @ V
#pragma unroll 8
        for (int n = 0; n < 64; n++) {
            float4 v0 = *(const float4*)&Vs[n * 132 + tx * 4];
            float4 v1 = *(const float4*)&Vs[n * 132 + 64 + tx * 4];
            float pv[4];
#pragma unroll
            for (int i = 0; i < 4; i++) pv[i] = Ps[(ty * 4 + i) * 68 + n];
#pragma unroll
            for (int i = 0; i < 4; i++) {
                const float p = pv[i];
                acc[i][0] += p * v0.x; acc[i][1] += p * v0.y;
                acc[i][2] += p * v0.z; acc[i][3] += p * v0.w;
                acc[i][4] += p * v1.x; acc[i][5] += p * v1.y;
                acc[i][6] += p * v1.z; acc[i][7] += p * v1.w;
            }
        }
    }

#pragma unroll
    for (int i = 0; i < 4; i++) {
        const float inv = 1.f / lI[i];
        const int row = q0 + ty * 4 + i;
        float4 o0 = make_float4(acc[i][0] * inv, acc[i][1] * inv, acc[i][2] * inv, acc[i][3] * inv);
        float4 o1 = make_float4(acc[i][4] * inv, acc[i][5] * inv, acc[i][6] * inv, acc[i][7] * inv);
        *(float4*)(Og + (size_t)row * CD + hD + tx * 4)      = o0;
        *(float4*)(Og + (size_t)row * CD + hD + 64 + tx * 4) = o1;
    }
}

// ---------------- position features: sin(W0*(coord*sw1 + sb1)) ----------------
__global__ __launch_bounds__(256) void pos_hidden(
    float* __restrict__ ph, const float* __restrict__ sw1, const float* __restrict__ sb1)
{
    const int idx = blockIdx.x * 256 + threadIdx.x;
    const int l = idx >> 11;
    const int c = idx & 2047;
    const float coord = -1.f + 2.f * (float)l / 2047.f;
    ph[idx] = sinf(30.f * (coord * sw1[c] + sb1[c]));
}

// ---------------- final: out = x + rmsnorm(O + pos, on_w) ----------------
__global__ __launch_bounds__(256) void fuse_out(
    const float* __restrict__ x, const float* __restrict__ ov,
    const float* __restrict__ pos, const float* __restrict__ w,
    float* __restrict__ out)
{
    __shared__ float t[2048];
    __shared__ float red[8];
    const int l = blockIdx.x;
    const int tid = threadIdx.x;
    float sq = 0.f;
    for (int c = tid; c < 2048; c += 256) {
        const float v = ov[(size_t)l * 2048 + c] + pos[(size_t)l * 2048 + c];
        t[c] = v; sq += v * v;
    }
#pragma unroll
    for (int o = 16; o > 0; o >>= 1) sq += __shfl_xor_sync(0xffffffffu, sq, o);
    if ((tid & 31) == 0) red[tid >> 5] = sq;
    __syncthreads();
    float total = 0.f;
#pragma unroll
    for (int i = 0; i < 8; i++) total += red[i];
    const float rn = rsqrtf(total * (1.f / 2048.f) + 1e-6f);
    for (int c = tid; c < 2048; c += 256)
        out[(size_t)l * 2048 + c] = x[(size_t)l * 2048 + c] + t[c] * rn * w[c];
}

// ---------------- launch ----------------
extern "C" void kernel_launch(void* const* d_in, const int* in_sizes, int n_in,
                              void* d_out, int out_size)
{
    (void)in_sizes; (void)n_in; (void)out_size;
    const float* x   = (const float*)d_in[0];
    const float* h0  = (const float*)d_in[1];
    const float* h1  = (const float*)d_in[2];
    const float* h2  = (const float*)d_in[3];
    const float* Wq  = (const float*)d_in[4];
    const float* Wk  = (const float*)d_in[5];
    const float* Wv  = (const float*)d_in[6];
    const float* Wo  = (const float*)d_in[7];
    const float* qn  = (const float*)d_in[8];
    const float* kn  = (const float*)d_in[9];
    const float* on  = (const float*)d_in[10];
    const float* sw1 = (const float*)d_in[11];
    const float* sb1 = (const float*)d_in[12];
    const float* sw2 = (const float*)d_in[13];
    const float* sb2 = (const float*)d_in[14];
    float* out = (float*)d_out;

    float *Q, *K, *V, *AO, *O, *PH, *PS;
    cudaGetSymbolAddress((void**)&Q,  gQ);
    cudaGetSymbolAddress((void**)&K,  gK);
    cudaGetSymbolAddress((void**)&V,  gV);
    cudaGetSymbolAddress((void**)&AO, gAO);
    cudaGetSymbolAddress((void**)&O,  gO);
    cudaGetSymbolAddress((void**)&PH, gPH);
    cudaGetSymbolAddress((void**)&PS, gPS);

    const dim3 gg(16, 16);
    const size_t LC = (size_t)LQ * CD;

    // projections (all NT: C[m,n] = sum_k A[m,k]*W[n,k])
    sgemm<true,  false><<<gg, 256>>>(h2, Wq, nullptr, Q,            2048, 2048, 2048);
    sgemm<true,  false><<<gg, 256>>>(h0, Wk, nullptr, K,            2048, 2048, 2048);
    sgemm<true,  false><<<gg, 256>>>(h1, Wk, nullptr, K + LC,       2048, 2048, 2048);
    sgemm<true,  false><<<gg, 256>>>(h0, Wv, nullptr, V,            2048, 2048, 2048);
    sgemm<true,  false><<<gg, 256>>>(h1, Wv, nullptr, V + LC,       2048, 2048, 2048);

    const dim3 gn(LQ, HN);
    normrope<<<gn, 128>>>(Q,      qn, 2.f);
    normrope<<<gn, 128>>>(K,      kn, 0.f);
    normrope<<<gn, 128>>>(K + LC, kn, 1.f);

    const int FS = (128 * 68 + 128 * 68 + 64 * 132 + 64 * 68) * 4;  // ~118 KB
    cudaFuncSetAttribute(flash, cudaFuncAttributeMaxDynamicSharedMemorySize, FS);
    flash<<<dim3(32, 16), 256, FS>>>(Q, K, V, AO);

    sgemm<true,  false><<<gg, 256>>>(AO, Wo, nullptr, O, 2048, 2048, 2048);

    pos_hidden<<<(LQ * CD) / 256, 256>>>(PH, sw1, sb1);
    sgemm<false, true ><<<gg, 256>>>(PH, sw2, sb2, PS, 2048, 2048, 2048);

    fuse_out<<<LQ, 256>>>(x, O, PS, on, out);
}

// round 3
// speedup vs baseline: 1.5324x; 1.5324x over previous
#include <cuda_runtime.h>
#include <cstdint>
#include <math.h>

#define LQ   2048
#define CD   2048
#define HN   16
#define DD   128
#define KVL  4096

// ---------------- scratch (device globals; no allocation) ----------------
__device__ float gQ [LQ  * CD];
__device__ float gK [KVL * CD];
__device__ float gV [KVL * CD];
__device__ float gAO[LQ  * CD];
__device__ float gO [LQ  * CD];
__device__ float gPH[LQ  * CD];
__device__ float gPS[LQ  * CD];

// ---------------- helpers ----------------
__device__ __forceinline__ float tf32r(float x) {
    uint32_t u;
    asm("cvt.rna.tf32.f32 %0, %1;" : "=r"(u) : "f"(x));
    return __uint_as_float(u);
}

__device__ __forceinline__ void mma_tf32(float c[4], const uint32_t a[4], const uint32_t b[2]) {
    asm volatile(
        "mma.sync.aligned.m16n8k8.row.col.f32.tf32.tf32.f32 "
        "{%0,%1,%2,%3}, {%4,%5,%6,%7}, {%8,%9}, {%0,%1,%2,%3};"
        : "+f"(c[0]), "+f"(c[1]), "+f"(c[2]), "+f"(c[3])
        : "r"(a[0]), "r"(a[1]), "r"(a[2]), "r"(a[3]), "r"(b[0]), "r"(b[1]));
}

// ---------------- tf32 mma.sync GEMM ----------------
// C[m,n] = sum_k A[m,k] * (BT ? B[n,k] : B[k,n])  (+ bias[n] if BIAS)
// CTA tile 128x128, BK=32, 256 threads (8 warps: 2m x 4n, warp tile 64x32).
template<bool BT, bool BIAS>
__global__ __launch_bounds__(256) void mmagemm(
    const float* __restrict__ A, const float* __restrict__ B,
    const float* __restrict__ bias, float* __restrict__ Cc,
    int M, int N, int K)
{
    __shared__ float As[128][36];   // [m][k], pad->stride 36
    __shared__ float Bs[128][36];   // [n][k]

    const int tid  = threadIdx.x;
    const int wid  = tid >> 5, lane = tid & 31;
    const int gid  = lane >> 2, tig = lane & 3;
    const int wm   = (wid & 1) * 64;
    const int wn   = (wid >> 1) * 32;
    const int bm   = blockIdx.y * 128, bn = blockIdx.x * 128;

    float c[4][4][4];
#pragma unroll
    for (int i = 0; i < 4; i++)
#pragma unroll
        for (int j = 0; j < 4; j++)
#pragma unroll
            for (int r = 0; r < 4; r++) c[i][j][r] = 0.f;

    float4 ra[4], rb[4];
    const int NK = K >> 5;

    auto loadA = [&](int k0) {
#pragma unroll
        for (int i = 0; i < 4; i++) {
            const int idx = i * 256 + tid, r = idx >> 3, s = idx & 7;
            ra[i] = *(const float4*)(A + (size_t)(bm + r) * K + k0 + s * 4);
        }
    };
    auto loadB = [&](int k0) {
#pragma unroll
        for (int i = 0; i < 4; i++) {
            const int idx = i * 256 + tid;
            if (BT) {
                const int r = idx >> 3, s = idx & 7;
                rb[i] = *(const float4*)(B + (size_t)(bn + r) * K + k0 + s * 4);
            } else {
                const int kr = idx >> 5, ng = idx & 31;
                rb[i] = *(const float4*)(B + (size_t)(k0 + kr) * N + bn + ng * 4);
            }
        }
    };
    auto storeA = [&]() {
#pragma unroll
        for (int i = 0; i < 4; i++) {
            const int idx = i * 256 + tid, r = idx >> 3, s = idx & 7;
            float4 v = ra[i];
            v.x = tf32r(v.x); v.y = tf32r(v.y); v.z = tf32r(v.z); v.w = tf32r(v.w);
            *(float4*)&As[r][s * 4] = v;
        }
    };
    auto storeB = [&]() {
#pragma unroll
        for (int i = 0; i < 4; i++) {
            const int idx = i * 256 + tid;
            float4 v = rb[i];
            if (BT) {
                const int r = idx >> 3, s = idx & 7;
                v.x = tf32r(v.x); v.y = tf32r(v.y); v.z = tf32r(v.z); v.w = tf32r(v.w);
                *(float4*)&Bs[r][s * 4] = v;
            } else {
                const int kr = idx >> 5, ng = idx & 31;
                Bs[ng * 4 + 0][kr] = tf32r(v.x);
                Bs[ng * 4 + 1][kr] = tf32r(v.y);
                Bs[ng * 4 + 2][kr] = tf32r(v.z);
                Bs[ng * 4 + 3][kr] = tf32r(v.w);
            }
        }
    };
    auto compute = [&]() {
#pragma unroll
        for (int ks = 0; ks < 4; ks++) {
            const int k = ks * 8;
            uint32_t af[4][4], bf[4][2];
#pragma unroll
            for (int mi = 0; mi < 4; mi++) {
                const int m = wm + mi * 16;
                af[mi][0] = __float_as_uint(As[m + gid    ][k + tig    ]);
                af[mi][1] = __float_as_uint(As[m + gid + 8][k + tig    ]);
                af[mi][2] = __float_as_uint(As[m + gid    ][k + tig + 4]);
                af[mi][3] = __float_as_uint(As[m + gid + 8][k + tig + 4]);
            }
#pragma unroll
            for (int ni = 0; ni < 4; ni++) {
                const int n = wn + ni * 8;
                bf[ni][0] = __float_as_uint(Bs[n + gid][k + tig    ]);
                bf[ni][1] = __float_as_uint(Bs[n + gid][k + tig + 4]);
            }
#pragma unroll
            for (int mi = 0; mi < 4; mi++)
#pragma unroll
                for (int ni = 0; ni < 4; ni++)
                    mma_tf32(c[mi][ni], af[mi], bf[ni]);
        }
    };

    loadA(0); loadB(0);
    storeA(); storeB();
    __syncthreads();

    for (int kc = 0; kc < NK; kc++) {
        if (kc + 1 < NK) { loadA((kc + 1) * 32); loadB((kc + 1) * 32); }
        compute();
        __syncthreads();
        if (kc + 1 < NK) { storeA(); storeB(); __syncthreads(); }
    }

    // epilogue
#pragma unroll
    for (int mi = 0; mi < 4; mi++) {
        const int row0 = bm + wm + mi * 16 + gid;
#pragma unroll
        for (int ni = 0; ni < 4; ni++) {
            const int col = bn + wn + ni * 8 + tig * 2;
            float2 v0 = make_float2(c[mi][ni][0], c[mi][ni][1]);
            float2 v1 = make_float2(c[mi][ni][2], c[mi][ni][3]);
            if (BIAS) {
                const float b0 = bias[col], b1 = bias[col + 1];
                v0.x += b0; v0.y += b1; v1.x += b0; v1.y += b1;
            }
            *(float2*)(Cc + (size_t)row0 * N + col)       = v0;
            *(float2*)(Cc + (size_t)(row0 + 8) * N + col) = v1;
        }
    }
}

// ---------------- per-(row,head) rmsnorm + depth rope ----------------
__global__ __launch_bounds__(128) void normrope(
    float* __restrict__ buf, const float* __restrict__ w, float depth)
{
    const int row = blockIdx.x;
    const int h   = blockIdx.y;
    float* p = buf + (size_t)row * CD + h * DD;
    const int d = threadIdx.x;

    float v  = p[d];
    float sq = v * v;
#pragma unroll
    for (int o = 16; o > 0; o >>= 1) sq += __shfl_xor_sync(0xffffffffu, sq, o);
    __shared__ float ws[4];
    if ((d & 31) == 0) ws[d >> 5] = sq;
    __syncthreads();
    const float total = ws[0] + ws[1] + ws[2] + ws[3];
    const float rn = rsqrtf(total * (1.f / 128.f) + 1e-6f);

    __shared__ float sn[128];
    sn[d] = v * rn * w[d];
    __syncthreads();

    float out;
    if (d < 64) {
        float ang = depth * powf(10000.f, -(float)d * (1.f / 64.f));
        out = sn[d] * cosf(ang) - sn[d + 64] * sinf(ang);
    } else {
        int i = d - 64;
        float ang = depth * powf(10000.f, -(float)i * (1.f / 64.f));
        out = sn[i] * sinf(ang) + sn[d] * cosf(ang);
    }
    p[d] = out;
}

// ---------------- flash attention (fp32, online softmax) ----------------
__global__ __launch_bounds__(256) void flash(
    const float* __restrict__ Qg, const float* __restrict__ Kg,
    const float* __restrict__ Vg, float* __restrict__ Og)
{
    extern __shared__ float sm[];
    float* Qs = sm;                  // [128][68] transposed
    float* Ks = Qs + 128 * 68;       // [128][68] transposed
    float* Vs = Ks + 128 * 68;       // [64][132] natural
    float* Ps = Vs + 64 * 132;       // [64][68]  probs [m][n]

    const int tid = threadIdx.x;
    const int tx = tid & 15, ty = tid >> 4;
    const int h  = blockIdx.y;
    const int q0 = blockIdx.x * 64;
    const int hD = h * DD;
    const float scale = 0.08838834764831845f;

    {
        const int m  = tid >> 2;
        const int dl = (tid & 3) << 2;
#pragma unroll
        for (int pp = 0; pp < 8; pp++) {
            const int d = pp * 16 + dl;
            float4 v = *(const float4*)(Qg + (size_t)(q0 + m) * CD + hD + d);
            Qs[(d + 0) * 68 + m] = v.x * scale;
            Qs[(d + 1) * 68 + m] = v.y * scale;
            Qs[(d + 2) * 68 + m] = v.z * scale;
            Qs[(d + 3) * 68 + m] = v.w * scale;
        }
    }

    float mI[4], lI[4], acc[4][8];
#pragma unroll
    for (int i = 0; i < 4; i++) {
        mI[i] = -1e30f; lI[i] = 0.f;
#pragma unroll
        for (int c = 0; c < 8; c++) acc[i][c] = 0.f;
    }

    for (int k0 = 0; k0 < KVL; k0 += 64) {
        __syncthreads();
        {
            const int n  = tid >> 2;
            const int dl = (tid & 3) << 2;
#pragma unroll
            for (int pp = 0; pp < 8; pp++) {
                const int d = pp * 16 + dl;
                float4 v = *(const float4*)(Kg + (size_t)(k0 + n) * CD + hD + d);
                Ks[(d + 0) * 68 + n] = v.x;
                Ks[(d + 1) * 68 + n] = v.y;
                Ks[(d + 2) * 68 + n] = v.z;
                Ks[(d + 3) * 68 + n] = v.w;
                float4 w = *(const float4*)(Vg + (size_t)(k0 + n) * CD + hD + d);
                *(float4*)&Vs[n * 132 + d] = w;
            }
        }
        __syncthreads();

        float s[4][4];
#pragma unroll
        for (int i = 0; i < 4; i++)
#pragma unroll
            for (int j = 0; j < 4; j++) s[i][j] = 0.f;
#pragma unroll 16
        for (int d = 0; d < 128; d++) {
            float4 qv = *(const float4*)&Qs[d * 68 + ty * 4];
            float4 kv = *(const float4*)&Ks[d * 68 + tx * 4];
            s[0][0] += qv.x * kv.x; s[0][1] += qv.x * kv.y; s[0][2] += qv.x * kv.z; s[0][3] += qv.x * kv.w;
            s[1][0] += qv.y * kv.x; s[1][1] += qv.y * kv.y; s[1][2] += qv.y * kv.z; s[1][3] += qv.y * kv.w;
            s[2][0] += qv.z * kv.x; s[2][1] += qv.z * kv.y; s[2][2] += qv.z * kv.z; s[2][3] += qv.z * kv.w;
            s[3][0] += qv.w * kv.x; s[3][1] += qv.w * kv.y; s[3][2] += qv.w * kv.z; s[3][3] += qv.w * kv.w;
        }

        float pr[4][4];
#pragma unroll
        for (int i = 0; i < 4; i++) {
            float rmax = fmaxf(fmaxf(s[i][0], s[i][1]), fmaxf(s[i][2], s[i][3]));
            rmax = fmaxf(rmax, __shfl_xor_sync(0xffffffffu, rmax, 1));
            rmax = fmaxf(rmax, __shfl_xor_sync(0xffffffffu, rmax, 2));
            rmax = fmaxf(rmax, __shfl_xor_sync(0xffffffffu, rmax, 4));
            rmax = fmaxf(rmax, __shfl_xor_sync(0xffffffffu, rmax, 8));
            const float mn    = fmaxf(mI[i], rmax);
            const float alpha = __expf(mI[i] - mn);
            float rsum = 0.f;
#pragma unroll
            for (int j = 0; j < 4; j++) { pr[i][j] = __expf(s[i][j] - mn); rsum += pr[i][j]; }
            rsum += __shfl_xor_sync(0xffffffffu, rsum, 1);
            rsum += __shfl_xor_sync(0xffffffffu, rsum, 2);
            rsum += __shfl_xor_sync(0xffffffffu, rsum, 4);
            rsum += __shfl_xor_sync(0xffffffffu, rsum, 8);
            lI[i] = lI[i] * alpha + rsum;
            mI[i] = mn;
#pragma unroll
            for (int c = 0; c < 8; c++) acc[i][c] *= alpha;
        }
#pragma unroll
        for (int i = 0; i < 4; i++)
#pragma unroll
            for (int j = 0; j < 4; j++)
                Ps[(ty * 4 + i) * 68 + tx * 4 + j] = pr[i][j];
        __syncthreads();

#pragma unroll 8
        for (int n = 0; n < 64; n++) {
            float4 v0 = *(const float4*)&Vs[n * 132 + tx * 4];
            float4 v1 = *(const float4*)&Vs[n * 132 + 64 + tx * 4];
            float pv[4];
#pragma unroll
            for (int i = 0; i < 4; i++) pv[i] = Ps[(ty * 4 + i) * 68 + n];
#pragma unroll
            for (int i = 0; i < 4; i++) {
                const float p = pv[i];
                acc[i][0] += p * v0.x; acc[i][1] += p * v0.y;
                acc[i][2] += p * v0.z; acc[i][3] += p * v0.w;
                acc[i][4] += p * v1.x; acc[i][5] += p * v1.y;
                acc[i][6] += p * v1.z; acc[i][7] += p * v1.w;
            }
        }
    }

#pragma unroll
    for (int i = 0; i < 4; i++) {
        const float inv = 1.f / lI[i];
        const int row = q0 + ty * 4 + i;
        float4 o0 = make_float4(acc[i][0] * inv, acc[i][1] * inv, acc[i][2] * inv, acc[i][3] * inv);
        float4 o1 = make_float4(acc[i][4] * inv, acc[i][5] * inv, acc[i][6] * inv, acc[i][7] * inv);
        *(float4*)(Og + (size_t)row * CD + hD + tx * 4)      = o0;
        *(float4*)(Og + (size_t)row * CD + hD + 64 + tx * 4) = o1;
    }
}

// ---------------- position features ----------------
__global__ __launch_bounds__(256) void pos_hidden(
    float* __restrict__ ph, const float* __restrict__ sw1, const float* __restrict__ sb1)
{
    const int idx = blockIdx.x * 256 + threadIdx.x;
    const int l = idx >> 11;
    const int c = idx & 2047;
    const float coord = -1.f + 2.f * (float)l / 2047.f;
    ph[idx] = sinf(30.f * (coord * sw1[c] + sb1[c]));
}

// ---------------- final: out = x + rmsnorm(O + pos, on_w) ----------------
__global__ __launch_bounds__(256) void fuse_out(
    const float* __restrict__ x, const float* __restrict__ ov,
    const float* __restrict__ pos, const float* __restrict__ w,
    float* __restrict__ out)
{
    __shared__ float t[2048];
    __shared__ float red[8];
    const int l = blockIdx.x;
    const int tid = threadIdx.x;
    float sq = 0.f;
    for (int c = tid; c < 2048; c += 256) {
        const float v = ov[(size_t)l * 2048 + c] + pos[(size_t)l * 2048 + c];
        t[c] = v; sq += v * v;
    }
#pragma unroll
    for (int o = 16; o > 0; o >>= 1) sq += __shfl_xor_sync(0xffffffffu, sq, o);
    if ((tid & 31) == 0) red[tid >> 5] = sq;
    __syncthreads();
    float total = 0.f;
#pragma unroll
    for (int i = 0; i < 8; i++) total += red[i];
    const float rn = rsqrtf(total * (1.f / 2048.f) + 1e-6f);
    for (int c = tid; c < 2048; c += 256)
        out[(size_t)l * 2048 + c] = x[(size_t)l * 2048 + c] + t[c] * rn * w[c];
}

// ---------------- launch ----------------
extern "C" void kernel_launch(void* const* d_in, const int* in_sizes, int n_in,
                              void* d_out, int out_size)
{
    (void)in_sizes; (void)n_in; (void)out_size;
    const float* x   = (const float*)d_in[0];
    const float* h0  = (const float*)d_in[1];
    const float* h1  = (const float*)d_in[2];
    const float* h2  = (const float*)d_in[3];
    const float* Wq  = (const float*)d_in[4];
    const float* Wk  = (const float*)d_in[5];
    const float* Wv  = (const float*)d_in[6];
    const float* Wo  = (const float*)d_in[7];
    const float* qn  = (const float*)d_in[8];
    const float* kn  = (const float*)d_in[9];
    const float* on  = (const float*)d_in[10];
    const float* sw1 = (const float*)d_in[11];
    const float* sb1 = (const float*)d_in[12];
    const float* sw2 = (const float*)d_in[13];
    const float* sb2 = (const float*)d_in[14];
    float* out = (float*)d_out;

    float *Q, *K, *V, *AO, *O, *PH, *PS;
    cudaGetSymbolAddress((void**)&Q,  gQ);
    cudaGetSymbolAddress((void**)&K,  gK);
    cudaGetSymbolAddress((void**)&V,  gV);
    cudaGetSymbolAddress((void**)&AO, gAO);
    cudaGetSymbolAddress((void**)&O,  gO);
    cudaGetSymbolAddress((void**)&PH, gPH);
    cudaGetSymbolAddress((void**)&PS, gPS);

    const dim3 gg(16, 16);
    const size_t LC = (size_t)LQ * CD;

    mmagemm<true,  false><<<gg, 256>>>(h2, Wq, nullptr, Q,      2048, 2048, 2048);
    mmagemm<true,  false><<<gg, 256>>>(h0, Wk, nullptr, K,      2048, 2048, 2048);
    mmagemm<true,  false><<<gg, 256>>>(h1, Wk, nullptr, K + LC, 2048, 2048, 2048);
    mmagemm<true,  false><<<gg, 256>>>(h0, Wv, nullptr, V,      2048, 2048, 2048);
    mmagemm<true,  false><<<gg, 256>>>(h1, Wv, nullptr, V + LC, 2048, 2048, 2048);

    const dim3 gn(LQ, HN);
    normrope<<<gn, 128>>>(Q,      qn, 2.f);
    normrope<<<gn, 128>>>(K,      kn, 0.f);
    normrope<<<gn, 128>>>(K + LC, kn, 1.f);

    const int FS = (128 * 68 + 128 * 68 + 64 * 132 + 64 * 68) * 4;
    cudaFuncSetAttribute(flash, cudaFuncAttributeMaxDynamicSharedMemorySize, FS);
    flash<<<dim3(32, 16), 256, FS>>>(Q, K, V, AO);

    mmagemm<true,  false><<<gg, 256>>>(AO, Wo, nullptr, O, 2048, 2048, 2048);

    pos_hidden<<<(LQ * CD) / 256, 256>>>(PH, sw1, sb1);
    mmagemm<false, true ><<<gg, 256>>>(PH, sw2, sb2, PS, 2048, 2048, 2048);

    fuse_out<<<LQ, 256>>>(x, O, PS, on, out);
}

// round 4
// speedup vs baseline: 2.9023x; 1.8940x over previous
#include <cuda_runtime.h>
#include <cstdint>
#include <math.h>

#define LQ   2048
#define CD   2048
#define HN   16
#define DD   128
#define KVL  4096

// ---------------- scratch (device globals; no allocation) ----------------
__device__ float gQ [LQ  * CD];
__device__ float gK [KVL * CD];
__device__ float gV [KVL * CD];
__device__ float gAO[LQ  * CD];
__device__ float gO [LQ  * CD];
__device__ float gPH[LQ  * CD];
__device__ float gPS[LQ  * CD];

// ---------------- helpers ----------------
__device__ __forceinline__ float tf32r(float x) {
    uint32_t u;
    asm("cvt.rna.tf32.f32 %0, %1;" : "=r"(u) : "f"(x));
    return __uint_as_float(u);
}

__device__ __forceinline__ void mma_tf32(float c[4], const uint32_t a[4], const uint32_t b[2]) {
    asm volatile(
        "mma.sync.aligned.m16n8k8.row.col.f32.tf32.tf32.f32 "
        "{%0,%1,%2,%3}, {%4,%5,%6,%7}, {%8,%9}, {%0,%1,%2,%3};"
        : "+f"(c[0]), "+f"(c[1]), "+f"(c[2]), "+f"(c[3])
        : "r"(a[0]), "r"(a[1]), "r"(a[2]), "r"(a[3]), "r"(b[0]), "r"(b[1]));
}

#define CPASYNC16(dst, src) \
    asm volatile("cp.async.cg.shared.global [%0], [%1], 16;" :: "r"(dst), "l"(src) : "memory")
#define CPCOMMIT() asm volatile("cp.async.commit_group;" ::: "memory")

// ---------------- tf32 mma.sync GEMM ----------------
// C[m,n] = sum_k A[m,k] * (BT ? B[n,k] : B[k,n])  (+ bias[n] if BIAS)
template<bool BT, bool BIAS>
__global__ __launch_bounds__(256) void mmagemm(
    const float* __restrict__ A, const float* __restrict__ B,
    const float* __restrict__ bias, float* __restrict__ Cc,
    int M, int N, int K)
{
    __shared__ float As[128][36];
    __shared__ float Bs[128][36];

    const int tid  = threadIdx.x;
    const int wid  = tid >> 5, lane = tid & 31;
    const int gid  = lane >> 2, tig = lane & 3;
    const int wm   = (wid & 1) * 64;
    const int wn   = (wid >> 1) * 32;
    const int bm   = blockIdx.y * 128, bn = blockIdx.x * 128;

    float c[4][4][4];
#pragma unroll
    for (int i = 0; i < 4; i++)
#pragma unroll
        for (int j = 0; j < 4; j++)
#pragma unroll
            for (int r = 0; r < 4; r++) c[i][j][r] = 0.f;

    float4 ra[4], rb[4];
    const int NK = K >> 5;

    auto loadA = [&](int k0) {
#pragma unroll
        for (int i = 0; i < 4; i++) {
            const int idx = i * 256 + tid, r = idx >> 3, s = idx & 7;
            ra[i] = *(const float4*)(A + (size_t)(bm + r) * K + k0 + s * 4);
        }
    };
    auto loadB = [&](int k0) {
#pragma unroll
        for (int i = 0; i < 4; i++) {
            const int idx = i * 256 + tid;
            if (BT) {
                const int r = idx >> 3, s = idx & 7;
                rb[i] = *(const float4*)(B + (size_t)(bn + r) * K + k0 + s * 4);
            } else {
                const int kr = idx >> 5, ng = idx & 31;
                rb[i] = *(const float4*)(B + (size_t)(k0 + kr) * N + bn + ng * 4);
            }
        }
    };
    auto storeA = [&]() {
#pragma unroll
        for (int i = 0; i < 4; i++) {
            const int idx = i * 256 + tid, r = idx >> 3, s = idx & 7;
            float4 v = ra[i];
            v.x = tf32r(v.x); v.y = tf32r(v.y); v.z = tf32r(v.z); v.w = tf32r(v.w);
            *(float4*)&As[r][s * 4] = v;
        }
    };
    auto storeB = [&]() {
#pragma unroll
        for (int i = 0; i < 4; i++) {
            const int idx = i * 256 + tid;
            float4 v = rb[i];
            if (BT) {
                const int r = idx >> 3, s = idx & 7;
                v.x = tf32r(v.x); v.y = tf32r(v.y); v.z = tf32r(v.z); v.w = tf32r(v.w);
                *(float4*)&Bs[r][s * 4] = v;
            } else {
                const int kr = idx >> 5, ng = idx & 31;
                Bs[ng * 4 + 0][kr] = tf32r(v.x);
                Bs[ng * 4 + 1][kr] = tf32r(v.y);
                Bs[ng * 4 + 2][kr] = tf32r(v.z);
                Bs[ng * 4 + 3][kr] = tf32r(v.w);
            }
        }
    };
    auto compute = [&]() {
#pragma unroll
        for (int ks = 0; ks < 4; ks++) {
            const int k = ks * 8;
            uint32_t af[4][4], bf[4][2];
#pragma unroll
            for (int mi = 0; mi < 4; mi++) {
                const int m = wm + mi * 16;
                af[mi][0] = __float_as_uint(As[m + gid    ][k + tig    ]);
                af[mi][1] = __float_as_uint(As[m + gid + 8][k + tig    ]);
                af[mi][2] = __float_as_uint(As[m + gid    ][k + tig + 4]);
                af[mi][3] = __float_as_uint(As[m + gid + 8][k + tig + 4]);
            }
#pragma unroll
            for (int ni = 0; ni < 4; ni++) {
                const int n = wn + ni * 8;
                bf[ni][0] = __float_as_uint(Bs[n + gid][k + tig    ]);
                bf[ni][1] = __float_as_uint(Bs[n + gid][k + tig + 4]);
            }
#pragma unroll
            for (int mi = 0; mi < 4; mi++)
#pragma unroll
                for (int ni = 0; ni < 4; ni++)
                    mma_tf32(c[mi][ni], af[mi], bf[ni]);
        }
    };

    loadA(0); loadB(0);
    storeA(); storeB();
    __syncthreads();

    for (int kc = 0; kc < NK; kc++) {
        if (kc + 1 < NK) { loadA((kc + 1) * 32); loadB((kc + 1) * 32); }
        compute();
        __syncthreads();
        if (kc + 1 < NK) { storeA(); storeB(); __syncthreads(); }
    }

#pragma unroll
    for (int mi = 0; mi < 4; mi++) {
        const int row0 = bm + wm + mi * 16 + gid;
#pragma unroll
        for (int ni = 0; ni < 4; ni++) {
            const int col = bn + wn + ni * 8 + tig * 2;
            float2 v0 = make_float2(c[mi][ni][0], c[mi][ni][1]);
            float2 v1 = make_float2(c[mi][ni][2], c[mi][ni][3]);
            if (BIAS) {
                const float b0 = bias[col], b1 = bias[col + 1];
                v0.x += b0; v0.y += b1; v1.x += b0; v1.y += b1;
            }
            *(float2*)(Cc + (size_t)row0 * N + col)       = v0;
            *(float2*)(Cc + (size_t)(row0 + 8) * N + col) = v1;
        }
    }
}

// ---------------- per-(row,head) rmsnorm + depth rope ----------------
__global__ __launch_bounds__(128) void normrope(
    float* __restrict__ buf, const float* __restrict__ w, float depth)
{
    const int row = blockIdx.x;
    const int h   = blockIdx.y;
    float* p = buf + (size_t)row * CD + h * DD;
    const int d = threadIdx.x;

    float v  = p[d];
    float sq = v * v;
#pragma unroll
    for (int o = 16; o > 0; o >>= 1) sq += __shfl_xor_sync(0xffffffffu, sq, o);
    __shared__ float ws[4];
    if ((d & 31) == 0) ws[d >> 5] = sq;
    __syncthreads();
    const float total = ws[0] + ws[1] + ws[2] + ws[3];
    const float rn = rsqrtf(total * (1.f / 128.f) + 1e-6f);

    __shared__ float sn[128];
    sn[d] = v * rn * w[d];
    __syncthreads();

    float out;
    if (d < 64) {
        float ang = depth * powf(10000.f, -(float)d * (1.f / 64.f));
        out = sn[d] * cosf(ang) - sn[d + 64] * sinf(ang);
    } else {
        int i = d - 64;
        float ang = depth * powf(10000.f, -(float)i * (1.f / 64.f));
        out = sn[i] * sinf(ang) + sn[d] * cosf(ang);
    }
    p[d] = out;
}

// ---------------- flash attention via tf32 mma.sync ----------------
// CTA: 128 q-rows x 1 head. 8 warps, warp w owns q rows [w*16, w*16+16).
// KV tile 32, double-buffered cp.async. smem strides chosen conflict-free.
#define QTS 132          // Qs/Ks row stride (floats)
#define VTS 136          // Vs row stride
#define PTS 36           // Ps row stride
#define OFF_K0 (128 * QTS)
#define OFF_K1 (OFF_K0 + 32 * QTS)
#define OFF_V0 (OFF_K1 + 32 * QTS)
#define OFF_V1 (OFF_V0 + 32 * VTS)
#define OFF_P  (OFF_V1 + 32 * VTS)
#define FSMEM  ((OFF_P + 128 * PTS) * 4)   // bytes

__global__ __launch_bounds__(256) void flashmma(
    const float* __restrict__ Qg, const float* __restrict__ Kg,
    const float* __restrict__ Vg, float* __restrict__ Og)
{
    extern __shared__ float sm[];
    float* Qs = sm;
    float* KsB[2] = { sm + OFF_K0, sm + OFF_K1 };
    float* VsB[2] = { sm + OFF_V0, sm + OFF_V1 };
    float* Ps = sm + OFF_P;

    const int tid  = threadIdx.x;
    const int wid  = tid >> 5, lane = tid & 31;
    const int gid  = lane >> 2, tig = lane & 3;
    const int h    = blockIdx.y;
    const int q0   = blockIdx.x * 128;
    const int hD   = h * DD;
    const int w16  = wid * 16;
    const float scale = 0.08838834764831845f;   // 1/sqrt(128)

    // ---- load Q tile (convert tf32, pre-scale) ----
#pragma unroll
    for (int i = 0; i < 16; i++) {
        const int idx = i * 256 + tid;
        const int r = idx >> 5, c = (idx & 31) * 4;
        float4 v = *(const float4*)(Qg + (size_t)(q0 + r) * CD + hD + c);
        v.x = tf32r(v.x * scale); v.y = tf32r(v.y * scale);
        v.z = tf32r(v.z * scale); v.w = tf32r(v.w * scale);
        *(float4*)&Qs[r * QTS + c] = v;
    }

    // ---- cp.async prefetch of K/V tile `it` into buffer it&1 ----
    auto prefetch = [&](int it) {
        const int b = it & 1;
        const int k0 = it * 32;
        const uint32_t kd = (uint32_t)__cvta_generic_to_shared(KsB[b]);
        const uint32_t vd = (uint32_t)__cvta_generic_to_shared(VsB[b]);
#pragma unroll
        for (int i = 0; i < 4; i++) {
            const int idx = i * 256 + tid;
            const int r = idx >> 5, c = (idx & 31) * 4;
            CPASYNC16(kd + (r * QTS + c) * 4, Kg + (size_t)(k0 + r) * CD + hD + c);
            CPASYNC16(vd + (r * VTS + c) * 4, Vg + (size_t)(k0 + r) * CD + hD + c);
        }
        CPCOMMIT();
    };

    const int NIT = KVL / 32;   // 128
    prefetch(0);
    prefetch(1);

    float m0 = -1e30f, m1 = -1e30f, l0 = 0.f, l1 = 0.f;
    float o[16][4];
#pragma unroll
    for (int ni = 0; ni < 16; ni++)
#pragma unroll
        for (int r = 0; r < 4; r++) o[ni][r] = 0.f;

    for (int it = 0; it < NIT; it++) {
        const int b = it & 1;
        const float* Ks = KsB[b];
        const float* Vs = VsB[b];

        if (it + 1 < NIT) asm volatile("cp.async.wait_group 1;" ::: "memory");
        else              asm volatile("cp.async.wait_group 0;" ::: "memory");
        __syncthreads();

        // ---- S = Q K^T : warp computes rows [w16,w16+16) x 32 kv ----
        float sc[4][4];
#pragma unroll
        for (int ni = 0; ni < 4; ni++)
#pragma unroll
            for (int r = 0; r < 4; r++) sc[ni][r] = 0.f;

#pragma unroll
        for (int ks = 0; ks < 16; ks++) {
            const int k = ks * 8;
            uint32_t af[4];
            af[0] = __float_as_uint(Qs[(w16 + gid    ) * QTS + k + tig    ]);
            af[1] = __float_as_uint(Qs[(w16 + gid + 8) * QTS + k + tig    ]);
            af[2] = __float_as_uint(Qs[(w16 + gid    ) * QTS + k + tig + 4]);
            af[3] = __float_as_uint(Qs[(w16 + gid + 8) * QTS + k + tig + 4]);
#pragma unroll
            for (int ni = 0; ni < 4; ni++) {
                uint32_t bf[2];
                bf[0] = __float_as_uint(Ks[(ni * 8 + gid) * QTS + k + tig    ]);
                bf[1] = __float_as_uint(Ks[(ni * 8 + gid) * QTS + k + tig + 4]);
                mma_tf32(sc[ni], af, bf);
            }
        }

        // ---- online softmax (rows gid and gid+8; reduce over tig lanes) ----
        float rm0 = -1e30f, rm1 = -1e30f;
#pragma unroll
        for (int ni = 0; ni < 4; ni++) {
            rm0 = fmaxf(rm0, fmaxf(sc[ni][0], sc[ni][1]));
            rm1 = fmaxf(rm1, fmaxf(sc[ni][2], sc[ni][3]));
        }
        rm0 = fmaxf(rm0, __shfl_xor_sync(0xffffffffu, rm0, 1));
        rm0 = fmaxf(rm0, __shfl_xor_sync(0xffffffffu, rm0, 2));
        rm1 = fmaxf(rm1, __shfl_xor_sync(0xffffffffu, rm1, 1));
        rm1 = fmaxf(rm1, __shfl_xor_sync(0xffffffffu, rm1, 2));

        const float mn0 = fmaxf(m0, rm0), mn1 = fmaxf(m1, rm1);
        const float a0 = __expf(m0 - mn0), a1 = __expf(m1 - mn1);
        m0 = mn0; m1 = mn1;

        float rs0 = 0.f, rs1 = 0.f;
#pragma unroll
        for (int ni = 0; ni < 4; ni++) {
            sc[ni][0] = __expf(sc[ni][0] - mn0);
            sc[ni][1] = __expf(sc[ni][1] - mn0);
            sc[ni][2] = __expf(sc[ni][2] - mn1);
            sc[ni][3] = __expf(sc[ni][3] - mn1);
            rs0 += sc[ni][0] + sc[ni][1];
            rs1 += sc[ni][2] + sc[ni][3];
        }
        rs0 += __shfl_xor_sync(0xffffffffu, rs0, 1);
        rs0 += __shfl_xor_sync(0xffffffffu, rs0, 2);
        rs1 += __shfl_xor_sync(0xffffffffu, rs1, 1);
        rs1 += __shfl_xor_sync(0xffffffffu, rs1, 2);
        l0 = l0 * a0 + rs0;
        l1 = l1 * a1 + rs1;

#pragma unroll
        for (int ni = 0; ni < 16; ni++) {
            o[ni][0] *= a0; o[ni][1] *= a0;
            o[ni][2] *= a1; o[ni][3] *= a1;
        }

        // ---- store P (warp-private rows) ----
#pragma unroll
        for (int ni = 0; ni < 4; ni++) {
            const int col = ni * 8 + tig * 2;
            *(float2*)&Ps[(w16 + gid    ) * PTS + col] =
                make_float2(tf32r(sc[ni][0]), tf32r(sc[ni][1]));
            *(float2*)&Ps[(w16 + gid + 8) * PTS + col] =
                make_float2(tf32r(sc[ni][2]), tf32r(sc[ni][3]));
        }
        __syncwarp();

        // ---- O += P V  (V^T fragments via swapped indexing) ----
#pragma unroll
        for (int ks = 0; ks < 4; ks++) {
            const int k = ks * 8;
            uint32_t paf[4];
            paf[0] = __float_as_uint(Ps[(w16 + gid    ) * PTS + k + tig    ]);
            paf[1] = __float_as_uint(Ps[(w16 + gid + 8) * PTS + k + tig    ]);
            paf[2] = __float_as_uint(Ps[(w16 + gid    ) * PTS + k + tig + 4]);
            paf[3] = __float_as_uint(Ps[(w16 + gid + 8) * PTS + k + tig + 4]);
#pragma unroll
            for (int ni = 0; ni < 16; ni++) {
                const int d = ni * 8;
                uint32_t bf[2];
                bf[0] = __float_as_uint(Vs[(k + tig    ) * VTS + d + gid]);
                bf[1] = __float_as_uint(Vs[(k + tig + 4) * VTS + d + gid]);
                mma_tf32(o[ni], paf, bf);
            }
        }

        __syncthreads();
        if (it + 2 < NIT) prefetch(it + 2);
    }

    // ---- epilogue ----
    const float inv0 = 1.f / l0, inv1 = 1.f / l1;
    const int row0 = q0 + w16 + gid;
#pragma unroll
    for (int ni = 0; ni < 16; ni++) {
        const int col = hD + ni * 8 + tig * 2;
        *(float2*)(Og + (size_t)row0 * CD + col) =
            make_float2(o[ni][0] * inv0, o[ni][1] * inv0);
        *(float2*)(Og + (size_t)(row0 + 8) * CD + col) =
            make_float2(o[ni][2] * inv1, o[ni][3] * inv1);
    }
}

// ---------------- position features ----------------
__global__ __launch_bounds__(256) void pos_hidden(
    float* __restrict__ ph, const float* __restrict__ sw1, const float* __restrict__ sb1)
{
    const int idx = blockIdx.x * 256 + threadIdx.x;
    const int l = idx >> 11;
    const int c = idx & 2047;
    const float coord = -1.f + 2.f * (float)l / 2047.f;
    ph[idx] = sinf(30.f * (coord * sw1[c] + sb1[c]));
}

// ---------------- final: out = x + rmsnorm(O + pos, on_w) ----------------
__global__ __launch_bounds__(256) void fuse_out(
    const float* __restrict__ x, const float* __restrict__ ov,
    const float* __restrict__ pos, const float* __restrict__ w,
    float* __restrict__ out)
{
    __shared__ float t[2048];
    __shared__ float red[8];
    const int l = blockIdx.x;
    const int tid = threadIdx.x;
    float sq = 0.f;
    for (int c = tid; c < 2048; c += 256) {
        const float v = ov[(size_t)l * 2048 + c] + pos[(size_t)l * 2048 + c];
        t[c] = v; sq += v * v;
    }
#pragma unroll
    for (int o = 16; o > 0; o >>= 1) sq += __shfl_xor_sync(0xffffffffu, sq, o);
    if ((tid & 31) == 0) red[tid >> 5] = sq;
    __syncthreads();
    float total = 0.f;
#pragma unroll
    for (int i = 0; i < 8; i++) total += red[i];
    const float rn = rsqrtf(total * (1.f / 2048.f) + 1e-6f);
    for (int c = tid; c < 2048; c += 256)
        out[(size_t)l * 2048 + c] = x[(size_t)l * 2048 + c] + t[c] * rn * w[c];
}

// ---------------- launch ----------------
extern "C" void kernel_launch(void* const* d_in, const int* in_sizes, int n_in,
                              void* d_out, int out_size)
{
    (void)in_sizes; (void)n_in; (void)out_size;
    const float* x   = (const float*)d_in[0];
    const float* h0  = (const float*)d_in[1];
    const float* h1  = (const float*)d_in[2];
    const float* h2  = (const float*)d_in[3];
    const float* Wq  = (const float*)d_in[4];
    const float* Wk  = (const float*)d_in[5];
    const float* Wv  = (const float*)d_in[6];
    const float* Wo  = (const float*)d_in[7];
    const float* qn  = (const float*)d_in[8];
    const float* kn  = (const float*)d_in[9];
    const float* on  = (const float*)d_in[10];
    const float* sw1 = (const float*)d_in[11];
    const float* sb1 = (const float*)d_in[12];
    const float* sw2 = (const float*)d_in[13];
    const float* sb2 = (const float*)d_in[14];
    float* out = (float*)d_out;

    float *Q, *K, *V, *AO, *O, *PH, *PS;
    cudaGetSymbolAddress((void**)&Q,  gQ);
    cudaGetSymbolAddress((void**)&K,  gK);
    cudaGetSymbolAddress((void**)&V,  gV);
    cudaGetSymbolAddress((void**)&AO, gAO);
    cudaGetSymbolAddress((void**)&O,  gO);
    cudaGetSymbolAddress((void**)&PH, gPH);
    cudaGetSymbolAddress((void**)&PS, gPS);

    const dim3 gg(16, 16);
    const size_t LC = (size_t)LQ * CD;

    mmagemm<true,  false><<<gg, 256>>>(h2, Wq, nullptr, Q,      2048, 2048, 2048);
    mmagemm<true,  false><<<gg, 256>>>(h0, Wk, nullptr, K,      2048, 2048, 2048);
    mmagemm<true,  false><<<gg, 256>>>(h1, Wk, nullptr, K + LC, 2048, 2048, 2048);
    mmagemm<true,  false><<<gg, 256>>>(h0, Wv, nullptr, V,      2048, 2048, 2048);
    mmagemm<true,  false><<<gg, 256>>>(h1, Wv, nullptr, V + LC, 2048, 2048, 2048);

    const dim3 gn(LQ, HN);
    normrope<<<gn, 128>>>(Q,      qn, 2.f);
    normrope<<<gn, 128>>>(K,      kn, 0.f);
    normrope<<<gn, 128>>>(K + LC, kn, 1.f);

    cudaFuncSetAttribute(flashmma, cudaFuncAttributeMaxDynamicSharedMemorySize, FSMEM);
    flashmma<<<dim3(16, 16), 256, FSMEM>>>(Q, K, V, AO);

    mmagemm<true,  false><<<gg, 256>>>(AO, Wo, nullptr, O, 2048, 2048, 2048);

    pos_hidden<<<(LQ * CD) / 256, 256>>>(PH, sw1, sb1);
    mmagemm<false, true ><<<gg, 256>>>(PH, sw2, sb2, PS, 2048, 2048, 2048);

    fuse_out<<<LQ, 256>>>(x, O, PS, on, out);
}

// round 5
// speedup vs baseline: 3.4938x; 1.2038x over previous
#include <cuda_runtime.h>
#include <cstdint>
#include <math.h>

#define LQ   2048
#define CD   2048
#define HN   16
#define DD   128
#define KVL  4096

// ---------------- scratch (device globals; no allocation) ----------------
__device__ float gQ [LQ  * CD];
__device__ float gK [KVL * CD];
__device__ float gV [KVL * CD];
__device__ float gAO[LQ  * CD];
__device__ float gO [LQ  * CD];
__device__ float gPH[LQ  * CD];
__device__ float gPS[LQ  * CD];

// ---------------- helpers ----------------
__device__ __forceinline__ float tf32r(float x) {
    uint32_t u;
    asm("cvt.rna.tf32.f32 %0, %1;" : "=r"(u) : "f"(x));
    return __uint_as_float(u);
}

__device__ __forceinline__ void mma_tf32(float c[4], const uint32_t a[4], const uint32_t b[2]) {
    asm volatile(
        "mma.sync.aligned.m16n8k8.row.col.f32.tf32.tf32.f32 "
        "{%0,%1,%2,%3}, {%4,%5,%6,%7}, {%8,%9}, {%0,%1,%2,%3};"
        : "+f"(c[0]), "+f"(c[1]), "+f"(c[2]), "+f"(c[3])
        : "r"(a[0]), "r"(a[1]), "r"(a[2]), "r"(a[3]), "r"(b[0]), "r"(b[1]));
}

#define CPASYNC16(dst, src) \
    asm volatile("cp.async.cg.shared.global [%0], [%1], 16;" :: "r"(dst), "l"(src) : "memory")
#define CPCOMMIT()   asm volatile("cp.async.commit_group;" ::: "memory")
#define CPWAIT1()    asm volatile("cp.async.wait_group 1;" ::: "memory")
#define CPWAIT0()    asm volatile("cp.async.wait_group 0;" ::: "memory")

// ---------------- tf32 mma.sync GEMM, cp.async double-buffered ----------------
// C[m,n] = sum_k A[m,k] * (BT ? B[n,k] : B[k,n])  (+ bias[n] if BIAS)
// CTA tile 128x128, BK=32, 8 warps (2m x 4n), 2-stage cp.async.
#define GS_TILE 4608                       // floats per stage tile (>=128*36 and 32*132)
#define GSMEM   (4 * GS_TILE * 4)          // 73728 bytes

template<bool BT, bool BIAS>
__global__ __launch_bounds__(256, 2) void mmagemm(
    const float* __restrict__ A, const float* __restrict__ B,
    const float* __restrict__ bias, float* __restrict__ Cc,
    int M, int N, int K)
{
    extern __shared__ float smemf[];
    const uint32_t sbase = (uint32_t)__cvta_generic_to_shared(smemf);

    const int tid  = threadIdx.x;
    const int wid  = tid >> 5, lane = tid & 31;
    const int gid  = lane >> 2, tig = lane & 3;
    const int wm   = (wid & 1) * 64;
    const int wn   = (wid >> 1) * 32;
    const int bm   = blockIdx.y * 128, bn = blockIdx.x * 128;

    float c[4][4][4];
#pragma unroll
    for (int i = 0; i < 4; i++)
#pragma unroll
        for (int j = 0; j < 4; j++)
#pragma unroll
            for (int r = 0; r < 4; r++) c[i][j][r] = 0.f;

    const int NK = K >> 5;

    auto prefetch = [&](int kc) {
        const int s = kc & 1;
        const int k0 = kc << 5;
        const uint32_t ab = sbase + (s * GS_TILE) * 4;
        const uint32_t bb = sbase + ((2 + s) * GS_TILE) * 4;
#pragma unroll
        for (int i = 0; i < 4; i++) {
            const int idx = i * 256 + tid;
            const int r = idx >> 3, cc = (idx & 7) * 4;
            CPASYNC16(ab + (r * 36 + cc) * 4, A + (size_t)(bm + r) * K + k0 + cc);
        }
        if (BT) {
#pragma unroll
            for (int i = 0; i < 4; i++) {
                const int idx = i * 256 + tid;
                const int r = idx >> 3, cc = (idx & 7) * 4;
                CPASYNC16(bb + (r * 36 + cc) * 4, B + (size_t)(bn + r) * K + k0 + cc);
            }
        } else {
#pragma unroll
            for (int i = 0; i < 4; i++) {
                const int idx = i * 256 + tid;
                const int kr = idx >> 5, cc = (idx & 31) * 4;
                CPASYNC16(bb + (kr * 132 + cc) * 4, B + (size_t)(k0 + kr) * N + bn + cc);
            }
        }
        CPCOMMIT();
    };

    prefetch(0);

    for (int kc = 0; kc < NK; kc++) {
        const bool more = (kc + 1 < NK);
        if (more) prefetch(kc + 1);
        if (more) CPWAIT1(); else CPWAIT0();
        __syncthreads();

        const float* sA = smemf + (kc & 1) * GS_TILE;
        const float* sB = smemf + (2 + (kc & 1)) * GS_TILE;

#pragma unroll
        for (int ks = 0; ks < 4; ks++) {
            const int k = ks * 8;
            uint32_t af[4][4], bf[4][2];
#pragma unroll
            for (int mi = 0; mi < 4; mi++) {
                const int m = wm + mi * 16;
                af[mi][0] = __float_as_uint(sA[(m + gid    ) * 36 + k + tig    ]);
                af[mi][1] = __float_as_uint(sA[(m + gid + 8) * 36 + k + tig    ]);
                af[mi][2] = __float_as_uint(sA[(m + gid    ) * 36 + k + tig + 4]);
                af[mi][3] = __float_as_uint(sA[(m + gid + 8) * 36 + k + tig + 4]);
            }
#pragma unroll
            for (int ni = 0; ni < 4; ni++) {
                const int n = wn + ni * 8 + gid;
                if (BT) {
                    bf[ni][0] = __float_as_uint(sB[n * 36 + k + tig    ]);
                    bf[ni][1] = __float_as_uint(sB[n * 36 + k + tig + 4]);
                } else {
                    bf[ni][0] = __float_as_uint(sB[(k + tig    ) * 132 + n]);
                    bf[ni][1] = __float_as_uint(sB[(k + tig + 4) * 132 + n]);
                }
            }
#pragma unroll
            for (int mi = 0; mi < 4; mi++)
#pragma unroll
                for (int ni = 0; ni < 4; ni++)
                    mma_tf32(c[mi][ni], af[mi], bf[ni]);
        }
        __syncthreads();
    }

#pragma unroll
    for (int mi = 0; mi < 4; mi++) {
        const int row0 = bm + wm + mi * 16 + gid;
#pragma unroll
        for (int ni = 0; ni < 4; ni++) {
            const int col = bn + wn + ni * 8 + tig * 2;
            float2 v0 = make_float2(c[mi][ni][0], c[mi][ni][1]);
            float2 v1 = make_float2(c[mi][ni][2], c[mi][ni][3]);
            if (BIAS) {
                const float b0 = bias[col], b1 = bias[col + 1];
                v0.x += b0; v0.y += b1; v1.x += b0; v1.y += b1;
            }
            *(float2*)(Cc + (size_t)row0 * N + col)       = v0;
            *(float2*)(Cc + (size_t)(row0 + 8) * N + col) = v1;
        }
    }
}

// ---------------- per-(row,head) rmsnorm + depth rope ----------------
__global__ __launch_bounds__(128) void normrope(
    float* __restrict__ buf, const float* __restrict__ w, float depth)
{
    const int row = blockIdx.x;
    const int h   = blockIdx.y;
    float* p = buf + (size_t)row * CD + h * DD;
    const int d = threadIdx.x;

    float v  = p[d];
    float sq = v * v;
#pragma unroll
    for (int o = 16; o > 0; o >>= 1) sq += __shfl_xor_sync(0xffffffffu, sq, o);
    __shared__ float ws[4];
    if ((d & 31) == 0) ws[d >> 5] = sq;
    __syncthreads();
    const float total = ws[0] + ws[1] + ws[2] + ws[3];
    const float rn = rsqrtf(total * (1.f / 128.f) + 1e-6f);

    __shared__ float sn[128];
    sn[d] = v * rn * w[d];
    __syncthreads();

    float out;
    if (d < 64) {
        float ang = depth * __expf(-(float)d * 0.14391156f);   // ln(10000)/64
        out = sn[d] * cosf(ang) - sn[d + 64] * sinf(ang);
    } else {
        int i = d - 64;
        float ang = depth * __expf(-(float)i * 0.14391156f);
        out = sn[i] * sinf(ang) + sn[d] * cosf(ang);
    }
    p[d] = out;
}

// ---------------- flash attention via tf32 mma.sync ----------------
// CTA: 128 q-rows x 1 head. 8 warps; warp w owns q rows [w*16, w*16+16).
// Q fragments live in registers. KV tile 32, double-buffered cp.async.
#define KTS 132
#define VTS 136
#define PTS 36
#define OFF_K0 0
#define OFF_K1 (32 * KTS)
#define OFF_V0 (2 * 32 * KTS)
#define OFF_V1 (OFF_V0 + 32 * VTS)
#define OFF_P  (OFF_V1 + 32 * VTS)
#define FSMEM  ((OFF_P + 128 * PTS) * 4)   // 87040 bytes

__global__ __launch_bounds__(256) void flashmma(
    const float* __restrict__ Qg, const float* __restrict__ Kg,
    const float* __restrict__ Vg, float* __restrict__ Og)
{
    extern __shared__ float sm[];
    float* KsB[2] = { sm + OFF_K0, sm + OFF_K1 };
    float* VsB[2] = { sm + OFF_V0, sm + OFF_V1 };
    float* Ps = sm + OFF_P;

    const int tid  = threadIdx.x;
    const int wid  = tid >> 5, lane = tid & 31;
    const int gid  = lane >> 2, tig = lane & 3;
    const int h    = blockIdx.y;
    const int q0   = blockIdx.x * 128;
    const int hD   = h * DD;
    const int w16  = wid * 16;
    const float scale = 0.08838834764831845f;   // 1/sqrt(128)

    // ---- Q fragments in registers (scaled, RNE tf32) ----
    uint32_t qf[16][4];
    {
        const float* qr0 = Qg + (size_t)(q0 + w16 + gid) * CD + hD;
        const float* qr1 = qr0 + (size_t)8 * CD;
#pragma unroll
        for (int ks = 0; ks < 16; ks++) {
            const int k = ks * 8;
            qf[ks][0] = __float_as_uint(tf32r(qr0[k + tig    ] * scale));
            qf[ks][1] = __float_as_uint(tf32r(qr1[k + tig    ] * scale));
            qf[ks][2] = __float_as_uint(tf32r(qr0[k + tig + 4] * scale));
            qf[ks][3] = __float_as_uint(tf32r(qr1[k + tig + 4] * scale));
        }
    }

    auto prefetch = [&](int it) {
        const int b = it & 1;
        const int k0 = it * 32;
        const uint32_t kd = (uint32_t)__cvta_generic_to_shared(KsB[b]);
        const uint32_t vd = (uint32_t)__cvta_generic_to_shared(VsB[b]);
#pragma unroll
        for (int i = 0; i < 4; i++) {
            const int idx = i * 256 + tid;
            const int r = idx >> 5, c = (idx & 31) * 4;
            CPASYNC16(kd + (r * KTS + c) * 4, Kg + (size_t)(k0 + r) * CD + hD + c);
            CPASYNC16(vd + (r * VTS + c) * 4, Vg + (size_t)(k0 + r) * CD + hD + c);
        }
        CPCOMMIT();
    };

    const int NIT = KVL / 32;   // 128
    prefetch(0);
    prefetch(1);

    float m0 = -1e30f, m1 = -1e30f, l0 = 0.f, l1 = 0.f;
    float o[16][4];
#pragma unroll
    for (int ni = 0; ni < 16; ni++)
#pragma unroll
        for (int r = 0; r < 4; r++) o[ni][r] = 0.f;

    for (int it = 0; it < NIT; it++) {
        const int b = it & 1;
        const float* Ks = KsB[b];
        const float* Vs = VsB[b];

        if (it + 1 < NIT) CPWAIT1(); else CPWAIT0();
        __syncthreads();

        // ---- S = Q K^T ----
        float sc[4][4];
#pragma unroll
        for (int ni = 0; ni < 4; ni++)
#pragma unroll
            for (int r = 0; r < 4; r++) sc[ni][r] = 0.f;

#pragma unroll
        for (int ks = 0; ks < 16; ks++) {
            const int k = ks * 8;
#pragma unroll
            for (int ni = 0; ni < 4; ni++) {
                uint32_t bf[2];
                bf[0] = __float_as_uint(Ks[(ni * 8 + gid) * KTS + k + tig    ]);
                bf[1] = __float_as_uint(Ks[(ni * 8 + gid) * KTS + k + tig + 4]);
                mma_tf32(sc[ni], qf[ks], bf);
            }
        }

        // ---- online softmax (rows gid and gid+8; reduce over 4 tig lanes) ----
        float rm0 = -1e30f, rm1 = -1e30f;
#pragma unroll
        for (int ni = 0; ni < 4; ni++) {
            rm0 = fmaxf(rm0, fmaxf(sc[ni][0], sc[ni][1]));
            rm1 = fmaxf(rm1, fmaxf(sc[ni][2], sc[ni][3]));
        }
        rm0 = fmaxf(rm0, __shfl_xor_sync(0xffffffffu, rm0, 1));
        rm0 = fmaxf(rm0, __shfl_xor_sync(0xffffffffu, rm0, 2));
        rm1 = fmaxf(rm1, __shfl_xor_sync(0xffffffffu, rm1, 1));
        rm1 = fmaxf(rm1, __shfl_xor_sync(0xffffffffu, rm1, 2));

        const float mn0 = fmaxf(m0, rm0), mn1 = fmaxf(m1, rm1);
        const float a0 = __expf(m0 - mn0), a1 = __expf(m1 - mn1);
        m0 = mn0; m1 = mn1;

        float rs0 = 0.f, rs1 = 0.f;
#pragma unroll
        for (int ni = 0; ni < 4; ni++) {
            sc[ni][0] = __expf(sc[ni][0] - mn0);
            sc[ni][1] = __expf(sc[ni][1] - mn0);
            sc[ni][2] = __expf(sc[ni][2] - mn1);
            sc[ni][3] = __expf(sc[ni][3] - mn1);
            rs0 += sc[ni][0] + sc[ni][1];
            rs1 += sc[ni][2] + sc[ni][3];
        }
        rs0 += __shfl_xor_sync(0xffffffffu, rs0, 1);
        rs0 += __shfl_xor_sync(0xffffffffu, rs0, 2);
        rs1 += __shfl_xor_sync(0xffffffffu, rs1, 1);
        rs1 += __shfl_xor_sync(0xffffffffu, rs1, 2);
        l0 = l0 * a0 + rs0;
        l1 = l1 * a1 + rs1;

#pragma unroll
        for (int ni = 0; ni < 16; ni++) {
            o[ni][0] *= a0; o[ni][1] *= a0;
            o[ni][2] *= a1; o[ni][3] *= a1;
        }

        // ---- store P (warp-private rows) ----
#pragma unroll
        for (int ni = 0; ni < 4; ni++) {
            const int col = ni * 8 + tig * 2;
            *(float2*)&Ps[(w16 + gid    ) * PTS + col] =
                make_float2(tf32r(sc[ni][0]), tf32r(sc[ni][1]));
            *(float2*)&Ps[(w16 + gid + 8) * PTS + col] =
                make_float2(tf32r(sc[ni][2]), tf32r(sc[ni][3]));
        }
        __syncwarp();

        // ---- O += P V  (V^T fragments via swapped indexing) ----
#pragma unroll
        for (int ks = 0; ks < 4; ks++) {
            const int k = ks * 8;
            uint32_t paf[4];
            paf[0] = __float_as_uint(Ps[(w16 + gid    ) * PTS + k + tig    ]);
            paf[1] = __float_as_uint(Ps[(w16 + gid + 8) * PTS + k + tig    ]);
            paf[2] = __float_as_uint(Ps[(w16 + gid    ) * PTS + k + tig + 4]);
            paf[3] = __float_as_uint(Ps[(w16 + gid + 8) * PTS + k + tig + 4]);
#pragma unroll
            for (int ni = 0; ni < 16; ni++) {
                const int d = ni * 8;
                uint32_t bf[2];
                bf[0] = __float_as_uint(Vs[(k + tig    ) * VTS + d + gid]);
                bf[1] = __float_as_uint(Vs[(k + tig + 4) * VTS + d + gid]);
                mma_tf32(o[ni], paf, bf);
            }
        }

        __syncthreads();
        if (it + 2 < NIT) prefetch(it + 2);
    }

    // ---- epilogue ----
    const float inv0 = 1.f / l0, inv1 = 1.f / l1;
    const int row0 = q0 + w16 + gid;
#pragma unroll
    for (int ni = 0; ni < 16; ni++) {
        const int col = hD + ni * 8 + tig * 2;
        *(float2*)(Og + (size_t)row0 * CD + col) =
            make_float2(o[ni][0] * inv0, o[ni][1] * inv0);
        *(float2*)(Og + (size_t)(row0 + 8) * CD + col) =
            make_float2(o[ni][2] * inv1, o[ni][3] * inv1);
    }
}

// ---------------- position features ----------------
__global__ __launch_bounds__(256) void pos_hidden(
    float* __restrict__ ph, const float* __restrict__ sw1, const float* __restrict__ sb1)
{
    const int idx = blockIdx.x * 256 + threadIdx.x;
    const int l = idx >> 11;
    const int c = idx & 2047;
    const float coord = -1.f + 2.f * (float)l / 2047.f;
    ph[idx] = sinf(30.f * (coord * sw1[c] + sb1[c]));
}

// ---------------- final: out = x + rmsnorm(O + pos, on_w) ----------------
__global__ __launch_bounds__(256) void fuse_out(
    const float* __restrict__ x, const float* __restrict__ ov,
    const float* __restrict__ pos, const float* __restrict__ w,
    float* __restrict__ out)
{
    __shared__ float t[2048];
    __shared__ float red[8];
    const int l = blockIdx.x;
    const int tid = threadIdx.x;
    float sq = 0.f;
    for (int c = tid; c < 2048; c += 256) {
        const float v = ov[(size_t)l * 2048 + c] + pos[(size_t)l * 2048 + c];
        t[c] = v; sq += v * v;
    }
#pragma unroll
    for (int o = 16; o > 0; o >>= 1) sq += __shfl_xor_sync(0xffffffffu, sq, o);
    if ((tid & 31) == 0) red[tid >> 5] = sq;
    __syncthreads();
    float total = 0.f;
#pragma unroll
    for (int i = 0; i < 8; i++) total += red[i];
    const float rn = rsqrtf(total * (1.f / 2048.f) + 1e-6f);
    for (int c = tid; c < 2048; c += 256)
        out[(size_t)l * 2048 + c] = x[(size_t)l * 2048 + c] + t[c] * rn * w[c];
}

// ---------------- launch ----------------
extern "C" void kernel_launch(void* const* d_in, const int* in_sizes, int n_in,
                              void* d_out, int out_size)
{
    (void)in_sizes; (void)n_in; (void)out_size;
    const float* x   = (const float*)d_in[0];
    const float* h0  = (const float*)d_in[1];
    const float* h1  = (const float*)d_in[2];
    const float* h2  = (const float*)d_in[3];
    const float* Wq  = (const float*)d_in[4];
    const float* Wk  = (const float*)d_in[5];
    const float* Wv  = (const float*)d_in[6];
    const float* Wo  = (const float*)d_in[7];
    const float* qn  = (const float*)d_in[8];
    const float* kn  = (const float*)d_in[9];
    const float* on  = (const float*)d_in[10];
    const float* sw1 = (const float*)d_in[11];
    const float* sb1 = (const float*)d_in[12];
    const float* sw2 = (const float*)d_in[13];
    const float* sb2 = (const float*)d_in[14];
    float* out = (float*)d_out;

    float *Q, *K, *V, *AO, *O, *PH, *PS;
    cudaGetSymbolAddress((void**)&Q,  gQ);
    cudaGetSymbolAddress((void**)&K,  gK);
    cudaGetSymbolAddress((void**)&V,  gV);
    cudaGetSymbolAddress((void**)&AO, gAO);
    cudaGetSymbolAddress((void**)&O,  gO);
    cudaGetSymbolAddress((void**)&PH, gPH);
    cudaGetSymbolAddress((void**)&PS, gPS);

    cudaFuncSetAttribute(mmagemm<true,  false>, cudaFuncAttributeMaxDynamicSharedMemorySize, GSMEM);
    cudaFuncSetAttribute(mmagemm<false, true >, cudaFuncAttributeMaxDynamicSharedMemorySize, GSMEM);
    cudaFuncSetAttribute(flashmma, cudaFuncAttributeMaxDynamicSharedMemorySize, FSMEM);

    const dim3 gg(16, 16);
    const size_t LC = (size_t)LQ * CD;

    mmagemm<true,  false><<<gg, 256, GSMEM>>>(h2, Wq, nullptr, Q,      2048, 2048, 2048);
    mmagemm<true,  false><<<gg, 256, GSMEM>>>(h0, Wk, nullptr, K,      2048, 2048, 2048);
    mmagemm<true,  false><<<gg, 256, GSMEM>>>(h1, Wk, nullptr, K + LC, 2048, 2048, 2048);
    mmagemm<true,  false><<<gg, 256, GSMEM>>>(h0, Wv, nullptr, V,      2048, 2048, 2048);
    mmagemm<true,  false><<<gg, 256, GSMEM>>>(h1, Wv, nullptr, V + LC, 2048, 2048, 2048);

    const dim3 gn(LQ, HN);
    normrope<<<gn, 128>>>(Q,      qn, 2.f);
    normrope<<<gn, 128>>>(K,      kn, 0.f);
    normrope<<<gn, 128>>>(K + LC, kn, 1.f);

    flashmma<<<dim3(16, 16), 256, FSMEM>>>(Q, K, V, AO);

    mmagemm<true,  false><<<gg, 256, GSMEM>>>(AO, Wo, nullptr, O, 2048, 2048, 2048);

    pos_hidden<<<(LQ * CD) / 256, 256>>>(PH, sw1, sb1);
    mmagemm<false, true ><<<gg, 256, GSMEM>>>(PH, sw2, sb2, PS, 2048, 2048, 2048);

    fuse_out<<<LQ, 256>>>(x, O, PS, on, out);
}

// round 6
// speedup vs baseline: 3.7365x; 1.0695x over previous
#include <cuda_runtime.h>
#include <cstdint>
#include <math.h>

#define LQ   2048
#define CD   2048
#define HN   16
#define DD   128
#define KVL  4096

// ---------------- scratch (device globals; no allocation) ----------------
__device__ float gQ [LQ  * CD];
__device__ float gK [KVL * CD];
__device__ float gV [KVL * CD];
__device__ float gAO[LQ  * CD];
__device__ float gO [LQ  * CD];
__device__ float gPH[LQ  * CD];
__device__ float gPS[LQ  * CD];

// ---------------- helpers ----------------
__device__ __forceinline__ float tf32r(float x) {
    uint32_t u;
    asm("cvt.rna.tf32.f32 %0, %1;" : "=r"(u) : "f"(x));
    return __uint_as_float(u);
}

__device__ __forceinline__ void mma_tf32(float c[4], const uint32_t a[4], const uint32_t b[2]) {
    asm volatile(
        "mma.sync.aligned.m16n8k8.row.col.f32.tf32.tf32.f32 "
        "{%0,%1,%2,%3}, {%4,%5,%6,%7}, {%8,%9}, {%0,%1,%2,%3};"
        : "+f"(c[0]), "+f"(c[1]), "+f"(c[2]), "+f"(c[3])
        : "r"(a[0]), "r"(a[1]), "r"(a[2]), "r"(a[3]), "r"(b[0]), "r"(b[1]));
}

#define CPASYNC16(dst, src) \
    asm volatile("cp.async.cg.shared.global [%0], [%1], 16;" :: "r"(dst), "l"(src) : "memory")
#define CPCOMMIT()   asm volatile("cp.async.commit_group;" ::: "memory")
#define CPWAIT1()    asm volatile("cp.async.wait_group 1;" ::: "memory")
#define CPWAIT0()    asm volatile("cp.async.wait_group 0;" ::: "memory")

// ---------------- tf32 mma.sync GEMM core ----------------
// CTA tile 128x128, BK=32, 128 threads (4 warps, 2m x 2n, warp tile 64x64).
// 2-stage cp.async double buffer.
#define GS_TILE 4608                       // floats per stage tile (128*36; BN stage 32*132=4224)
#define GSMEM   (4 * GS_TILE * 4)          // 73728 bytes

template<bool BT, bool BIAS>
__device__ __forceinline__ void gemm_core(
    const float* __restrict__ A, const float* __restrict__ B,
    const float* __restrict__ bias, float* __restrict__ Cc,
    int M, int N, int K)
{
    extern __shared__ float smemf[];
    const uint32_t sbase = (uint32_t)__cvta_generic_to_shared(smemf);

    const int tid  = threadIdx.x;          // 0..127
    const int wid  = tid >> 5, lane = tid & 31;
    const int gid  = lane >> 2, tig = lane & 3;
    const int wm   = (wid & 1) * 64;
    const int wn   = (wid >> 1) * 64;
    const int bm   = blockIdx.y * 128, bn = blockIdx.x * 128;

    float c[4][8][4];
#pragma unroll
    for (int i = 0; i < 4; i++)
#pragma unroll
        for (int j = 0; j < 8; j++)
#pragma unroll
            for (int r = 0; r < 4; r++) c[i][j][r] = 0.f;

    const int NK = K >> 5;

    auto prefetch = [&](int kc) {
        const int s = kc & 1;
        const int k0 = kc << 5;
        const uint32_t ab = sbase + (s * GS_TILE) * 4;
        const uint32_t bb = sbase + ((2 + s) * GS_TILE) * 4;
#pragma unroll
        for (int i = 0; i < 8; i++) {
            const int idx = i * 128 + tid;
            const int r = idx >> 3, cc = (idx & 7) * 4;
            CPASYNC16(ab + (r * 36 + cc) * 4, A + (size_t)(bm + r) * K + k0 + cc);
        }
        if (BT) {
#pragma unroll
            for (int i = 0; i < 8; i++) {
                const int idx = i * 128 + tid;
                const int r = idx >> 3, cc = (idx & 7) * 4;
                CPASYNC16(bb + (r * 36 + cc) * 4, B + (size_t)(bn + r) * K + k0 + cc);
            }
        } else {
#pragma unroll
            for (int i = 0; i < 8; i++) {
                const int idx = i * 128 + tid;
                const int kr = idx >> 5, cc = (idx & 31) * 4;
                CPASYNC16(bb + (kr * 132 + cc) * 4, B + (size_t)(k0 + kr) * N + bn + cc);
            }
        }
        CPCOMMIT();
    };

    prefetch(0);

    for (int kc = 0; kc < NK; kc++) {
        const bool more = (kc + 1 < NK);
        if (more) prefetch(kc + 1);
        if (more) CPWAIT1(); else CPWAIT0();
        __syncthreads();

        const float* sA = smemf + (kc & 1) * GS_TILE;
        const float* sB = smemf + (2 + (kc & 1)) * GS_TILE;

#pragma unroll
        for (int ks = 0; ks < 4; ks++) {
            const int k = ks * 8;
            uint32_t af[4][4], bf[8][2];
#pragma unroll
            for (int mi = 0; mi < 4; mi++) {
                const int m = wm + mi * 16;
                af[mi][0] = __float_as_uint(sA[(m + gid    ) * 36 + k + tig    ]);
                af[mi][1] = __float_as_uint(sA[(m + gid + 8) * 36 + k + tig    ]);
                af[mi][2] = __float_as_uint(sA[(m + gid    ) * 36 + k + tig + 4]);
                af[mi][3] = __float_as_uint(sA[(m + gid + 8) * 36 + k + tig + 4]);
            }
#pragma unroll
            for (int ni = 0; ni < 8; ni++) {
                const int n = wn + ni * 8 + gid;
                if (BT) {
                    bf[ni][0] = __float_as_uint(sB[n * 36 + k + tig    ]);
                    bf[ni][1] = __float_as_uint(sB[n * 36 + k + tig + 4]);
                } else {
                    bf[ni][0] = __float_as_uint(sB[(k + tig    ) * 132 + n]);
                    bf[ni][1] = __float_as_uint(sB[(k + tig + 4) * 132 + n]);
                }
            }
#pragma unroll
            for (int mi = 0; mi < 4; mi++)
#pragma unroll
                for (int ni = 0; ni < 8; ni++)
                    mma_tf32(c[mi][ni], af[mi], bf[ni]);
        }
        __syncthreads();
    }

#pragma unroll
    for (int mi = 0; mi < 4; mi++) {
        const int row0 = bm + wm + mi * 16 + gid;
#pragma unroll
        for (int ni = 0; ni < 8; ni++) {
            const int col = bn + wn + ni * 8 + tig * 2;
            float2 v0 = make_float2(c[mi][ni][0], c[mi][ni][1]);
            float2 v1 = make_float2(c[mi][ni][2], c[mi][ni][3]);
            if (BIAS) {
                const float b0 = bias[col], b1 = bias[col + 1];
                v0.x += b0; v0.y += b1; v1.x += b0; v1.y += b1;
            }
            *(float2*)(Cc + (size_t)row0 * N + col)       = v0;
            *(float2*)(Cc + (size_t)(row0 + 8) * N + col) = v1;
        }
    }
}

template<bool BT, bool BIAS>
__global__ __launch_bounds__(128) void mmagemm(
    const float* __restrict__ A, const float* __restrict__ B,
    const float* __restrict__ bias, float* __restrict__ Cc,
    int M, int N, int K)
{
    gemm_core<BT, BIAS>(A, B, bias, Cc, M, N, K);
}

// batched projections: z selects (A, B, C), all 2048^3 NT
struct Proj5 {
    const float* A[5];
    const float* B[5];
    float*       C[5];
};
__global__ __launch_bounds__(128) void proj5_kernel(Proj5 jobs)
{
    const int z = blockIdx.z;
    gemm_core<true, false>(jobs.A[z], jobs.B[z], nullptr, jobs.C[z], 2048, 2048, 2048);
}

// ---------------- per-(row,head) rmsnorm + depth rope ----------------
__global__ __launch_bounds__(128) void normrope(
    float* __restrict__ buf, const float* __restrict__ w, float depth)
{
    const int row = blockIdx.x;
    const int h   = blockIdx.y;
    float* p = buf + (size_t)row * CD + h * DD;
    const int d = threadIdx.x;

    float v  = p[d];
    float sq = v * v;
#pragma unroll
    for (int o = 16; o > 0; o >>= 1) sq += __shfl_xor_sync(0xffffffffu, sq, o);
    __shared__ float ws[4];
    if ((d & 31) == 0) ws[d >> 5] = sq;
    __syncthreads();
    const float total = ws[0] + ws[1] + ws[2] + ws[3];
    const float rn = rsqrtf(total * (1.f / 128.f) + 1e-6f);

    __shared__ float sn[128];
    sn[d] = v * rn * w[d];
    __syncthreads();

    float out;
    if (d < 64) {
        float ang = depth * __expf(-(float)d * 0.14391156f);   // ln(10000)/64
        out = sn[d] * cosf(ang) - sn[d + 64] * sinf(ang);
    } else {
        int i = d - 64;
        float ang = depth * __expf(-(float)i * 0.14391156f);
        out = sn[i] * sinf(ang) + sn[d] * cosf(ang);
    }
    p[d] = out;
}

// ---------------- flash attention via tf32 mma.sync ----------------
// CTA: 128 q-rows x 1 head. 8 warps; warp w owns q rows [w*16, w*16+16).
// Q fragments live in registers. KV tile 32, double-buffered cp.async.
#define KTS 132
#define VTS 136
#define PTS 36
#define OFF_K0 0
#define OFF_K1 (32 * KTS)
#define OFF_V0 (2 * 32 * KTS)
#define OFF_V1 (OFF_V0 + 32 * VTS)
#define OFF_P  (OFF_V1 + 32 * VTS)
#define FSMEM  ((OFF_P + 128 * PTS) * 4)   // 87040 bytes

__global__ __launch_bounds__(256) void flashmma(
    const float* __restrict__ Qg, const float* __restrict__ Kg,
    const float* __restrict__ Vg, float* __restrict__ Og)
{
    extern __shared__ float sm[];
    float* KsB[2] = { sm + OFF_K0, sm + OFF_K1 };
    float* VsB[2] = { sm + OFF_V0, sm + OFF_V1 };
    float* Ps = sm + OFF_P;

    const int tid  = threadIdx.x;
    const int wid  = tid >> 5, lane = tid & 31;
    const int gid  = lane >> 2, tig = lane & 3;
    const int h    = blockIdx.y;
    const int q0   = blockIdx.x * 128;
    const int hD   = h * DD;
    const int w16  = wid * 16;
    const float scale = 0.08838834764831845f;   // 1/sqrt(128)

    // ---- Q fragments in registers (scaled, RNE tf32) ----
    uint32_t qf[16][4];
    {
        const float* qr0 = Qg + (size_t)(q0 + w16 + gid) * CD + hD;
        const float* qr1 = qr0 + (size_t)8 * CD;
#pragma unroll
        for (int ks = 0; ks < 16; ks++) {
            const int k = ks * 8;
            qf[ks][0] = __float_as_uint(tf32r(qr0[k + tig    ] * scale));
            qf[ks][1] = __float_as_uint(tf32r(qr1[k + tig    ] * scale));
            qf[ks][2] = __float_as_uint(tf32r(qr0[k + tig + 4] * scale));
            qf[ks][3] = __float_as_uint(tf32r(qr1[k + tig + 4] * scale));
        }
    }

    auto prefetch = [&](int it) {
        const int b = it & 1;
        const int k0 = it * 32;
        const uint32_t kd = (uint32_t)__cvta_generic_to_shared(KsB[b]);
        const uint32_t vd = (uint32_t)__cvta_generic_to_shared(VsB[b]);
#pragma unroll
        for (int i = 0; i < 4; i++) {
            const int idx = i * 256 + tid;
            const int r = idx >> 5, c = (idx & 31) * 4;
            CPASYNC16(kd + (r * KTS + c) * 4, Kg + (size_t)(k0 + r) * CD + hD + c);
            CPASYNC16(vd + (r * VTS + c) * 4, Vg + (size_t)(k0 + r) * CD + hD + c);
        }
        CPCOMMIT();
    };

    const int NIT = KVL / 32;   // 128
    prefetch(0);
    prefetch(1);

    float m0 = -1e30f, m1 = -1e30f, l0 = 0.f, l1 = 0.f;
    float o[16][4];
#pragma unroll
    for (int ni = 0; ni < 16; ni++)
#pragma unroll
        for (int r = 0; r < 4; r++) o[ni][r] = 0.f;

    for (int it = 0; it < NIT; it++) {
        const int b = it & 1;
        const float* Ks = KsB[b];
        const float* Vs = VsB[b];

        if (it + 1 < NIT) CPWAIT1(); else CPWAIT0();
        __syncthreads();

        // ---- S = Q K^T ----
        float sc[4][4];
#pragma unroll
        for (int ni = 0; ni < 4; ni++)
#pragma unroll
            for (int r = 0; r < 4; r++) sc[ni][r] = 0.f;

#pragma unroll
        for (int ks = 0; ks < 16; ks++) {
            const int k = ks * 8;
#pragma unroll
            for (int ni = 0; ni < 4; ni++) {
                uint32_t bf[2];
                bf[0] = __float_as_uint(Ks[(ni * 8 + gid) * KTS + k + tig    ]);
                bf[1] = __float_as_uint(Ks[(ni * 8 + gid) * KTS + k + tig + 4]);
                mma_tf32(sc[ni], qf[ks], bf);
            }
        }

        // ---- online softmax ----
        float rm0 = -1e30f, rm1 = -1e30f;
#pragma unroll
        for (int ni = 0; ni < 4; ni++) {
            rm0 = fmaxf(rm0, fmaxf(sc[ni][0], sc[ni][1]));
            rm1 = fmaxf(rm1, fmaxf(sc[ni][2], sc[ni][3]));
        }
        rm0 = fmaxf(rm0, __shfl_xor_sync(0xffffffffu, rm0, 1));
        rm0 = fmaxf(rm0, __shfl_xor_sync(0xffffffffu, rm0, 2));
        rm1 = fmaxf(rm1, __shfl_xor_sync(0xffffffffu, rm1, 1));
        rm1 = fmaxf(rm1, __shfl_xor_sync(0xffffffffu, rm1, 2));

        const float mn0 = fmaxf(m0, rm0), mn1 = fmaxf(m1, rm1);
        const float a0 = __expf(m0 - mn0), a1 = __expf(m1 - mn1);
        m0 = mn0; m1 = mn1;

        float rs0 = 0.f, rs1 = 0.f;
#pragma unroll
        for (int ni = 0; ni < 4; ni++) {
            sc[ni][0] = __expf(sc[ni][0] - mn0);
            sc[ni][1] = __expf(sc[ni][1] - mn0);
            sc[ni][2] = __expf(sc[ni][2] - mn1);
            sc[ni][3] = __expf(sc[ni][3] - mn1);
            rs0 += sc[ni][0] + sc[ni][1];
            rs1 += sc[ni][2] + sc[ni][3];
        }
        rs0 += __shfl_xor_sync(0xffffffffu, rs0, 1);
        rs0 += __shfl_xor_sync(0xffffffffu, rs0, 2);
        rs1 += __shfl_xor_sync(0xffffffffu, rs1, 1);
        rs1 += __shfl_xor_sync(0xffffffffu, rs1, 2);
        l0 = l0 * a0 + rs0;
        l1 = l1 * a1 + rs1;

#pragma unroll
        for (int ni = 0; ni < 16; ni++) {
            o[ni][0] *= a0; o[ni][1] *= a0;
            o[ni][2] *= a1; o[ni][3] *= a1;
        }

        // ---- store P (warp-private rows) ----
#pragma unroll
        for (int ni = 0; ni < 4; ni++) {
            const int col = ni * 8 + tig * 2;
            *(float2*)&Ps[(w16 + gid    ) * PTS + col] =
                make_float2(tf32r(sc[ni][0]), tf32r(sc[ni][1]));
            *(float2*)&Ps[(w16 + gid + 8) * PTS + col] =
                make_float2(tf32r(sc[ni][2]), tf32r(sc[ni][3]));
        }
        __syncwarp();

        // ---- O += P V ----
#pragma unroll
        for (int ks = 0; ks < 4; ks++) {
            const int k = ks * 8;
            uint32_t paf[4];
            paf[0] = __float_as_uint(Ps[(w16 + gid    ) * PTS + k + tig    ]);
            paf[1] = __float_as_uint(Ps[(w16 + gid + 8) * PTS + k + tig    ]);
            paf[2] = __float_as_uint(Ps[(w16 + gid    ) * PTS + k + tig + 4]);
            paf[3] = __float_as_uint(Ps[(w16 + gid + 8) * PTS + k + tig + 4]);
#pragma unroll
            for (int ni = 0; ni < 16; ni++) {
                const int d = ni * 8;
                uint32_t bf[2];
                bf[0] = __float_as_uint(Vs[(k + tig    ) * VTS + d + gid]);
                bf[1] = __float_as_uint(Vs[(k + tig + 4) * VTS + d + gid]);
                mma_tf32(o[ni], paf, bf);
            }
        }

        __syncthreads();
        if (it + 2 < NIT) prefetch(it + 2);
    }

    // ---- epilogue ----
    const float inv0 = 1.f / l0, inv1 = 1.f / l1;
    const int row0 = q0 + w16 + gid;
#pragma unroll
    for (int ni = 0; ni < 16; ni++) {
        const int col = hD + ni * 8 + tig * 2;
        *(float2*)(Og + (size_t)row0 * CD + col) =
            make_float2(o[ni][0] * inv0, o[ni][1] * inv0);
        *(float2*)(Og + (size_t)(row0 + 8) * CD + col) =
            make_float2(o[ni][2] * inv1, o[ni][3] * inv1);
    }
}

// ---------------- position features ----------------
__global__ __launch_bounds__(256) void pos_hidden(
    float* __restrict__ ph, const float* __restrict__ sw1, const float* __restrict__ sb1)
{
    const int idx = blockIdx.x * 256 + threadIdx.x;
    const int l = idx >> 11;
    const int c = idx & 2047;
    const float coord = -1.f + 2.f * (float)l / 2047.f;
    ph[idx] = sinf(30.f * (coord * sw1[c] + sb1[c]));
}

// ---------------- final: out = x + rmsnorm(O + pos, on_w) ----------------
__global__ __launch_bounds__(256) void fuse_out(
    const float* __restrict__ x, const float* __restrict__ ov,
    const float* __restrict__ pos, const float* __restrict__ w,
    float* __restrict__ out)
{
    __shared__ float t[2048];
    __shared__ float red[8];
    const int l = blockIdx.x;
    const int tid = threadIdx.x;
    float sq = 0.f;
    for (int c = tid; c < 2048; c += 256) {
        const float v = ov[(size_t)l * 2048 + c] + pos[(size_t)l * 2048 + c];
        t[c] = v; sq += v * v;
    }
#pragma unroll
    for (int o = 16; o > 0; o >>= 1) sq += __shfl_xor_sync(0xffffffffu, sq, o);
    if ((tid & 31) == 0) red[tid >> 5] = sq;
    __syncthreads();
    float total = 0.f;
#pragma unroll
    for (int i = 0; i < 8; i++) total += red[i];
    const float rn = rsqrtf(total * (1.f / 2048.f) + 1e-6f);
    for (int c = tid; c < 2048; c += 256)
        out[(size_t)l * 2048 + c] = x[(size_t)l * 2048 + c] + t[c] * rn * w[c];
}

// ---------------- launch ----------------
extern "C" void kernel_launch(void* const* d_in, const int* in_sizes, int n_in,
                              void* d_out, int out_size)
{
    (void)in_sizes; (void)n_in; (void)out_size;
    const float* x   = (const float*)d_in[0];
    const float* h0  = (const float*)d_in[1];
    const float* h1  = (const float*)d_in[2];
    const float* h2  = (const float*)d_in[3];
    const float* Wq  = (const float*)d_in[4];
    const float* Wk  = (const float*)d_in[5];
    const float* Wv  = (const float*)d_in[6];
    const float* Wo  = (const float*)d_in[7];
    const float* qn  = (const float*)d_in[8];
    const float* kn  = (const float*)d_in[9];
    const float* on  = (const float*)d_in[10];
    const float* sw1 = (const float*)d_in[11];
    const float* sb1 = (const float*)d_in[12];
    const float* sw2 = (const float*)d_in[13];
    const float* sb2 = (const float*)d_in[14];
    float* out = (float*)d_out;

    float *Q, *K, *V, *AO, *O, *PH, *PS;
    cudaGetSymbolAddress((void**)&Q,  gQ);
    cudaGetSymbolAddress((void**)&K,  gK);
    cudaGetSymbolAddress((void**)&V,  gV);
    cudaGetSymbolAddress((void**)&AO, gAO);
    cudaGetSymbolAddress((void**)&O,  gO);
    cudaGetSymbolAddress((void**)&PH, gPH);
    cudaGetSymbolAddress((void**)&PS, gPS);

    cudaFuncSetAttribute(proj5_kernel,          cudaFuncAttributeMaxDynamicSharedMemorySize, GSMEM);
    cudaFuncSetAttribute(mmagemm<true,  false>, cudaFuncAttributeMaxDynamicSharedMemorySize, GSMEM);
    cudaFuncSetAttribute(mmagemm<false, true >, cudaFuncAttributeMaxDynamicSharedMemorySize, GSMEM);
    cudaFuncSetAttribute(flashmma,              cudaFuncAttributeMaxDynamicSharedMemorySize, FSMEM);

    const size_t LC = (size_t)LQ * CD;

    Proj5 jobs;
    jobs.A[0] = h2; jobs.B[0] = Wq; jobs.C[0] = Q;
    jobs.A[1] = h0; jobs.B[1] = Wk; jobs.C[1] = K;
    jobs.A[2] = h1; jobs.B[2] = Wk; jobs.C[2] = K + LC;
    jobs.A[3] = h0; jobs.B[3] = Wv; jobs.C[3] = V;
    jobs.A[4] = h1; jobs.B[4] = Wv; jobs.C[4] = V + LC;
    proj5_kernel<<<dim3(16, 16, 5), 128, GSMEM>>>(jobs);

    const dim3 gn(LQ, HN);
    normrope<<<gn, 128>>>(Q,      qn, 2.f);
    normrope<<<gn, 128>>>(K,      kn, 0.f);
    normrope<<<gn, 128>>>(K + LC, kn, 1.f);

    flashmma<<<dim3(16, 16), 256, FSMEM>>>(Q, K, V, AO);

    mmagemm<true,  false><<<dim3(16, 16), 128, GSMEM>>>(AO, Wo, nullptr, O, 2048, 2048, 2048);

    pos_hidden<<<(LQ * CD) / 256, 256>>>(PH, sw1, sb1);
    mmagemm<false, true ><<<dim3(16, 16), 128, GSMEM>>>(PH, sw2, sb2, PS, 2048, 2048, 2048);

    fuse_out<<<LQ, 256>>>(x, O, PS, on, out);
}

// round 7
// speedup vs baseline: 3.9058x; 1.0453x over previous
#include <cuda_runtime.h>
#include <cstdint>
#include <math.h>

#define LQ   2048
#define CD   2048
#define HN   16
#define DD   128
#define KVL  4096

// ---------------- scratch (device globals; no allocation) ----------------
__device__ float gQ [LQ  * CD];
__device__ float gK [KVL * CD];
__device__ float gV [KVL * CD];
__device__ float gAO[LQ  * CD];
__device__ float gO [LQ  * CD];
__device__ float gPH[LQ  * CD];
__device__ float gPS[LQ  * CD];

// ---------------- helpers ----------------
__device__ __forceinline__ float tf32r(float x) {
    uint32_t u;
    asm("cvt.rna.tf32.f32 %0, %1;" : "=r"(u) : "f"(x));
    return __uint_as_float(u);
}

__device__ __forceinline__ void mma_tf32(float c[4], const uint32_t a[4], const uint32_t b[2]) {
    asm volatile(
        "mma.sync.aligned.m16n8k8.row.col.f32.tf32.tf32.f32 "
        "{%0,%1,%2,%3}, {%4,%5,%6,%7}, {%8,%9}, {%0,%1,%2,%3};"
        : "+f"(c[0]), "+f"(c[1]), "+f"(c[2]), "+f"(c[3])
        : "r"(a[0]), "r"(a[1]), "r"(a[2]), "r"(a[3]), "r"(b[0]), "r"(b[1]));
}

#define CPASYNC16(dst, src) \
    asm volatile("cp.async.cg.shared.global [%0], [%1], 16;" :: "r"(dst), "l"(src) : "memory")
#define CPCOMMIT()   asm volatile("cp.async.commit_group;" ::: "memory")
#define CPWAIT1()    asm volatile("cp.async.wait_group 1;" ::: "memory")
#define CPWAIT0()    asm volatile("cp.async.wait_group 0;" ::: "memory")

// ---------------- tf32 mma.sync GEMM core ----------------
// CTA tile 128x128, BK=32, 128 threads (4 warps, 2m x 2n, warp tile 64x64).
#define GS_TILE 4608
#define GSMEM   (4 * GS_TILE * 4)          // 73728 bytes

template<bool BT, bool BIAS>
__device__ __forceinline__ void gemm_core(
    const float* __restrict__ A, const float* __restrict__ B,
    const float* __restrict__ bias, float* __restrict__ Cc,
    int M, int N, int K)
{
    extern __shared__ float smemf[];
    const uint32_t sbase = (uint32_t)__cvta_generic_to_shared(smemf);

    const int tid  = threadIdx.x;
    const int wid  = tid >> 5, lane = tid & 31;
    const int gid  = lane >> 2, tig = lane & 3;
    const int wm   = (wid & 1) * 64;
    const int wn   = (wid >> 1) * 64;
    const int bm   = blockIdx.y * 128, bn = blockIdx.x * 128;

    float c[4][8][4];
#pragma unroll
    for (int i = 0; i < 4; i++)
#pragma unroll
        for (int j = 0; j < 8; j++)
#pragma unroll
            for (int r = 0; r < 4; r++) c[i][j][r] = 0.f;

    const int NK = K >> 5;

    auto prefetch = [&](int kc) {
        const int s = kc & 1;
        const int k0 = kc << 5;
        const uint32_t ab = sbase + (s * GS_TILE) * 4;
        const uint32_t bb = sbase + ((2 + s) * GS_TILE) * 4;
#pragma unroll
        for (int i = 0; i < 8; i++) {
            const int idx = i * 128 + tid;
            const int r = idx >> 3, cc = (idx & 7) * 4;
            CPASYNC16(ab + (r * 36 + cc) * 4, A + (size_t)(bm + r) * K + k0 + cc);
        }
        if (BT) {
#pragma unroll
            for (int i = 0; i < 8; i++) {
                const int idx = i * 128 + tid;
                const int r = idx >> 3, cc = (idx & 7) * 4;
                CPASYNC16(bb + (r * 36 + cc) * 4, B + (size_t)(bn + r) * K + k0 + cc);
            }
        } else {
#pragma unroll
            for (int i = 0; i < 8; i++) {
                const int idx = i * 128 + tid;
                const int kr = idx >> 5, cc = (idx & 31) * 4;
                CPASYNC16(bb + (kr * 132 + cc) * 4, B + (size_t)(k0 + kr) * N + bn + cc);
            }
        }
        CPCOMMIT();
    };

    prefetch(0);

    for (int kc = 0; kc < NK; kc++) {
        const bool more = (kc + 1 < NK);
        if (more) prefetch(kc + 1);
        if (more) CPWAIT1(); else CPWAIT0();
        __syncthreads();

        const float* sA = smemf + (kc & 1) * GS_TILE;
        const float* sB = smemf + (2 + (kc & 1)) * GS_TILE;

#pragma unroll
        for (int ks = 0; ks < 4; ks++) {
            const int k = ks * 8;
            uint32_t af[4][4], bf[8][2];
#pragma unroll
            for (int mi = 0; mi < 4; mi++) {
                const int m = wm + mi * 16;
                af[mi][0] = __float_as_uint(sA[(m + gid    ) * 36 + k + tig    ]);
                af[mi][1] = __float_as_uint(sA[(m + gid + 8) * 36 + k + tig    ]);
                af[mi][2] = __float_as_uint(sA[(m + gid    ) * 36 + k + tig + 4]);
                af[mi][3] = __float_as_uint(sA[(m + gid + 8) * 36 + k + tig + 4]);
            }
#pragma unroll
            for (int ni = 0; ni < 8; ni++) {
                const int n = wn + ni * 8 + gid;
                if (BT) {
                    bf[ni][0] = __float_as_uint(sB[n * 36 + k + tig    ]);
                    bf[ni][1] = __float_as_uint(sB[n * 36 + k + tig + 4]);
                } else {
                    bf[ni][0] = __float_as_uint(sB[(k + tig    ) * 132 + n]);
                    bf[ni][1] = __float_as_uint(sB[(k + tig + 4) * 132 + n]);
                }
            }
#pragma unroll
            for (int mi = 0; mi < 4; mi++)
#pragma unroll
                for (int ni = 0; ni < 8; ni++)
                    mma_tf32(c[mi][ni], af[mi], bf[ni]);
        }
        __syncthreads();
    }

#pragma unroll
    for (int mi = 0; mi < 4; mi++) {
        const int row0 = bm + wm + mi * 16 + gid;
#pragma unroll
        for (int ni = 0; ni < 8; ni++) {
            const int col = bn + wn + ni * 8 + tig * 2;
            float2 v0 = make_float2(c[mi][ni][0], c[mi][ni][1]);
            float2 v1 = make_float2(c[mi][ni][2], c[mi][ni][3]);
            if (BIAS) {
                const float b0 = bias[col], b1 = bias[col + 1];
                v0.x += b0; v0.y += b1; v1.x += b0; v1.y += b1;
            }
            *(float2*)(Cc + (size_t)row0 * N + col)       = v0;
            *(float2*)(Cc + (size_t)(row0 + 8) * N + col) = v1;
        }
    }
}

// batched projections: z selects (A, B, C), all 2048^3 NT
struct Proj5 {
    const float* A[5];
    const float* B[5];
    float*       C[5];
};
__global__ __launch_bounds__(128) void proj5_kernel(Proj5 jobs)
{
    const int z = blockIdx.z;
    gemm_core<true, false>(jobs.A[z], jobs.B[z], nullptr, jobs.C[z], 2048, 2048, 2048);
}

// combined Wo projection (z=0, NT) and pos projection (z=1, NN + bias)
__global__ __launch_bounds__(128) void gemm2_kernel(
    const float* AO, const float* Wo, float* O,
    const float* PH, const float* sw2, const float* sb2, float* PS)
{
    if (blockIdx.z == 0)
        gemm_core<true,  false>(AO, Wo, nullptr, O, 2048, 2048, 2048);
    else
        gemm_core<false, true >(PH, sw2, sb2, PS, 2048, 2048, 2048);
}

// ---------------- per-(row,head) rmsnorm + depth rope (3 tensors, one launch) ----------------
__global__ __launch_bounds__(128) void normrope3(
    float* __restrict__ Qb, float* __restrict__ Kb,
    const float* __restrict__ qn, const float* __restrict__ kn)
{
    const int z   = blockIdx.z;           // 0: Q(depth2), 1: K0(depth0), 2: K1(depth1)
    float* base   = (z == 0) ? Qb : (Kb + (size_t)(z - 1) * LQ * CD);
    const float* w = (z == 0) ? qn : kn;
    const float depth = (z == 0) ? 2.f : (float)(z - 1);

    const int row = blockIdx.x;
    const int h   = blockIdx.y;
    float* p = base + (size_t)row * CD + h * DD;
    const int d = threadIdx.x;

    float v  = p[d];
    float sq = v * v;
#pragma unroll
    for (int o = 16; o > 0; o >>= 1) sq += __shfl_xor_sync(0xffffffffu, sq, o);
    __shared__ float ws[4];
    if ((d & 31) == 0) ws[d >> 5] = sq;
    __syncthreads();
    const float total = ws[0] + ws[1] + ws[2] + ws[3];
    const float rn = rsqrtf(total * (1.f / 128.f) + 1e-6f);

    __shared__ float sn[128];
    sn[d] = v * rn * w[d];
    __syncthreads();

    float out;
    if (d < 64) {
        float ang = depth * __expf(-(float)d * 0.14391156f);   // ln(10000)/64
        out = sn[d] * cosf(ang) - sn[d + 64] * sinf(ang);
    } else {
        int i = d - 64;
        float ang = depth * __expf(-(float)i * 0.14391156f);
        out = sn[i] * sinf(ang) + sn[d] * cosf(ang);
    }
    p[d] = out;
}

// ---------------- flash attention via tf32 mma.sync, no-max softmax ----------------
// Scores are bounded: |q|,|k| <= sqrt(128) after rmsnorm (weights==1), so
// s <= sqrt(128) ~= 11.31, exp(s) <= 8.2e4, row sum <= 3.4e8 -- safe in fp32
// without max subtraction. Softmax is shift-invariant; result is exact.
#define KTS 132
#define VTS 136
#define PTS 36
#define OFF_K0 0
#define OFF_K1 (32 * KTS)
#define OFF_V0 (2 * 32 * KTS)
#define OFF_V1 (OFF_V0 + 32 * VTS)
#define OFF_P  (OFF_V1 + 32 * VTS)
#define FSMEM  ((OFF_P + 128 * PTS) * 4)   // 87040 bytes

__global__ __launch_bounds__(256) void flashmma(
    const float* __restrict__ Qg, const float* __restrict__ Kg,
    const float* __restrict__ Vg, float* __restrict__ Og)
{
    extern __shared__ float sm[];
    float* KsB[2] = { sm + OFF_K0, sm + OFF_K1 };
    float* VsB[2] = { sm + OFF_V0, sm + OFF_V1 };
    float* Ps = sm + OFF_P;

    const int tid  = threadIdx.x;
    const int wid  = tid >> 5, lane = tid & 31;
    const int gid  = lane >> 2, tig = lane & 3;
    const int h    = blockIdx.y;
    const int q0   = blockIdx.x * 128;
    const int hD   = h * DD;
    const int w16  = wid * 16;
    const float scale = 0.08838834764831845f;   // 1/sqrt(128)

    // ---- Q fragments in registers (scaled, RNE tf32) ----
    uint32_t qf[16][4];
    {
        const float* qr0 = Qg + (size_t)(q0 + w16 + gid) * CD + hD;
        const float* qr1 = qr0 + (size_t)8 * CD;
#pragma unroll
        for (int ks = 0; ks < 16; ks++) {
            const int k = ks * 8;
            qf[ks][0] = __float_as_uint(tf32r(qr0[k + tig    ] * scale));
            qf[ks][1] = __float_as_uint(tf32r(qr1[k + tig    ] * scale));
            qf[ks][2] = __float_as_uint(tf32r(qr0[k + tig + 4] * scale));
            qf[ks][3] = __float_as_uint(tf32r(qr1[k + tig + 4] * scale));
        }
    }

    auto prefetch = [&](int it) {
        const int b = it & 1;
        const int k0 = it * 32;
        const uint32_t kd = (uint32_t)__cvta_generic_to_shared(KsB[b]);
        const uint32_t vd = (uint32_t)__cvta_generic_to_shared(VsB[b]);
#pragma unroll
        for (int i = 0; i < 4; i++) {
            const int idx = i * 256 + tid;
            const int r = idx >> 5, c = (idx & 31) * 4;
            CPASYNC16(kd + (r * KTS + c) * 4, Kg + (size_t)(k0 + r) * CD + hD + c);
            CPASYNC16(vd + (r * VTS + c) * 4, Vg + (size_t)(k0 + r) * CD + hD + c);
        }
        CPCOMMIT();
    };

    const int NIT = KVL / 32;   // 128
    prefetch(0);
    prefetch(1);

    float l0 = 0.f, l1 = 0.f;   // per-thread partial row sums (reduced at end)
    float o[16][4];
#pragma unroll
    for (int ni = 0; ni < 16; ni++)
#pragma unroll
        for (int r = 0; r < 4; r++) o[ni][r] = 0.f;

    for (int it = 0; it < NIT; it++) {
        const int b = it & 1;
        const float* Ks = KsB[b];
        const float* Vs = VsB[b];

        if (it + 1 < NIT) CPWAIT1(); else CPWAIT0();
        __syncthreads();

        // ---- S = Q K^T ----
        float sc[4][4];
#pragma unroll
        for (int ni = 0; ni < 4; ni++)
#pragma unroll
            for (int r = 0; r < 4; r++) sc[ni][r] = 0.f;

#pragma unroll
        for (int ks = 0; ks < 16; ks++) {
            const int k = ks * 8;
#pragma unroll
            for (int ni = 0; ni < 4; ni++) {
                uint32_t bf[2];
                bf[0] = __float_as_uint(Ks[(ni * 8 + gid) * KTS + k + tig    ]);
                bf[1] = __float_as_uint(Ks[(ni * 8 + gid) * KTS + k + tig + 4]);
                mma_tf32(sc[ni], qf[ks], bf);
            }
        }

        // ---- exp (no max shift needed; see bound above) + partial sums ----
#pragma unroll
        for (int ni = 0; ni < 4; ni++) {
            sc[ni][0] = __expf(sc[ni][0]);
            sc[ni][1] = __expf(sc[ni][1]);
            sc[ni][2] = __expf(sc[ni][2]);
            sc[ni][3] = __expf(sc[ni][3]);
            l0 += sc[ni][0] + sc[ni][1];
            l1 += sc[ni][2] + sc[ni][3];
        }

        // ---- store P (warp-private rows) ----
#pragma unroll
        for (int ni = 0; ni < 4; ni++) {
            const int col = ni * 8 + tig * 2;
            *(float2*)&Ps[(w16 + gid    ) * PTS + col] =
                make_float2(tf32r(sc[ni][0]), tf32r(sc[ni][1]));
            *(float2*)&Ps[(w16 + gid + 8) * PTS + col] =
                make_float2(tf32r(sc[ni][2]), tf32r(sc[ni][3]));
        }
        __syncwarp();

        // ---- O += P V ----
#pragma unroll
        for (int ks = 0; ks < 4; ks++) {
            const int k = ks * 8;
            uint32_t paf[4];
            paf[0] = __float_as_uint(Ps[(w16 + gid    ) * PTS + k + tig    ]);
            paf[1] = __float_as_uint(Ps[(w16 + gid + 8) * PTS + k + tig    ]);
            paf[2] = __float_as_uint(Ps[(w16 + gid    ) * PTS + k + tig + 4]);
            paf[3] = __float_as_uint(Ps[(w16 + gid + 8) * PTS + k + tig + 4]);
#pragma unroll
            for (int ni = 0; ni < 16; ni++) {
                const int d = ni * 8;
                uint32_t bf[2];
                bf[0] = __float_as_uint(Vs[(k + tig    ) * VTS + d + gid]);
                bf[1] = __float_as_uint(Vs[(k + tig + 4) * VTS + d + gid]);
                mma_tf32(o[ni], paf, bf);
            }
        }

        __syncthreads();
        if (it + 2 < NIT) prefetch(it + 2);
    }

    // ---- final row-sum reduction over the 4 tig lanes ----
    l0 += __shfl_xor_sync(0xffffffffu, l0, 1);
    l0 += __shfl_xor_sync(0xffffffffu, l0, 2);
    l1 += __shfl_xor_sync(0xffffffffu, l1, 1);
    l1 += __shfl_xor_sync(0xffffffffu, l1, 2);

    const float inv0 = 1.f / l0, inv1 = 1.f / l1;
    const int row0 = q0 + w16 + gid;
#pragma unroll
    for (int ni = 0; ni < 16; ni++) {
        const int col = hD + ni * 8 + tig * 2;
        *(float2*)(Og + (size_t)row0 * CD + col) =
            make_float2(o[ni][0] * inv0, o[ni][1] * inv0);
        *(float2*)(Og + (size_t)(row0 + 8) * CD + col) =
            make_float2(o[ni][2] * inv1, o[ni][3] * inv1);
    }
}

// ---------------- position features ----------------
__global__ __launch_bounds__(256) void pos_hidden(
    float* __restrict__ ph, const float* __restrict__ sw1, const float* __restrict__ sb1)
{
    const int idx = blockIdx.x * 256 + threadIdx.x;
    const int l = idx >> 11;
    const int c = idx & 2047;
    const float coord = -1.f + 2.f * (float)l / 2047.f;
    ph[idx] = sinf(30.f * (coord * sw1[c] + sb1[c]));
}

// ---------------- final: out = x + rmsnorm(O + pos, on_w) ----------------
__global__ __launch_bounds__(256) void fuse_out(
    const float* __restrict__ x, const float* __restrict__ ov,
    const float* __restrict__ pos, const float* __restrict__ w,
    float* __restrict__ out)
{
    __shared__ float t[2048];
    __shared__ float red[8];
    const int l = blockIdx.x;
    const int tid = threadIdx.x;
    float sq = 0.f;
    for (int c = tid; c < 2048; c += 256) {
        const float v = ov[(size_t)l * 2048 + c] + pos[(size_t)l * 2048 + c];
        t[c] = v; sq += v * v;
    }
#pragma unroll
    for (int o = 16; o > 0; o >>= 1) sq += __shfl_xor_sync(0xffffffffu, sq, o);
    if ((tid & 31) == 0) red[tid >> 5] = sq;
    __syncthreads();
    float total = 0.f;
#pragma unroll
    for (int i = 0; i < 8; i++) total += red[i];
    const float rn = rsqrtf(total * (1.f / 2048.f) + 1e-6f);
    for (int c = tid; c < 2048; c += 256)
        out[(size_t)l * 2048 + c] = x[(size_t)l * 2048 + c] + t[c] * rn * w[c];
}

// ---------------- launch ----------------
extern "C" void kernel_launch(void* const* d_in, const int* in_sizes, int n_in,
                              void* d_out, int out_size)
{
    (void)in_sizes; (void)n_in; (void)out_size;
    const float* x   = (const float*)d_in[0];
    const float* h0  = (const float*)d_in[1];
    const float* h1  = (const float*)d_in[2];
    const float* h2  = (const float*)d_in[3];
    const float* Wq  = (const float*)d_in[4];
    const float* Wk  = (const float*)d_in[5];
    const float* Wv  = (const float*)d_in[6];
    const float* Wo  = (const float*)d_in[7];
    const float* qn  = (const float*)d_in[8];
    const float* kn  = (const float*)d_in[9];
    const float* on  = (const float*)d_in[10];
    const float* sw1 = (const float*)d_in[11];
    const float* sb1 = (const float*)d_in[12];
    const float* sw2 = (const float*)d_in[13];
    const float* sb2 = (const float*)d_in[14];
    float* out = (float*)d_out;

    float *Q, *K, *V, *AO, *O, *PH, *PS;
    cudaGetSymbolAddress((void**)&Q,  gQ);
    cudaGetSymbolAddress((void**)&K,  gK);
    cudaGetSymbolAddress((void**)&V,  gV);
    cudaGetSymbolAddress((void**)&AO, gAO);
    cudaGetSymbolAddress((void**)&O,  gO);
    cudaGetSymbolAddress((void**)&PH, gPH);
    cudaGetSymbolAddress((void**)&PS, gPS);

    cudaFuncSetAttribute(proj5_kernel, cudaFuncAttributeMaxDynamicSharedMemorySize, GSMEM);
    cudaFuncSetAttribute(gemm2_kernel, cudaFuncAttributeMaxDynamicSharedMemorySize, GSMEM);
    cudaFuncSetAttribute(flashmma,     cudaFuncAttributeMaxDynamicSharedMemorySize, FSMEM);

    const size_t LC = (size_t)LQ * CD;

    pos_hidden<<<(LQ * CD) / 256, 256>>>(PH, sw1, sb1);

    Proj5 jobs;
    jobs.A[0] = h2; jobs.B[0] = Wq; jobs.C[0] = Q;
    jobs.A[1] = h0; jobs.B[1] = Wk; jobs.C[1] = K;
    jobs.A[2] = h1; jobs.B[2] = Wk; jobs.C[2] = K + LC;
    jobs.A[3] = h0; jobs.B[3] = Wv; jobs.C[3] = V;
    jobs.A[4] = h1; jobs.B[4] = Wv; jobs.C[4] = V + LC;
    proj5_kernel<<<dim3(16, 16, 5), 128, GSMEM>>>(jobs);

    normrope3<<<dim3(LQ, HN, 3), 128>>>(Q, K, qn, kn);

    flashmma<<<dim3(16, 16), 256, FSMEM>>>(Q, K, V, AO);

    gemm2_kernel<<<dim3(16, 16, 2), 128, GSMEM>>>(AO, Wo, O, PH, sw2, sb2, PS);

    fuse_out<<<LQ, 256>>>(x, O, PS, on, out);
}

// round 8
// speedup vs baseline: 3.9804x; 1.0191x over previous
#include <cuda_runtime.h>
#include <cstdint>
#include <math.h>

#define LQ   2048
#define CD   2048
#define HN   16
#define DD   128
#define KVL  4096

// ---------------- scratch (device globals; no allocation) ----------------
__device__ float gQ [LQ  * CD];
__device__ float gK [KVL * CD];
__device__ float gV [KVL * CD];
__device__ float gAO[LQ  * CD];
__device__ float gO [LQ  * CD];
__device__ float gPH[LQ  * CD];
__device__ float gPS[LQ  * CD];

// ---------------- helpers ----------------
__device__ __forceinline__ float tf32r(float x) {
    uint32_t u;
    asm("cvt.rna.tf32.f32 %0, %1;" : "=r"(u) : "f"(x));
    return __uint_as_float(u);
}

__device__ __forceinline__ void mma_tf32(float c[4], const uint32_t a[4], const uint32_t b[2]) {
    asm volatile(
        "mma.sync.aligned.m16n8k8.row.col.f32.tf32.tf32.f32 "
        "{%0,%1,%2,%3}, {%4,%5,%6,%7}, {%8,%9}, {%0,%1,%2,%3};"
        : "+f"(c[0]), "+f"(c[1]), "+f"(c[2]), "+f"(c[3])
        : "r"(a[0]), "r"(a[1]), "r"(a[2]), "r"(a[3]), "r"(b[0]), "r"(b[1]));
}

// ldmatrix x4: one tf32 element per lane per 8x8-b16 matrix.
__device__ __forceinline__ void ldsm4(uint32_t* r, uint32_t addr) {
    asm volatile("ldmatrix.sync.aligned.m8n8.x4.shared.b16 {%0,%1,%2,%3}, [%4];"
        : "=r"(r[0]), "=r"(r[1]), "=r"(r[2]), "=r"(r[3]) : "r"(addr));
}

#define CPASYNC16(dst, src) \
    asm volatile("cp.async.cg.shared.global [%0], [%1], 16;" :: "r"(dst), "l"(src) : "memory")
#define CPCOMMIT()   asm volatile("cp.async.commit_group;" ::: "memory")
#define CPWAIT1()    asm volatile("cp.async.wait_group 1;" ::: "memory")
#define CPWAIT0()    asm volatile("cp.async.wait_group 0;" ::: "memory")

// ---------------- tf32 mma.sync GEMM core ----------------
// CTA tile 128x128, BK=32, 128 threads (4 warps, 2m x 2n, warp tile 64x64).
#define GS_TILE 4608
#define GSMEM   (4 * GS_TILE * 4)          // 73728 bytes

template<bool BT, bool BIAS>
__device__ __forceinline__ void gemm_core(
    const float* __restrict__ A, const float* __restrict__ B,
    const float* __restrict__ bias, float* __restrict__ Cc,
    int M, int N, int K)
{
    extern __shared__ float smemf[];
    const uint32_t sbase = (uint32_t)__cvta_generic_to_shared(smemf);

    const int tid  = threadIdx.x;
    const int wid  = tid >> 5, lane = tid & 31;
    const int gid  = lane >> 2, tig = lane & 3;
    const int wm   = (wid & 1) * 64;
    const int wn   = (wid >> 1) * 64;
    const int bm   = blockIdx.y * 128, bn = blockIdx.x * 128;

    // ldmatrix per-lane offsets
    const int arow = lane & 15,                 acol = (lane >> 4) * 4;       // A-frag x4
    const int brow = (lane & 7) + ((lane >> 4) << 3), bcol = ((lane >> 3) & 1) * 4; // B-frag x4 (2 n-tiles)

    float c[4][8][4];
#pragma unroll
    for (int i = 0; i < 4; i++)
#pragma unroll
        for (int j = 0; j < 8; j++)
#pragma unroll
            for (int r = 0; r < 4; r++) c[i][j][r] = 0.f;

    const int NK = K >> 5;

    auto prefetch = [&](int kc) {
        const int s = kc & 1;
        const int k0 = kc << 5;
        const uint32_t ab = sbase + (s * GS_TILE) * 4;
        const uint32_t bb = sbase + ((2 + s) * GS_TILE) * 4;
#pragma unroll
        for (int i = 0; i < 8; i++) {
            const int idx = i * 128 + tid;
            const int r = idx >> 3, cc = (idx & 7) * 4;
            CPASYNC16(ab + (r * 36 + cc) * 4, A + (size_t)(bm + r) * K + k0 + cc);
        }
        if (BT) {
#pragma unroll
            for (int i = 0; i < 8; i++) {
                const int idx = i * 128 + tid;
                const int r = idx >> 3, cc = (idx & 7) * 4;
                CPASYNC16(bb + (r * 36 + cc) * 4, B + (size_t)(bn + r) * K + k0 + cc);
            }
        } else {
#pragma unroll
            for (int i = 0; i < 8; i++) {
                const int idx = i * 128 + tid;
                const int kr = idx >> 5, cc = (idx & 31) * 4;
                CPASYNC16(bb + (kr * 132 + cc) * 4, B + (size_t)(k0 + kr) * N + bn + cc);
            }
        }
        CPCOMMIT();
    };

    prefetch(0);

    for (int kc = 0; kc < NK; kc++) {
        const bool more = (kc + 1 < NK);
        if (more) prefetch(kc + 1);
        if (more) CPWAIT1(); else CPWAIT0();
        __syncthreads();

        const uint32_t sAu = sbase + ((kc & 1) * GS_TILE) * 4;
        const uint32_t sBu = sbase + ((2 + (kc & 1)) * GS_TILE) * 4;
        const float*   sB  = smemf + (2 + (kc & 1)) * GS_TILE;

#pragma unroll
        for (int ks = 0; ks < 4; ks++) {
            const int k = ks * 8;
            uint32_t af[4][4], bf[8][2];
#pragma unroll
            for (int mi = 0; mi < 4; mi++)
                ldsm4(af[mi], sAu + (((wm + mi * 16 + arow) * 36) + k + acol) * 4);
            if (BT) {
#pragma unroll
                for (int p = 0; p < 4; p++) {
                    uint32_t t[4];
                    ldsm4(t, sBu + (((wn + p * 16 + brow) * 36) + k + bcol) * 4);
                    bf[2 * p][0] = t[0]; bf[2 * p][1] = t[1];
                    bf[2 * p + 1][0] = t[2]; bf[2 * p + 1][1] = t[3];
                }
            } else {
#pragma unroll
                for (int ni = 0; ni < 8; ni++) {
                    const int n = wn + ni * 8 + gid;
                    bf[ni][0] = __float_as_uint(sB[(k + tig    ) * 132 + n]);
                    bf[ni][1] = __float_as_uint(sB[(k + tig + 4) * 132 + n]);
                }
            }
#pragma unroll
            for (int mi = 0; mi < 4; mi++)
#pragma unroll
                for (int ni = 0; ni < 8; ni++)
                    mma_tf32(c[mi][ni], af[mi], bf[ni]);
        }
        __syncthreads();
    }

#pragma unroll
    for (int mi = 0; mi < 4; mi++) {
        const int row0 = bm + wm + mi * 16 + gid;
#pragma unroll
        for (int ni = 0; ni < 8; ni++) {
            const int col = bn + wn + ni * 8 + tig * 2;
            float2 v0 = make_float2(c[mi][ni][0], c[mi][ni][1]);
            float2 v1 = make_float2(c[mi][ni][2], c[mi][ni][3]);
            if (BIAS) {
                const float b0 = bias[col], b1 = bias[col + 1];
                v0.x += b0; v0.y += b1; v1.x += b0; v1.y += b1;
            }
            *(float2*)(Cc + (size_t)row0 * N + col)       = v0;
            *(float2*)(Cc + (size_t)(row0 + 8) * N + col) = v1;
        }
    }
}

// batched projections: z selects (A, B, C), all 2048^3 NT
struct Proj5 {
    const float* A[5];
    const float* B[5];
    float*       C[5];
};
__global__ __launch_bounds__(128) void proj5_kernel(Proj5 jobs)
{
    const int z = blockIdx.z;
    gemm_core<true, false>(jobs.A[z], jobs.B[z], nullptr, jobs.C[z], 2048, 2048, 2048);
}

// combined Wo projection (z=0, NT) and pos projection (z=1, NN + bias)
__global__ __launch_bounds__(128) void gemm2_kernel(
    const float* AO, const float* Wo, float* O,
    const float* PH, const float* sw2, const float* sb2, float* PS)
{
    if (blockIdx.z == 0)
        gemm_core<true,  false>(AO, Wo, nullptr, O, 2048, 2048, 2048);
    else
        gemm_core<false, true >(PH, sw2, sb2, PS, 2048, 2048, 2048);
}

// ---------------- per-(row,head) rmsnorm + depth rope (3 tensors, one launch) ----------------
__global__ __launch_bounds__(128) void normrope3(
    float* __restrict__ Qb, float* __restrict__ Kb,
    const float* __restrict__ qn, const float* __restrict__ kn)
{
    const int z   = blockIdx.z;           // 0: Q(depth2), 1: K0(depth0), 2: K1(depth1)
    float* base   = (z == 0) ? Qb : (Kb + (size_t)(z - 1) * LQ * CD);
    const float* w = (z == 0) ? qn : kn;
    const float depth = (z == 0) ? 2.f : (float)(z - 1);

    const int row = blockIdx.x;
    const int h   = blockIdx.y;
    float* p = base + (size_t)row * CD + h * DD;
    const int d = threadIdx.x;

    float v  = p[d];
    float sq = v * v;
#pragma unroll
    for (int o = 16; o > 0; o >>= 1) sq += __shfl_xor_sync(0xffffffffu, sq, o);
    __shared__ float ws[4];
    if ((d & 31) == 0) ws[d >> 5] = sq;
    __syncthreads();
    const float total = ws[0] + ws[1] + ws[2] + ws[3];
    const float rn = rsqrtf(total * (1.f / 128.f) + 1e-6f);

    __shared__ float sn[128];
    sn[d] = v * rn * w[d];
    __syncthreads();

    float out;
    if (d < 64) {
        float ang = depth * __expf(-(float)d * 0.14391156f);   // ln(10000)/64
        out = sn[d] * cosf(ang) - sn[d + 64] * sinf(ang);
    } else {
        int i = d - 64;
        float ang = depth * __expf(-(float)i * 0.14391156f);
        out = sn[i] * sinf(ang) + sn[d] * cosf(ang);
    }
    p[d] = out;
}

// ---------------- flash attention: tf32 mma.sync + ldmatrix, no-max softmax ----------------
// Scores bounded by sqrt(128) after rmsnorm (weights==1) -> exp safe in fp32
// without max subtraction (softmax shift-invariance; exact).
#define KTS 132
#define VTS 136
#define PTS 36
#define OFF_K0 0
#define OFF_K1 (32 * KTS)
#define OFF_V0 (2 * 32 * KTS)
#define OFF_V1 (OFF_V0 + 32 * VTS)
#define OFF_VT (OFF_V1 + 32 * VTS)          // Vt[d=128][kv=32] stride 36
#define OFF_P  (OFF_VT + 128 * 36)
#define FSMEM  ((OFF_P + 128 * PTS) * 4)    // 105472 bytes

__global__ __launch_bounds__(256) void flashmma(
    const float* __restrict__ Qg, const float* __restrict__ Kg,
    const float* __restrict__ Vg, float* __restrict__ Og)
{
    extern __shared__ float sm[];
    const uint32_t smu = (uint32_t)__cvta_generic_to_shared(sm);
    float* VsB[2] = { sm + OFF_V0, sm + OFF_V1 };
    float* Vt = sm + OFF_VT;
    float* Ps = sm + OFF_P;
    const uint32_t Ktu[2] = { smu + OFF_K0 * 4, smu + OFF_K1 * 4 };
    const uint32_t Vtu = smu + OFF_VT * 4;
    const uint32_t Psu = smu + OFF_P * 4;

    const int tid  = threadIdx.x;
    const int wid  = tid >> 5, lane = tid & 31;
    const int gid  = lane >> 2, tig = lane & 3;
    const int h    = blockIdx.y;
    const int q0   = blockIdx.x * 128;
    const int hD   = h * DD;
    const int w16  = wid * 16;
    const float scale = 0.08838834764831845f;   // 1/sqrt(128)

    // ldmatrix per-lane offsets
    const int arow = lane & 15,                 acol = (lane >> 4) * 4;
    const int brow = (lane & 7) + ((lane >> 4) << 3), bcol = ((lane >> 3) & 1) * 4;

    // ---- Q fragments in registers (scaled, RNE tf32) ----
    uint32_t qf[16][4];
    {
        const float* qr0 = Qg + (size_t)(q0 + w16 + gid) * CD + hD;
        const float* qr1 = qr0 + (size_t)8 * CD;
#pragma unroll
        for (int ks = 0; ks < 16; ks++) {
            const int k = ks * 8;
            qf[ks][0] = __float_as_uint(tf32r(qr0[k + tig    ] * scale));
            qf[ks][1] = __float_as_uint(tf32r(qr1[k + tig    ] * scale));
            qf[ks][2] = __float_as_uint(tf32r(qr0[k + tig + 4] * scale));
            qf[ks][3] = __float_as_uint(tf32r(qr1[k + tig + 4] * scale));
        }
    }

    auto prefetch = [&](int it) {
        const int b = it & 1;
        const int k0 = it * 32;
        const uint32_t kd = Ktu[b];
        const uint32_t vd = smu + (b ? OFF_V1 : OFF_V0) * 4;
#pragma unroll
        for (int i = 0; i < 4; i++) {
            const int idx = i * 256 + tid;
            const int r = idx >> 5, c = (idx & 31) * 4;
            CPASYNC16(kd + (r * KTS + c) * 4, Kg + (size_t)(k0 + r) * CD + hD + c);
            CPASYNC16(vd + (r * VTS + c) * 4, Vg + (size_t)(k0 + r) * CD + hD + c);
        }
        CPCOMMIT();
    };

    const int NIT = KVL / 32;   // 128
    prefetch(0);
    prefetch(1);

    float l0 = 0.f, l1 = 0.f;
    float o[16][4];
#pragma unroll
    for (int ni = 0; ni < 16; ni++)
#pragma unroll
        for (int r = 0; r < 4; r++) o[ni][r] = 0.f;

    for (int it = 0; it < NIT; it++) {
        const int b = it & 1;
        const float* Vs = VsB[b];
        const uint32_t Ku = Ktu[b];

        if (it + 1 < NIT) CPWAIT1(); else CPWAIT0();
        __syncthreads();

        // ---- transpose V tile into Vt[d][kv] (conflict-free lane mapping) ----
        {
            const int dr = w16 + (lane >> 2);
            const int kc = lane & 3;
#pragma unroll
            for (int j = 0; j < 2; j++) {
                const int d = dr + 8 * j;
#pragma unroll
                for (int kp = 0; kp < 8; kp++) {
                    const int kv = kc + 4 * kp;
                    Vt[d * 36 + kv] = Vs[kv * VTS + d];
                }
            }
        }

        // ---- S = Q K^T (K b-frags via ldmatrix.x4, 2 n-tiles each) ----
        float sc[4][4];
#pragma unroll
        for (int ni = 0; ni < 4; ni++)
#pragma unroll
            for (int r = 0; r < 4; r++) sc[ni][r] = 0.f;

#pragma unroll
        for (int ks = 0; ks < 16; ks++) {
            const int k = ks * 8;
            uint32_t t[4];
            ldsm4(t, Ku + (brow * KTS + k + bcol) * 4);          // kv rows 0-15
            mma_tf32(sc[0], qf[ks], t);
            mma_tf32(sc[1], qf[ks], t + 2);
            ldsm4(t, Ku + ((16 + brow) * KTS + k + bcol) * 4);   // kv rows 16-31
            mma_tf32(sc[2], qf[ks], t);
            mma_tf32(sc[3], qf[ks], t + 2);
        }

        // ---- exp (no max shift) + partial sums ----
#pragma unroll
        for (int ni = 0; ni < 4; ni++) {
            sc[ni][0] = __expf(sc[ni][0]);
            sc[ni][1] = __expf(sc[ni][1]);
            sc[ni][2] = __expf(sc[ni][2]);
            sc[ni][3] = __expf(sc[ni][3]);
            l0 += sc[ni][0] + sc[ni][1];
            l1 += sc[ni][2] + sc[ni][3];
        }

        // ---- store P (warp-private rows) ----
#pragma unroll
        for (int ni = 0; ni < 4; ni++) {
            const int col = ni * 8 + tig * 2;
            *(float2*)&Ps[(w16 + gid    ) * PTS + col] =
                make_float2(tf32r(sc[ni][0]), tf32r(sc[ni][1]));
            *(float2*)&Ps[(w16 + gid + 8) * PTS + col] =
                make_float2(tf32r(sc[ni][2]), tf32r(sc[ni][3]));
        }
        __syncthreads();   // P ready (cross-checked) + Vt ready for all warps

        // ---- O += P V  (P a-frags + Vt b-frags via ldmatrix.x4) ----
#pragma unroll
        for (int ks = 0; ks < 4; ks++) {
            const int k = ks * 8;
            uint32_t paf[4];
            ldsm4(paf, Psu + ((w16 + arow) * PTS + k + acol) * 4);
#pragma unroll
            for (int dp = 0; dp < 8; dp++) {
                uint32_t t[4];
                ldsm4(t, Vtu + ((dp * 16 + brow) * 36 + k + bcol) * 4);
                mma_tf32(o[dp * 2],     paf, t);
                mma_tf32(o[dp * 2 + 1], paf, t + 2);
            }
        }

        __syncthreads();
        if (it + 2 < NIT) prefetch(it + 2);
    }

    // ---- final row-sum reduction over the 4 tig lanes ----
    l0 += __shfl_xor_sync(0xffffffffu, l0, 1);
    l0 += __shfl_xor_sync(0xffffffffu, l0, 2);
    l1 += __shfl_xor_sync(0xffffffffu, l1, 1);
    l1 += __shfl_xor_sync(0xffffffffu, l1, 2);

    const float inv0 = 1.f / l0, inv1 = 1.f / l1;
    const int row0 = q0 + w16 + gid;
#pragma unroll
    for (int ni = 0; ni < 16; ni++) {
        const int col = hD + ni * 8 + tig * 2;
        *(float2*)(Og + (size_t)row0 * CD + col) =
            make_float2(o[ni][0] * inv0, o[ni][1] * inv0);
        *(float2*)(Og + (size_t)(row0 + 8) * CD + col) =
            make_float2(o[ni][2] * inv1, o[ni][3] * inv1);
    }
}

// ---------------- position features ----------------
__global__ __launch_bounds__(256) void pos_hidden(
    float* __restrict__ ph, const float* __restrict__ sw1, const float* __restrict__ sb1)
{
    const int idx = blockIdx.x * 256 + threadIdx.x;
    const int l = idx >> 11;
    const int c = idx & 2047;
    const float coord = -1.f + 2.f * (float)l / 2047.f;
    ph[idx] = sinf(30.f * (coord * sw1[c] + sb1[c]));
}

// ---------------- final: out = x + rmsnorm(O + pos, on_w) ----------------
__global__ __launch_bounds__(256) void fuse_out(
    const float* __restrict__ x, const float* __restrict__ ov,
    const float* __restrict__ pos, const float* __restrict__ w,
    float* __restrict__ out)
{
    __shared__ float t[2048];
    __shared__ float red[8];
    const int l = blockIdx.x;
    const int tid = threadIdx.x;
    float sq = 0.f;
    for (int c = tid; c < 2048; c += 256) {
        const float v = ov[(size_t)l * 2048 + c] + pos[(size_t)l * 2048 + c];
        t[c] = v; sq += v * v;
    }
#pragma unroll
    for (int o = 16; o > 0; o >>= 1) sq += __shfl_xor_sync(0xffffffffu, sq, o);
    if ((tid & 31) == 0) red[tid >> 5] = sq;
    __syncthreads();
    float total = 0.f;
#pragma unroll
    for (int i = 0; i < 8; i++) total += red[i];
    const float rn = rsqrtf(total * (1.f / 2048.f) + 1e-6f);
    for (int c = tid; c < 2048; c += 256)
        out[(size_t)l * 2048 + c] = x[(size_t)l * 2048 + c] + t[c] * rn * w[c];
}

// ---------------- launch ----------------
extern "C" void kernel_launch(void* const* d_in, const int* in_sizes, int n_in,
                              void* d_out, int out_size)
{
    (void)in_sizes; (void)n_in; (void)out_size;
    const float* x   = (const float*)d_in[0];
    const float* h0  = (const float*)d_in[1];
    const float* h1  = (const float*)d_in[2];
    const float* h2  = (const float*)d_in[3];
    const float* Wq  = (const float*)d_in[4];
    const float* Wk  = (const float*)d_in[5];
    const float* Wv  = (const float*)d_in[6];
    const float* Wo  = (const float*)d_in[7];
    const float* qn  = (const float*)d_in[8];
    const float* kn  = (const float*)d_in[9];
    const float* on  = (const float*)d_in[10];
    const float* sw1 = (const float*)d_in[11];
    const float* sb1 = (const float*)d_in[12];
    const float* sw2 = (const float*)d_in[13];
    const float* sb2 = (const float*)d_in[14];
    float* out = (float*)d_out;

    float *Q, *K, *V, *AO, *O, *PH, *PS;
    cudaGetSymbolAddress((void**)&Q,  gQ);
    cudaGetSymbolAddress((void**)&K,  gK);
    cudaGetSymbolAddress((void**)&V,  gV);
    cudaGetSymbolAddress((void**)&AO, gAO);
    cudaGetSymbolAddress((void**)&O,  gO);
    cudaGetSymbolAddress((void**)&PH, gPH);
    cudaGetSymbolAddress((void**)&PS, gPS);

    cudaFuncSetAttribute(proj5_kernel, cudaFuncAttributeMaxDynamicSharedMemorySize, GSMEM);
    cudaFuncSetAttribute(gemm2_kernel, cudaFuncAttributeMaxDynamicSharedMemorySize, GSMEM);
    cudaFuncSetAttribute(flashmma,     cudaFuncAttributeMaxDynamicSharedMemorySize, FSMEM);

    const size_t LC = (size_t)LQ * CD;

    pos_hidden<<<(LQ * CD) / 256, 256>>>(PH, sw1, sb1);

    Proj5 jobs;
    jobs.A[0] = h2; jobs.B[0] = Wq; jobs.C[0] = Q;
    jobs.A[1] = h0; jobs.B[1] = Wk; jobs.C[1] = K;
    jobs.A[2] = h1; jobs.B[2] = Wk; jobs.C[2] = K + LC;
    jobs.A[3] = h0; jobs.B[3] = Wv; jobs.C[3] = V;
    jobs.A[4] = h1; jobs.B[4] = Wv; jobs.C[4] = V + LC;
    proj5_kernel<<<dim3(16, 16, 5), 128, GSMEM>>>(jobs);

    normrope3<<<dim3(LQ, HN, 3), 128>>>(Q, K, qn, kn);

    flashmma<<<dim3(16, 16), 256, FSMEM>>>(Q, K, V, AO);

    gemm2_kernel<<<dim3(16, 16, 2), 128, GSMEM>>>(AO, Wo, O, PH, sw2, sb2, PS);

    fuse_out<<<LQ, 256>>>(x, O, PS, on, out);
}

// round 9
// speedup vs baseline: 4.2195x; 1.0601x over previous
#include <cuda_runtime.h>
#include <cstdint>
#include <math.h>

#define LQ   2048
#define CD   2048
#define HN   16
#define DD   128
#define KVL  4096

// ---------------- scratch (device globals; no allocation) ----------------
__device__ float gQ [LQ  * CD];
__device__ float gK [KVL * CD];
__device__ float gV [KVL * CD];
__device__ float gVT[CD  * KVL];   // V transposed: [c=h*128+d][kv]
__device__ float gAO[LQ  * CD];
__device__ float gO [LQ  * CD];
__device__ float gPH[LQ  * CD];
__device__ float gPS[LQ  * CD];

// ---------------- helpers ----------------
__device__ __forceinline__ float tf32r(float x) {
    uint32_t u;
    asm("cvt.rna.tf32.f32 %0, %1;" : "=r"(u) : "f"(x));
    return __uint_as_float(u);
}

__device__ __forceinline__ void mma_tf32(float c[4], const uint32_t a[4], const uint32_t b[2]) {
    asm volatile(
        "mma.sync.aligned.m16n8k8.row.col.f32.tf32.tf32.f32 "
        "{%0,%1,%2,%3}, {%4,%5,%6,%7}, {%8,%9}, {%0,%1,%2,%3};"
        : "+f"(c[0]), "+f"(c[1]), "+f"(c[2]), "+f"(c[3])
        : "r"(a[0]), "r"(a[1]), "r"(a[2]), "r"(a[3]), "r"(b[0]), "r"(b[1]));
}

// ldmatrix x4: one tf32 element per lane per 8x8-b16 matrix.
__device__ __forceinline__ void ldsm4(uint32_t* r, uint32_t addr) {
    asm volatile("ldmatrix.sync.aligned.m8n8.x4.shared.b16 {%0,%1,%2,%3}, [%4];"
        : "=r"(r[0]), "=r"(r[1]), "=r"(r[2]), "=r"(r[3]) : "r"(addr));
}

#define CPASYNC16(dst, src) \
    asm volatile("cp.async.cg.shared.global [%0], [%1], 16;" :: "r"(dst), "l"(src) : "memory")
#define CPCOMMIT()   asm volatile("cp.async.commit_group;" ::: "memory")
#define CPWAIT1()    asm volatile("cp.async.wait_group 1;" ::: "memory")
#define CPWAIT0()    asm volatile("cp.async.wait_group 0;" ::: "memory")

// ---------------- tf32 mma.sync GEMM core ----------------
// CTA tile 128x128, BK=32, 128 threads (4 warps, 2m x 2n, warp tile 64x64).
#define GS_TILE 4608
#define GSMEM   (4 * GS_TILE * 4)          // 73728 bytes

template<bool BT, bool BIAS>
__device__ __forceinline__ void gemm_core(
    const float* __restrict__ A, const float* __restrict__ B,
    const float* __restrict__ bias, float* __restrict__ Cc,
    int M, int N, int K)
{
    extern __shared__ float smemf[];
    const uint32_t sbase = (uint32_t)__cvta_generic_to_shared(smemf);

    const int tid  = threadIdx.x;
    const int wid  = tid >> 5, lane = tid & 31;
    const int gid  = lane >> 2, tig = lane & 3;
    const int wm   = (wid & 1) * 64;
    const int wn   = (wid >> 1) * 64;
    const int bm   = blockIdx.y * 128, bn = blockIdx.x * 128;

    const int arow = lane & 15,                 acol = (lane >> 4) * 4;
    const int brow = (lane & 7) + ((lane >> 4) << 3), bcol = ((lane >> 3) & 1) * 4;

    float c[4][8][4];
#pragma unroll
    for (int i = 0; i < 4; i++)
#pragma unroll
        for (int j = 0; j < 8; j++)
#pragma unroll
            for (int r = 0; r < 4; r++) c[i][j][r] = 0.f;

    const int NK = K >> 5;

    auto prefetch = [&](int kc) {
        const int s = kc & 1;
        const int k0 = kc << 5;
        const uint32_t ab = sbase + (s * GS_TILE) * 4;
        const uint32_t bb = sbase + ((2 + s) * GS_TILE) * 4;
#pragma unroll
        for (int i = 0; i < 8; i++) {
            const int idx = i * 128 + tid;
            const int r = idx >> 3, cc = (idx & 7) * 4;
            CPASYNC16(ab + (r * 36 + cc) * 4, A + (size_t)(bm + r) * K + k0 + cc);
        }
        if (BT) {
#pragma unroll
            for (int i = 0; i < 8; i++) {
                const int idx = i * 128 + tid;
                const int r = idx >> 3, cc = (idx & 7) * 4;
                CPASYNC16(bb + (r * 36 + cc) * 4, B + (size_t)(bn + r) * K + k0 + cc);
            }
        } else {
#pragma unroll
            for (int i = 0; i < 8; i++) {
                const int idx = i * 128 + tid;
                const int kr = idx >> 5, cc = (idx & 31) * 4;
                CPASYNC16(bb + (kr * 132 + cc) * 4, B + (size_t)(k0 + kr) * N + bn + cc);
            }
        }
        CPCOMMIT();
    };

    prefetch(0);

    for (int kc = 0; kc < NK; kc++) {
        const bool more = (kc + 1 < NK);
        if (more) prefetch(kc + 1);
        if (more) CPWAIT1(); else CPWAIT0();
        __syncthreads();

        const uint32_t sAu = sbase + ((kc & 1) * GS_TILE) * 4;
        const uint32_t sBu = sbase + ((2 + (kc & 1)) * GS_TILE) * 4;
        const float*   sB  = smemf + (2 + (kc & 1)) * GS_TILE;

#pragma unroll
        for (int ks = 0; ks < 4; ks++) {
            const int k = ks * 8;
            uint32_t af[4][4], bf[8][2];
#pragma unroll
            for (int mi = 0; mi < 4; mi++)
                ldsm4(af[mi], sAu + (((wm + mi * 16 + arow) * 36) + k + acol) * 4);
            if (BT) {
#pragma unroll
                for (int p = 0; p < 4; p++) {
                    uint32_t t[4];
                    ldsm4(t, sBu + (((wn + p * 16 + brow) * 36) + k + bcol) * 4);
                    bf[2 * p][0] = t[0]; bf[2 * p][1] = t[1];
                    bf[2 * p + 1][0] = t[2]; bf[2 * p + 1][1] = t[3];
                }
            } else {
#pragma unroll
                for (int ni = 0; ni < 8; ni++) {
                    const int n = wn + ni * 8 + gid;
                    bf[ni][0] = __float_as_uint(sB[(k + tig    ) * 132 + n]);
                    bf[ni][1] = __float_as_uint(sB[(k + tig + 4) * 132 + n]);
                }
            }
#pragma unroll
            for (int mi = 0; mi < 4; mi++)
#pragma unroll
                for (int ni = 0; ni < 8; ni++)
                    mma_tf32(c[mi][ni], af[mi], bf[ni]);
        }
        __syncthreads();
    }

#pragma unroll
    for (int mi = 0; mi < 4; mi++) {
        const int row0 = bm + wm + mi * 16 + gid;
#pragma unroll
        for (int ni = 0; ni < 8; ni++) {
            const int col = bn + wn + ni * 8 + tig * 2;
            float2 v0 = make_float2(c[mi][ni][0], c[mi][ni][1]);
            float2 v1 = make_float2(c[mi][ni][2], c[mi][ni][3]);
            if (BIAS) {
                const float b0 = bias[col], b1 = bias[col + 1];
                v0.x += b0; v0.y += b1; v1.x += b0; v1.y += b1;
            }
            *(float2*)(Cc + (size_t)row0 * N + col)       = v0;
            *(float2*)(Cc + (size_t)(row0 + 8) * N + col) = v1;
        }
    }
}

// batched projections: z selects (A, B, C), all 2048^3 NT
struct Proj5 {
    const float* A[5];
    const float* B[5];
    float*       C[5];
};
__global__ __launch_bounds__(128) void proj5_kernel(Proj5 jobs)
{
    const int z = blockIdx.z;
    gemm_core<true, false>(jobs.A[z], jobs.B[z], nullptr, jobs.C[z], 2048, 2048, 2048);
}

// combined Wo projection (z=0, NT) and pos projection (z=1, NN + bias)
__global__ __launch_bounds__(128) void gemm2_kernel(
    const float* AO, const float* Wo, float* O,
    const float* PH, const float* sw2, const float* sb2, float* PS)
{
    if (blockIdx.z == 0)
        gemm_core<true,  false>(AO, Wo, nullptr, O, 2048, 2048, 2048);
    else
        gemm_core<false, true >(PH, sw2, sb2, PS, 2048, 2048, 2048);
}

// ---------------- V transpose: gV[kv][c] -> gVT[c][kv] ----------------
__global__ __launch_bounds__(256) void transposeV(
    const float* __restrict__ V, float* __restrict__ VT)
{
    __shared__ float t[32][33];
    const int kv0 = blockIdx.x * 32, c0 = blockIdx.y * 32;
    const int x = threadIdx.x & 31, y = (threadIdx.x >> 5) * 4;
#pragma unroll
    for (int j = 0; j < 4; j++)
        t[y + j][x] = V[(size_t)(kv0 + y + j) * CD + c0 + x];
    __syncthreads();
#pragma unroll
    for (int j = 0; j < 4; j++)
        VT[(size_t)(c0 + y + j) * KVL + kv0 + x] = t[x][y + j];
}

// ---------------- per-(row,head) rmsnorm + depth rope (3 tensors, one launch) ----------------
__global__ __launch_bounds__(128) void normrope3(
    float* __restrict__ Qb, float* __restrict__ Kb,
    const float* __restrict__ qn, const float* __restrict__ kn)
{
    const int z   = blockIdx.z;           // 0: Q(depth2), 1: K0(depth0), 2: K1(depth1)
    float* base   = (z == 0) ? Qb : (Kb + (size_t)(z - 1) * LQ * CD);
    const float* w = (z == 0) ? qn : kn;
    const float depth = (z == 0) ? 2.f : (float)(z - 1);

    const int row = blockIdx.x;
    const int h   = blockIdx.y;
    float* p = base + (size_t)row * CD + h * DD;
    const int d = threadIdx.x;

    float v  = p[d];
    float sq = v * v;
#pragma unroll
    for (int o = 16; o > 0; o >>= 1) sq += __shfl_xor_sync(0xffffffffu, sq, o);
    __shared__ float ws[4];
    if ((d & 31) == 0) ws[d >> 5] = sq;
    __syncthreads();
    const float total = ws[0] + ws[1] + ws[2] + ws[3];
    const float rn = rsqrtf(total * (1.f / 128.f) + 1e-6f);

    __shared__ float sn[128];
    sn[d] = v * rn * w[d];
    __syncthreads();

    float out;
    if (d < 64) {
        float ang = depth * __expf(-(float)d * 0.14391156f);   // ln(10000)/64
        out = sn[d] * cosf(ang) - sn[d + 64] * sinf(ang);
    } else {
        int i = d - 64;
        float ang = depth * __expf(-(float)i * 0.14391156f);
        out = sn[i] * sinf(ang) + sn[d] * cosf(ang);
    }
    p[d] = out;
}

// ---------------- flash attention: tf32 mma.sync + ldmatrix, no-max softmax ----------------
// Scores bounded by sqrt(128) after rmsnorm (weights==1) -> exp safe in fp32
// without max subtraction (softmax shift-invariance; exact).
// V pre-transposed globally (gVT); per-iter smem transpose eliminated.
#define KTS 132
#define TTS 36
#define PTS 36
#define OFF_K0 0
#define OFF_K1 (32 * KTS)                   // 4224
#define OFF_T0 (2 * 32 * KTS)               // 8448
#define OFF_T1 (OFF_T0 + 128 * TTS)         // 13056
#define OFF_P  (OFF_T1 + 128 * TTS)         // 17664
#define FSMEM  ((OFF_P + 128 * PTS) * 4)    // 89088 bytes

__global__ __launch_bounds__(256) void flashmma(
    const float* __restrict__ Qg, const float* __restrict__ Kg,
    const float* __restrict__ VTg, float* __restrict__ Og)
{
    extern __shared__ float sm[];
    const uint32_t smu = (uint32_t)__cvta_generic_to_shared(sm);
    float* Ps = sm + OFF_P;
    const uint32_t Ktu[2] = { smu + OFF_K0 * 4, smu + OFF_K1 * 4 };
    const uint32_t Ttu[2] = { smu + OFF_T0 * 4, smu + OFF_T1 * 4 };
    const uint32_t Psu = smu + OFF_P * 4;

    const int tid  = threadIdx.x;
    const int wid  = tid >> 5, lane = tid & 31;
    const int gid  = lane >> 2, tig = lane & 3;
    const int h    = blockIdx.y;
    const int q0   = blockIdx.x * 128;
    const int hD   = h * DD;
    const int hC   = h * DD;                 // channel base = h*128
    const int w16  = wid * 16;
    const float scale = 0.08838834764831845f;   // 1/sqrt(128)

    const int arow = lane & 15,                 acol = (lane >> 4) * 4;
    const int brow = (lane & 7) + ((lane >> 4) << 3), bcol = ((lane >> 3) & 1) * 4;

    // ---- Q fragments in registers (scaled, RNE tf32) ----
    uint32_t qf[16][4];
    {
        const float* qr0 = Qg + (size_t)(q0 + w16 + gid) * CD + hD;
        const float* qr1 = qr0 + (size_t)8 * CD;
#pragma unroll
        for (int ks = 0; ks < 16; ks++) {
            const int k = ks * 8;
            qf[ks][0] = __float_as_uint(tf32r(qr0[k + tig    ] * scale));
            qf[ks][1] = __float_as_uint(tf32r(qr1[k + tig    ] * scale));
            qf[ks][2] = __float_as_uint(tf32r(qr0[k + tig + 4] * scale));
            qf[ks][3] = __float_as_uint(tf32r(qr1[k + tig + 4] * scale));
        }
    }

    auto prefetch = [&](int it) {
        const int b = it & 1;
        const int k0 = it * 32;
        const uint32_t kd = Ktu[b];
        const uint32_t td = Ttu[b];
#pragma unroll
        for (int i = 0; i < 4; i++) {
            const int idx = i * 256 + tid;
            const int r = idx >> 5, c = (idx & 31) * 4;   // K: 32 rows x 128 cols
            CPASYNC16(kd + (r * KTS + c) * 4, Kg + (size_t)(k0 + r) * CD + hD + c);
            const int d = idx >> 3, kv = (idx & 7) * 4;   // Vt: 128 rows x 32 cols
            CPASYNC16(td + (d * TTS + kv) * 4, VTg + (size_t)(hC + d) * KVL + k0 + kv);
        }
        CPCOMMIT();
    };

    const int NIT = KVL / 32;   // 128
    prefetch(0);
    prefetch(1);

    float l0 = 0.f, l1 = 0.f;
    float o[16][4];
#pragma unroll
    for (int ni = 0; ni < 16; ni++)
#pragma unroll
        for (int r = 0; r < 4; r++) o[ni][r] = 0.f;

    for (int it = 0; it < NIT; it++) {
        const int b = it & 1;
        const uint32_t Ku = Ktu[b];
        const uint32_t Tu = Ttu[b];

        if (it + 1 < NIT) CPWAIT1(); else CPWAIT0();
        __syncthreads();

        // ---- S = Q K^T (K b-frags via ldmatrix.x4, 2 n-tiles each) ----
        float sc[4][4];
#pragma unroll
        for (int ni = 0; ni < 4; ni++)
#pragma unroll
            for (int r = 0; r < 4; r++) sc[ni][r] = 0.f;

#pragma unroll
        for (int ks = 0; ks < 16; ks++) {
            const int k = ks * 8;
            uint32_t t[4];
            ldsm4(t, Ku + (brow * KTS + k + bcol) * 4);          // kv rows 0-15
            mma_tf32(sc[0], qf[ks], t);
            mma_tf32(sc[1], qf[ks], t + 2);
            ldsm4(t, Ku + ((16 + brow) * KTS + k + bcol) * 4);   // kv rows 16-31
            mma_tf32(sc[2], qf[ks], t);
            mma_tf32(sc[3], qf[ks], t + 2);
        }

        // ---- exp (no max shift) + partial sums ----
#pragma unroll
        for (int ni = 0; ni < 4; ni++) {
            sc[ni][0] = __expf(sc[ni][0]);
            sc[ni][1] = __expf(sc[ni][1]);
            sc[ni][2] = __expf(sc[ni][2]);
            sc[ni][3] = __expf(sc[ni][3]);
            l0 += sc[ni][0] + sc[ni][1];
            l1 += sc[ni][2] + sc[ni][3];
        }

        // ---- store P (warp-private rows; only this warp re-reads them) ----
#pragma unroll
        for (int ni = 0; ni < 4; ni++) {
            const int col = ni * 8 + tig * 2;
            *(float2*)&Ps[(w16 + gid    ) * PTS + col] =
                make_float2(tf32r(sc[ni][0]), tf32r(sc[ni][1]));
            *(float2*)&Ps[(w16 + gid + 8) * PTS + col] =
                make_float2(tf32r(sc[ni][2]), tf32r(sc[ni][3]));
        }
        __syncwarp();

        // ---- O += P V  (P a-frags + Vt b-frags via ldmatrix.x4) ----
#pragma unroll
        for (int ks = 0; ks < 4; ks++) {
            const int k = ks * 8;
            uint32_t paf[4];
            ldsm4(paf, Psu + ((w16 + arow) * PTS + k + acol) * 4);
#pragma unroll
            for (int dp = 0; dp < 8; dp++) {
                uint32_t t[4];
                ldsm4(t, Tu + ((dp * 16 + brow) * TTS + k + bcol) * 4);
                mma_tf32(o[dp * 2],     paf, t);
                mma_tf32(o[dp * 2 + 1], paf, t + 2);
            }
        }

        __syncthreads();
        if (it + 2 < NIT) prefetch(it + 2);
    }

    // ---- final row-sum reduction over the 4 tig lanes ----
    l0 += __shfl_xor_sync(0xffffffffu, l0, 1);
    l0 += __shfl_xor_sync(0xffffffffu, l0, 2);
    l1 += __shfl_xor_sync(0xffffffffu, l1, 1);
    l1 += __shfl_xor_sync(0xffffffffu, l1, 2);

    const float inv0 = 1.f / l0, inv1 = 1.f / l1;
    const int row0 = q0 + w16 + gid;
#pragma unroll
    for (int ni = 0; ni < 16; ni++) {
        const int col = hD + ni * 8 + tig * 2;
        *(float2*)(Og + (size_t)row0 * CD + col) =
            make_float2(o[ni][0] * inv0, o[ni][1] * inv0);
        *(float2*)(Og + (size_t)(row0 + 8) * CD + col) =
            make_float2(o[ni][2] * inv1, o[ni][3] * inv1);
    }
}

// ---------------- position features ----------------
__global__ __launch_bounds__(256) void pos_hidden(
    float* __restrict__ ph, const float* __restrict__ sw1, const float* __restrict__ sb1)
{
    const int idx = blockIdx.x * 256 + threadIdx.x;
    const int l = idx >> 11;
    const int c = idx & 2047;
    const float coord = -1.f + 2.f * (float)l / 2047.f;
    ph[idx] = sinf(30.f * (coord * sw1[c] + sb1[c]));
}

// ---------------- final: out = x + rmsnorm(O + pos, on_w) ----------------
__global__ __launch_bounds__(256) void fuse_out(
    const float* __restrict__ x, const float* __restrict__ ov,
    const float* __restrict__ pos, const float* __restrict__ w,
    float* __restrict__ out)
{
    __shared__ float t[2048];
    __shared__ float red[8];
    const int l = blockIdx.x;
    const int tid = threadIdx.x;
    float sq = 0.f;
    for (int c = tid; c < 2048; c += 256) {
        const float v = ov[(size_t)l * 2048 + c] + pos[(size_t)l * 2048 + c];
        t[c] = v; sq += v * v;
    }
#pragma unroll
    for (int o = 16; o > 0; o >>= 1) sq += __shfl_xor_sync(0xffffffffu, sq, o);
    if ((tid & 31) == 0) red[tid >> 5] = sq;
    __syncthreads();
    float total = 0.f;
#pragma unroll
    for (int i = 0; i < 8; i++) total += red[i];
    const float rn = rsqrtf(total * (1.f / 2048.f) + 1e-6f);
    for (int c = tid; c < 2048; c += 256)
        out[(size_t)l * 2048 + c] = x[(size_t)l * 2048 + c] + t[c] * rn * w[c];
}

// ---------------- launch ----------------
extern "C" void kernel_launch(void* const* d_in, const int* in_sizes, int n_in,
                              void* d_out, int out_size)
{
    (void)in_sizes; (void)n_in; (void)out_size;
    const float* x   = (const float*)d_in[0];
    const float* h0  = (const float*)d_in[1];
    const float* h1  = (const float*)d_in[2];
    const float* h2  = (const float*)d_in[3];
    const float* Wq  = (const float*)d_in[4];
    const float* Wk  = (const float*)d_in[5];
    const float* Wv  = (const float*)d_in[6];
    const float* Wo  = (const float*)d_in[7];
    const float* qn  = (const float*)d_in[8];
    const float* kn  = (const float*)d_in[9];
    const float* on  = (const float*)d_in[10];
    const float* sw1 = (const float*)d_in[11];
    const float* sb1 = (const float*)d_in[12];
    const float* sw2 = (const float*)d_in[13];
    const float* sb2 = (const float*)d_in[14];
    float* out = (float*)d_out;

    float *Q, *K, *V, *VT, *AO, *O, *PH, *PS;
    cudaGetSymbolAddress((void**)&Q,  gQ);
    cudaGetSymbolAddress((void**)&K,  gK);
    cudaGetSymbolAddress((void**)&V,  gV);
    cudaGetSymbolAddress((void**)&VT, gVT);
    cudaGetSymbolAddress((void**)&AO, gAO);
    cudaGetSymbolAddress((void**)&O,  gO);
    cudaGetSymbolAddress((void**)&PH, gPH);
    cudaGetSymbolAddress((void**)&PS, gPS);

    cudaFuncSetAttribute(proj5_kernel, cudaFuncAttributeMaxDynamicSharedMemorySize, GSMEM);
    cudaFuncSetAttribute(gemm2_kernel, cudaFuncAttributeMaxDynamicSharedMemorySize, GSMEM);
    cudaFuncSetAttribute(flashmma,     cudaFuncAttributeMaxDynamicSharedMemorySize, FSMEM);

    const size_t LC = (size_t)LQ * CD;

    pos_hidden<<<(LQ * CD) / 256, 256>>>(PH, sw1, sb1);

    Proj5 jobs;
    jobs.A[0] = h2; jobs.B[0] = Wq; jobs.C[0] = Q;
    jobs.A[1] = h0; jobs.B[1] = Wk; jobs.C[1] = K;
    jobs.A[2] = h1; jobs.B[2] = Wk; jobs.C[2] = K + LC;
    jobs.A[3] = h0; jobs.B[3] = Wv; jobs.C[3] = V;
    jobs.A[4] = h1; jobs.B[4] = Wv; jobs.C[4] = V + LC;
    proj5_kernel<<<dim3(16, 16, 5), 128, GSMEM>>>(jobs);

    transposeV<<<dim3(KVL / 32, CD / 32), 256>>>(V, VT);
    normrope3<<<dim3(LQ, HN, 3), 128>>>(Q, K, qn, kn);

    flashmma<<<dim3(16, 16), 256, FSMEM>>>(Q, K, VT, AO);

    gemm2_kernel<<<dim3(16, 16, 2), 128, GSMEM>>>(AO, Wo, O, PH, sw2, sb2, PS);

    fuse_out<<<LQ, 256>>>(x, O, PS, on, out);
}

// round 10
// speedup vs baseline: 4.2655x; 1.0109x over previous
#include <cuda_runtime.h>
#include <cstdint>
#include <math.h>

#define LQ   2048
#define CD   2048
#define HN   16
#define DD   128
#define KVL  4096

// ---------------- scratch (device globals; no allocation) ----------------
__device__ float gQ [LQ  * CD];
__device__ float gK [KVL * CD];
__device__ float gV [KVL * CD];
__device__ float gVT[CD  * KVL];   // V transposed: [c=h*128+d][kv]
__device__ float gAO[LQ  * CD];
__device__ float gO [LQ  * CD];
__device__ float gPH[LQ  * CD];
__device__ float gPS[LQ  * CD];

// ---------------- helpers ----------------
__device__ __forceinline__ float tf32r(float x) {
    uint32_t u;
    asm("cvt.rna.tf32.f32 %0, %1;" : "=r"(u) : "f"(x));
    return __uint_as_float(u);
}

__device__ __forceinline__ void mma_tf32(float c[4], const uint32_t a[4], const uint32_t b[2]) {
    asm volatile(
        "mma.sync.aligned.m16n8k8.row.col.f32.tf32.tf32.f32 "
        "{%0,%1,%2,%3}, {%4,%5,%6,%7}, {%8,%9}, {%0,%1,%2,%3};"
        : "+f"(c[0]), "+f"(c[1]), "+f"(c[2]), "+f"(c[3])
        : "r"(a[0]), "r"(a[1]), "r"(a[2]), "r"(a[3]), "r"(b[0]), "r"(b[1]));
}

// ldmatrix x4: one tf32 element per lane per 8x8-b16 matrix.
__device__ __forceinline__ void ldsm4(uint32_t* r, uint32_t addr) {
    asm volatile("ldmatrix.sync.aligned.m8n8.x4.shared.b16 {%0,%1,%2,%3}, [%4];"
        : "=r"(r[0]), "=r"(r[1]), "=r"(r[2]), "=r"(r[3]) : "r"(addr));
}

#define CPASYNC16(dst, src) \
    asm volatile("cp.async.cg.shared.global [%0], [%1], 16;" :: "r"(dst), "l"(src) : "memory")
#define CPCOMMIT()   asm volatile("cp.async.commit_group;" ::: "memory")
#define CPWAIT1()    asm volatile("cp.async.wait_group 1;" ::: "memory")
#define CPWAIT0()    asm volatile("cp.async.wait_group 0;" ::: "memory")

// ---------------- tf32 mma.sync GEMM core ----------------
// CTA tile 128x128, BK=32, 128 threads (4 warps, 2m x 2n, warp tile 64x64).
#define GS_TILE 4608
#define GSMEM   (4 * GS_TILE * 4)          // 73728 bytes

template<bool BT, bool BIAS>
__device__ __forceinline__ void gemm_core(
    const float* __restrict__ A, const float* __restrict__ B,
    const float* __restrict__ bias, float* __restrict__ Cc,
    int M, int N, int K)
{
    extern __shared__ float smemf[];
    const uint32_t sbase = (uint32_t)__cvta_generic_to_shared(smemf);

    const int tid  = threadIdx.x;
    const int wid  = tid >> 5, lane = tid & 31;
    const int gid  = lane >> 2, tig = lane & 3;
    const int wm   = (wid & 1) * 64;
    const int wn   = (wid >> 1) * 64;
    const int bm   = blockIdx.y * 128, bn = blockIdx.x * 128;

    const int arow = lane & 15,                 acol = (lane >> 4) * 4;
    const int brow = (lane & 7) + ((lane >> 4) << 3), bcol = ((lane >> 3) & 1) * 4;

    float c[4][8][4];
#pragma unroll
    for (int i = 0; i < 4; i++)
#pragma unroll
        for (int j = 0; j < 8; j++)
#pragma unroll
            for (int r = 0; r < 4; r++) c[i][j][r] = 0.f;

    const int NK = K >> 5;

    auto prefetch = [&](int kc) {
        const int s = kc & 1;
        const int k0 = kc << 5;
        const uint32_t ab = sbase + (s * GS_TILE) * 4;
        const uint32_t bb = sbase + ((2 + s) * GS_TILE) * 4;
#pragma unroll
        for (int i = 0; i < 8; i++) {
            const int idx = i * 128 + tid;
            const int r = idx >> 3, cc = (idx & 7) * 4;
            CPASYNC16(ab + (r * 36 + cc) * 4, A + (size_t)(bm + r) * K + k0 + cc);
        }
        if (BT) {
#pragma unroll
            for (int i = 0; i < 8; i++) {
                const int idx = i * 128 + tid;
                const int r = idx >> 3, cc = (idx & 7) * 4;
                CPASYNC16(bb + (r * 36 + cc) * 4, B + (size_t)(bn + r) * K + k0 + cc);
            }
        } else {
#pragma unroll
            for (int i = 0; i < 8; i++) {
                const int idx = i * 128 + tid;
                const int kr = idx >> 5, cc = (idx & 31) * 4;
                CPASYNC16(bb + (kr * 132 + cc) * 4, B + (size_t)(k0 + kr) * N + bn + cc);
            }
        }
        CPCOMMIT();
    };

    prefetch(0);

    for (int kc = 0; kc < NK; kc++) {
        const bool more = (kc + 1 < NK);
        if (more) prefetch(kc + 1);
        if (more) CPWAIT1(); else CPWAIT0();
        __syncthreads();

        const uint32_t sAu = sbase + ((kc & 1) * GS_TILE) * 4;
        const uint32_t sBu = sbase + ((2 + (kc & 1)) * GS_TILE) * 4;
        const float*   sB  = smemf + (2 + (kc & 1)) * GS_TILE;

#pragma unroll
        for (int ks = 0; ks < 4; ks++) {
            const int k = ks * 8;
            uint32_t af[4][4], bf[8][2];
#pragma unroll
            for (int mi = 0; mi < 4; mi++)
                ldsm4(af[mi], sAu + (((wm + mi * 16 + arow) * 36) + k + acol) * 4);
            if (BT) {
#pragma unroll
                for (int p = 0; p < 4; p++) {
                    uint32_t t[4];
                    ldsm4(t, sBu + (((wn + p * 16 + brow) * 36) + k + bcol) * 4);
                    bf[2 * p][0] = t[0]; bf[2 * p][1] = t[1];
                    bf[2 * p + 1][0] = t[2]; bf[2 * p + 1][1] = t[3];
                }
            } else {
#pragma unroll
                for (int ni = 0; ni < 8; ni++) {
                    const int n = wn + ni * 8 + gid;
                    bf[ni][0] = __float_as_uint(sB[(k + tig    ) * 132 + n]);
                    bf[ni][1] = __float_as_uint(sB[(k + tig + 4) * 132 + n]);
                }
            }
#pragma unroll
            for (int mi = 0; mi < 4; mi++)
#pragma unroll
                for (int ni = 0; ni < 8; ni++)
                    mma_tf32(c[mi][ni], af[mi], bf[ni]);
        }
        __syncthreads();
    }

#pragma unroll
    for (int mi = 0; mi < 4; mi++) {
        const int row0 = bm + wm + mi * 16 + gid;
#pragma unroll
        for (int ni = 0; ni < 8; ni++) {
            const int col = bn + wn + ni * 8 + tig * 2;
            float2 v0 = make_float2(c[mi][ni][0], c[mi][ni][1]);
            float2 v1 = make_float2(c[mi][ni][2], c[mi][ni][3]);
            if (BIAS) {
                const float b0 = bias[col], b1 = bias[col + 1];
                v0.x += b0; v0.y += b1; v1.x += b0; v1.y += b1;
            }
            *(float2*)(Cc + (size_t)row0 * N + col)       = v0;
            *(float2*)(Cc + (size_t)(row0 + 8) * N + col) = v1;
        }
    }
}

// batched projections: z selects (A, B, C), all 2048^3 NT
struct Proj5 {
    const float* A[5];
    const float* B[5];
    float*       C[5];
};
__global__ __launch_bounds__(128) void proj5_kernel(Proj5 jobs)
{
    const int z = blockIdx.z;
    gemm_core<true, false>(jobs.A[z], jobs.B[z], nullptr, jobs.C[z], 2048, 2048, 2048);
}

// combined Wo projection (z=0, NT) and pos projection (z=1, NN + bias)
__global__ __launch_bounds__(128) void gemm2_kernel(
    const float* AO, const float* Wo, float* O,
    const float* PH, const float* sw2, const float* sb2, float* PS)
{
    if (blockIdx.z == 0)
        gemm_core<true,  false>(AO, Wo, nullptr, O, 2048, 2048, 2048);
    else
        gemm_core<false, true >(PH, sw2, sb2, PS, 2048, 2048, 2048);
}

// ---------------- V transpose: gV[kv][c] -> gVT[c][kv] ----------------
__global__ __launch_bounds__(256) void transposeV(
    const float* __restrict__ V, float* __restrict__ VT)
{
    __shared__ float t[32][33];
    const int kv0 = blockIdx.x * 32, c0 = blockIdx.y * 32;
    const int x = threadIdx.x & 31, y = (threadIdx.x >> 5) * 4;
#pragma unroll
    for (int j = 0; j < 4; j++)
        t[y + j][x] = V[(size_t)(kv0 + y + j) * CD + c0 + x];
    __syncthreads();
#pragma unroll
    for (int j = 0; j < 4; j++)
        VT[(size_t)(c0 + y + j) * KVL + kv0 + x] = t[x][y + j];
}

// ---------------- rmsnorm + depth rope: one warp per (row,head) ----------------
// 3 tensors (Q depth2, K0 depth0, K1 depth1). float4 per lane, shfl reduce,
// rope pairing via shfl_xor(16).
__global__ __launch_bounds__(256) void normrope3(
    float* __restrict__ Qb, float* __restrict__ Kb,
    const float* __restrict__ qn, const float* __restrict__ kn)
{
    const int wid  = threadIdx.x >> 5, lane = threadIdx.x & 31;
    const int pair = blockIdx.x * 8 + wid;      // 0 .. LQ*HN*3-1
    const int z    = pair / (LQ * HN);
    const int rem  = pair - z * (LQ * HN);
    const int row  = rem >> 4, h = rem & 15;

    float* base    = (z == 0) ? Qb : (Kb + (size_t)(z - 1) * LQ * CD);
    const float* w = (z == 0) ? qn : kn;
    const float depth = (z == 0) ? 2.f : (float)(z - 1);

    float* p = base + (size_t)row * CD + h * DD + lane * 4;
    float4 v = *(float4*)p;
    float sq = v.x * v.x + v.y * v.y + v.z * v.z + v.w * v.w;
#pragma unroll
    for (int o = 16; o > 0; o >>= 1) sq += __shfl_xor_sync(0xffffffffu, sq, o);
    const float rn = rsqrtf(sq * (1.f / 128.f) + 1e-6f);

    const float4 wv = *(const float4*)(w + lane * 4);
    float4 s = make_float4(v.x * rn * wv.x, v.y * rn * wv.y,
                           v.z * rn * wv.z, v.w * rn * wv.w);
    float4 q;
    q.x = __shfl_xor_sync(0xffffffffu, s.x, 16);
    q.y = __shfl_xor_sync(0xffffffffu, s.y, 16);
    q.z = __shfl_xor_sync(0xffffffffu, s.z, 16);
    q.w = __shfl_xor_sync(0xffffffffu, s.w, 16);

    const int dd0 = (lane & 15) * 4;
    float4 out;
    float cs[4], sn_[4];
#pragma unroll
    for (int j = 0; j < 4; j++) {
        const float ang = depth * __expf(-(float)(dd0 + j) * 0.14391156f); // ln(1e4)/64
        cs[j] = cosf(ang); sn_[j] = sinf(ang);
    }
    if (lane < 16) {        // own = x1, partner = x2 : x1*cos - x2*sin
        out.x = s.x * cs[0] - q.x * sn_[0];
        out.y = s.y * cs[1] - q.y * sn_[1];
        out.z = s.z * cs[2] - q.z * sn_[2];
        out.w = s.w * cs[3] - q.w * sn_[3];
    } else {                // own = x2, partner = x1 : x1*sin + x2*cos
        out.x = q.x * sn_[0] + s.x * cs[0];
        out.y = q.y * sn_[1] + s.y * cs[1];
        out.z = q.z * sn_[2] + s.z * cs[2];
        out.w = q.w * sn_[3] + s.w * cs[3];
    }
    *(float4*)p = out;
}

// ---------------- flash attention: tf32 mma.sync + ldmatrix, KV tile 64 ----------------
// No-max softmax (scores bounded by sqrt(128) after unit-weight rmsnorm; exact
// by shift invariance). V pre-transposed globally.
#define KTS 132
#define TTS 68
#define PTS 68
#define OFF_K0 0
#define OFF_K1 (64 * KTS)                   // 8448
#define OFF_T0 (2 * 64 * KTS)               // 16896
#define OFF_T1 (OFF_T0 + 128 * TTS)         // 25600
#define OFF_P  (OFF_T1 + 128 * TTS)         // 34304
#define FSMEM  ((OFF_P + 128 * PTS) * 4)    // 172032 bytes

__global__ __launch_bounds__(256) void flashmma(
    const float* __restrict__ Qg, const float* __restrict__ Kg,
    const float* __restrict__ VTg, float* __restrict__ Og)
{
    extern __shared__ float sm[];
    const uint32_t smu = (uint32_t)__cvta_generic_to_shared(sm);
    float* Ps = sm + OFF_P;
    const uint32_t Ktu[2] = { smu + OFF_K0 * 4, smu + OFF_K1 * 4 };
    const uint32_t Ttu[2] = { smu + OFF_T0 * 4, smu + OFF_T1 * 4 };
    const uint32_t Psu = smu + OFF_P * 4;

    const int tid  = threadIdx.x;
    const int wid  = tid >> 5, lane = tid & 31;
    const int gid  = lane >> 2, tig = lane & 3;
    const int h    = blockIdx.y;
    const int q0   = blockIdx.x * 128;
    const int hD   = h * DD;
    const int w16  = wid * 16;
    const float scale = 0.08838834764831845f;   // 1/sqrt(128)

    const int arow = lane & 15,                 acol = (lane >> 4) * 4;
    const int brow = (lane & 7) + ((lane >> 4) << 3), bcol = ((lane >> 3) & 1) * 4;

    // ---- Q fragments in registers (scaled, RNE tf32) ----
    uint32_t qf[16][4];
    {
        const float* qr0 = Qg + (size_t)(q0 + w16 + gid) * CD + hD;
        const float* qr1 = qr0 + (size_t)8 * CD;
#pragma unroll
        for (int ks = 0; ks < 16; ks++) {
            const int k = ks * 8;
            qf[ks][0] = __float_as_uint(tf32r(qr0[k + tig    ] * scale));
            qf[ks][1] = __float_as_uint(tf32r(qr1[k + tig    ] * scale));
            qf[ks][2] = __float_as_uint(tf32r(qr0[k + tig + 4] * scale));
            qf[ks][3] = __float_as_uint(tf32r(qr1[k + tig + 4] * scale));
        }
    }

    auto prefetch = [&](int it) {
        const int b = it & 1;
        const int k0 = it * 64;
        const uint32_t kd = Ktu[b];
        const uint32_t td = Ttu[b];
#pragma unroll
        for (int i = 0; i < 8; i++) {
            const int idx = i * 256 + tid;
            const int r = idx >> 5, c = (idx & 31) * 4;   // K: 64 rows x 128 cols
            CPASYNC16(kd + (r * KTS + c) * 4, Kg + (size_t)(k0 + r) * CD + hD + c);
            const int d = idx >> 4, kv = (idx & 15) * 4;  // Vt: 128 rows x 64 cols
            CPASYNC16(td + (d * TTS + kv) * 4, VTg + (size_t)(hD + d) * KVL + k0 + kv);
        }
        CPCOMMIT();
    };

    const int NIT = KVL / 64;   // 64
    prefetch(0);
    prefetch(1);

    float l0 = 0.f, l1 = 0.f;
    float o[16][4];
#pragma unroll
    for (int ni = 0; ni < 16; ni++)
#pragma unroll
        for (int r = 0; r < 4; r++) o[ni][r] = 0.f;

    for (int it = 0; it < NIT; it++) {
        const int b = it & 1;
        const uint32_t Ku = Ktu[b];
        const uint32_t Tu = Ttu[b];

        if (it + 1 < NIT) CPWAIT1(); else CPWAIT0();
        __syncthreads();

        // ---- S = Q K^T : 64 kv cols = 8 independent accumulator chains ----
        float sc[8][4];
#pragma unroll
        for (int ni = 0; ni < 8; ni++)
#pragma unroll
            for (int r = 0; r < 4; r++) sc[ni][r] = 0.f;

#pragma unroll
        for (int ks = 0; ks < 16; ks++) {
            const int k = ks * 8;
#pragma unroll
            for (int g = 0; g < 4; g++) {               // kv row-groups of 16
                uint32_t t[4];
                ldsm4(t, Ku + ((g * 16 + brow) * KTS + k + bcol) * 4);
                mma_tf32(sc[2 * g],     qf[ks], t);
                mma_tf32(sc[2 * g + 1], qf[ks], t + 2);
            }
        }

        // ---- exp (no max shift) + partial sums ----
#pragma unroll
        for (int ni = 0; ni < 8; ni++) {
            sc[ni][0] = __expf(sc[ni][0]);
            sc[ni][1] = __expf(sc[ni][1]);
            sc[ni][2] = __expf(sc[ni][2]);
            sc[ni][3] = __expf(sc[ni][3]);
            l0 += sc[ni][0] + sc[ni][1];
            l1 += sc[ni][2] + sc[ni][3];
        }

        // ---- store P (warp-private rows; only this warp re-reads them) ----
#pragma unroll
        for (int ni = 0; ni < 8; ni++) {
            const int col = ni * 8 + tig * 2;
            *(float2*)&Ps[(w16 + gid    ) * PTS + col] =
                make_float2(tf32r(sc[ni][0]), tf32r(sc[ni][1]));
            *(float2*)&Ps[(w16 + gid + 8) * PTS + col] =
                make_float2(tf32r(sc[ni][2]), tf32r(sc[ni][3]));
        }
        __syncwarp();

        // ---- O += P V  (P a-frags + Vt b-frags via ldmatrix.x4) ----
#pragma unroll
        for (int ks = 0; ks < 8; ks++) {
            const int k = ks * 8;
            uint32_t paf[4];
            ldsm4(paf, Psu + ((w16 + arow) * PTS + k + acol) * 4);
#pragma unroll
            for (int dp = 0; dp < 8; dp++) {
                uint32_t t[4];
                ldsm4(t, Tu + ((dp * 16 + brow) * TTS + k + bcol) * 4);
                mma_tf32(o[dp * 2],     paf, t);
                mma_tf32(o[dp * 2 + 1], paf, t + 2);
            }
        }

        __syncthreads();
        if (it + 2 < NIT) prefetch(it + 2);
    }

    // ---- final row-sum reduction over the 4 tig lanes ----
    l0 += __shfl_xor_sync(0xffffffffu, l0, 1);
    l0 += __shfl_xor_sync(0xffffffffu, l0, 2);
    l1 += __shfl_xor_sync(0xffffffffu, l1, 1);
    l1 += __shfl_xor_sync(0xffffffffu, l1, 2);

    const float inv0 = 1.f / l0, inv1 = 1.f / l1;
    const int row0 = q0 + w16 + gid;
#pragma unroll
    for (int ni = 0; ni < 16; ni++) {
        const int col = hD + ni * 8 + tig * 2;
        *(float2*)(Og + (size_t)row0 * CD + col) =
            make_float2(o[ni][0] * inv0, o[ni][1] * inv0);
        *(float2*)(Og + (size_t)(row0 + 8) * CD + col) =
            make_float2(o[ni][2] * inv1, o[ni][3] * inv1);
    }
}

// ---------------- position features ----------------
__global__ __launch_bounds__(256) void pos_hidden(
    float* __restrict__ ph, const float* __restrict__ sw1, const float* __restrict__ sb1)
{
    const int idx = blockIdx.x * 256 + threadIdx.x;
    const int l = idx >> 11;
    const int c = idx & 2047;
    const float coord = -1.f + 2.f * (float)l / 2047.f;
    ph[idx] = sinf(30.f * (coord * sw1[c] + sb1[c]));
}

// ---------------- final: out = x + rmsnorm(O + pos, on_w) ----------------
__global__ __launch_bounds__(256) void fuse_out(
    const float* __restrict__ x, const float* __restrict__ ov,
    const float* __restrict__ pos, const float* __restrict__ w,
    float* __restrict__ out)
{
    __shared__ float t[2048];
    __shared__ float red[8];
    const int l = blockIdx.x;
    const int tid = threadIdx.x;
    float sq = 0.f;
    for (int c = tid; c < 2048; c += 256) {
        const float v = ov[(size_t)l * 2048 + c] + pos[(size_t)l * 2048 + c];
        t[c] = v; sq += v * v;
    }
#pragma unroll
    for (int o = 16; o > 0; o >>= 1) sq += __shfl_xor_sync(0xffffffffu, sq, o);
    if ((tid & 31) == 0) red[tid >> 5] = sq;
    __syncthreads();
    float total = 0.f;
#pragma unroll
    for (int i = 0; i < 8; i++) total += red[i];
    const float rn = rsqrtf(total * (1.f / 2048.f) + 1e-6f);
    for (int c = tid; c < 2048; c += 256)
        out[(size_t)l * 2048 + c] = x[(size_t)l * 2048 + c] + t[c] * rn * w[c];
}

// ---------------- launch ----------------
extern "C" void kernel_launch(void* const* d_in, const int* in_sizes, int n_in,
                              void* d_out, int out_size)
{
    (void)in_sizes; (void)n_in; (void)out_size;
    const float* x   = (const float*)d_in[0];
    const float* h0  = (const float*)d_in[1];
    const float* h1  = (const float*)d_in[2];
    const float* h2  = (const float*)d_in[3];
    const float* Wq  = (const float*)d_in[4];
    const float* Wk  = (const float*)d_in[5];
    const float* Wv  = (const float*)d_in[6];
    const float* Wo  = (const float*)d_in[7];
    const float* qn  = (const float*)d_in[8];
    const float* kn  = (const float*)d_in[9];
    const float* on  = (const float*)d_in[10];
    const float* sw1 = (const float*)d_in[11];
    const float* sb1 = (const float*)d_in[12];
    const float* sw2 = (const float*)d_in[13];
    const float* sb2 = (const float*)d_in[14];
    float* out = (float*)d_out;

    float *Q, *K, *V, *VT, *AO, *O, *PH, *PS;
    cudaGetSymbolAddress((void**)&Q,  gQ);
    cudaGetSymbolAddress((void**)&K,  gK);
    cudaGetSymbolAddress((void**)&V,  gV);
    cudaGetSymbolAddress((void**)&VT, gVT);
    cudaGetSymbolAddress((void**)&AO, gAO);
    cudaGetSymbolAddress((void**)&O,  gO);
    cudaGetSymbolAddress((void**)&PH, gPH);
    cudaGetSymbolAddress((void**)&PS, gPS);

    cudaFuncSetAttribute(proj5_kernel, cudaFuncAttributeMaxDynamicSharedMemorySize, GSMEM);
    cudaFuncSetAttribute(gemm2_kernel, cudaFuncAttributeMaxDynamicSharedMemorySize, GSMEM);
    cudaFuncSetAttribute(flashmma,     cudaFuncAttributeMaxDynamicSharedMemorySize, FSMEM);

    const size_t LC = (size_t)LQ * CD;

    pos_hidden<<<(LQ * CD) / 256, 256>>>(PH, sw1, sb1);

    Proj5 jobs;
    jobs.A[0] = h2; jobs.B[0] = Wq; jobs.C[0] = Q;
    jobs.A[1] = h0; jobs.B[1] = Wk; jobs.C[1] = K;
    jobs.A[2] = h1; jobs.B[2] = Wk; jobs.C[2] = K + LC;
    jobs.A[3] = h0; jobs.B[3] = Wv; jobs.C[3] = V;
    jobs.A[4] = h1; jobs.B[4] = Wv; jobs.C[4] = V + LC;
    proj5_kernel<<<dim3(16, 16, 5), 128, GSMEM>>>(jobs);

    transposeV<<<dim3(KVL / 32, CD / 32), 256>>>(V, VT);
    normrope3<<<(LQ * HN * 3) / 8, 256>>>(Q, K, qn, kn);

    flashmma<<<dim3(16, 16), 256, FSMEM>>>(Q, K, VT, AO);

    gemm2_kernel<<<dim3(16, 16, 2), 128, GSMEM>>>(AO, Wo, O, PH, sw2, sb2, PS);

    fuse_out<<<LQ, 256>>>(x, O, PS, on, out);
}

// round 11
// speedup vs baseline: 5.1682x; 1.2116x over previous
#include <cuda_runtime.h>
#include <cuda_bf16.h>
#include <cstdint>
#include <math.h>

#define LQ   2048
#define CD   2048
#define HN   16
#define DD   128
#define KVL  4096

// ---------------- scratch (device globals; no allocation) ----------------
__device__ float gQ [LQ  * CD];
__device__ float gK [KVL * CD];
__device__ float gV [KVL * CD];
__device__ __nv_bfloat16 gKh [KVL * CD];   // normed+roped K in bf16
__device__ __nv_bfloat16 gVTh[CD  * KVL];  // V transposed, bf16: [c][kv]
__device__ float gAO[LQ  * CD];
__device__ float gO [LQ  * CD];
__device__ float gPH[LQ  * CD];
__device__ float gPS[LQ  * CD];

// ---------------- helpers ----------------
__device__ __forceinline__ float tf32r(float x) {
    uint32_t u;
    asm("cvt.rna.tf32.f32 %0, %1;" : "=r"(u) : "f"(x));
    return __uint_as_float(u);
}
__device__ __forceinline__ uint32_t packbf(float lo, float hi) {
    __nv_bfloat162 h = __floats2bfloat162_rn(lo, hi);
    return *(uint32_t*)&h;
}

__device__ __forceinline__ void mma_tf32(float c[4], const uint32_t a[4], const uint32_t b[2]) {
    asm volatile(
        "mma.sync.aligned.m16n8k8.row.col.f32.tf32.tf32.f32 "
        "{%0,%1,%2,%3}, {%4,%5,%6,%7}, {%8,%9}, {%0,%1,%2,%3};"
        : "+f"(c[0]), "+f"(c[1]), "+f"(c[2]), "+f"(c[3])
        : "r"(a[0]), "r"(a[1]), "r"(a[2]), "r"(a[3]), "r"(b[0]), "r"(b[1]));
}
__device__ __forceinline__ void mma_bf16(float c[4], const uint32_t a[4], const uint32_t b[2]) {
    asm volatile(
        "mma.sync.aligned.m16n8k16.row.col.f32.bf16.bf16.f32 "
        "{%0,%1,%2,%3}, {%4,%5,%6,%7}, {%8,%9}, {%0,%1,%2,%3};"
        : "+f"(c[0]), "+f"(c[1]), "+f"(c[2]), "+f"(c[3])
        : "r"(a[0]), "r"(a[1]), "r"(a[2]), "r"(a[3]), "r"(b[0]), "r"(b[1]));
}

// ldmatrix x4 (b16 native)
__device__ __forceinline__ void ldsm4(uint32_t* r, uint32_t addr) {
    asm volatile("ldmatrix.sync.aligned.m8n8.x4.shared.b16 {%0,%1,%2,%3}, [%4];"
        : "=r"(r[0]), "=r"(r[1]), "=r"(r[2]), "=r"(r[3]) : "r"(addr));
}

#define CPASYNC16(dst, src) \
    asm volatile("cp.async.cg.shared.global [%0], [%1], 16;" :: "r"(dst), "l"(src) : "memory")
#define CPCOMMIT()   asm volatile("cp.async.commit_group;" ::: "memory")
#define CPWAIT1()    asm volatile("cp.async.wait_group 1;" ::: "memory")
#define CPWAIT0()    asm volatile("cp.async.wait_group 0;" ::: "memory")

// ---------------- tf32 mma.sync GEMM core (unchanged) ----------------
#define GS_TILE 4608
#define GSMEM   (4 * GS_TILE * 4)

template<bool BT, bool BIAS>
__device__ __forceinline__ void gemm_core(
    const float* __restrict__ A, const float* __restrict__ B,
    const float* __restrict__ bias, float* __restrict__ Cc,
    int M, int N, int K)
{
    extern __shared__ float smemf[];
    const uint32_t sbase = (uint32_t)__cvta_generic_to_shared(smemf);

    const int tid  = threadIdx.x;
    const int wid  = tid >> 5, lane = tid & 31;
    const int gid  = lane >> 2, tig = lane & 3;
    const int wm   = (wid & 1) * 64;
    const int wn   = (wid >> 1) * 64;
    const int bm   = blockIdx.y * 128, bn = blockIdx.x * 128;

    const int arow = lane & 15,                 acol = (lane >> 4) * 4;
    const int brow = (lane & 7) + ((lane >> 4) << 3), bcol = ((lane >> 3) & 1) * 4;

    float c[4][8][4];
#pragma unroll
    for (int i = 0; i < 4; i++)
#pragma unroll
        for (int j = 0; j < 8; j++)
#pragma unroll
            for (int r = 0; r < 4; r++) c[i][j][r] = 0.f;

    const int NK = K >> 5;

    auto prefetch = [&](int kc) {
        const int s = kc & 1;
        const int k0 = kc << 5;
        const uint32_t ab = sbase + (s * GS_TILE) * 4;
        const uint32_t bb = sbase + ((2 + s) * GS_TILE) * 4;
#pragma unroll
        for (int i = 0; i < 8; i++) {
            const int idx = i * 128 + tid;
            const int r = idx >> 3, cc = (idx & 7) * 4;
            CPASYNC16(ab + (r * 36 + cc) * 4, A + (size_t)(bm + r) * K + k0 + cc);
        }
        if (BT) {
#pragma unroll
            for (int i = 0; i < 8; i++) {
                const int idx = i * 128 + tid;
                const int r = idx >> 3, cc = (idx & 7) * 4;
                CPASYNC16(bb + (r * 36 + cc) * 4, B + (size_t)(bn + r) * K + k0 + cc);
            }
        } else {
#pragma unroll
            for (int i = 0; i < 8; i++) {
                const int idx = i * 128 + tid;
                const int kr = idx >> 5, cc = (idx & 31) * 4;
                CPASYNC16(bb + (kr * 132 + cc) * 4, B + (size_t)(k0 + kr) * N + bn + cc);
            }
        }
        CPCOMMIT();
    };

    prefetch(0);

    for (int kc = 0; kc < NK; kc++) {
        const bool more = (kc + 1 < NK);
        if (more) prefetch(kc + 1);
        if (more) CPWAIT1(); else CPWAIT0();
        __syncthreads();

        const uint32_t sAu = sbase + ((kc & 1) * GS_TILE) * 4;
        const uint32_t sBu = sbase + ((2 + (kc & 1)) * GS_TILE) * 4;
        const float*   sB  = smemf + (2 + (kc & 1)) * GS_TILE;

#pragma unroll
        for (int ks = 0; ks < 4; ks++) {
            const int k = ks * 8;
            uint32_t af[4][4], bf[8][2];
#pragma unroll
            for (int mi = 0; mi < 4; mi++)
                ldsm4(af[mi], sAu + (((wm + mi * 16 + arow) * 36) + k + acol) * 4);
            if (BT) {
#pragma unroll
                for (int p = 0; p < 4; p++) {
                    uint32_t t[4];
                    ldsm4(t, sBu + (((wn + p * 16 + brow) * 36) + k + bcol) * 4);
                    bf[2 * p][0] = t[0]; bf[2 * p][1] = t[1];
                    bf[2 * p + 1][0] = t[2]; bf[2 * p + 1][1] = t[3];
                }
            } else {
#pragma unroll
                for (int ni = 0; ni < 8; ni++) {
                    const int n = wn + ni * 8 + gid;
                    bf[ni][0] = __float_as_uint(sB[(k + tig    ) * 132 + n]);
                    bf[ni][1] = __float_as_uint(sB[(k + tig + 4) * 132 + n]);
                }
            }
#pragma unroll
            for (int mi = 0; mi < 4; mi++)
#pragma unroll
                for (int ni = 0; ni < 8; ni++)
                    mma_tf32(c[mi][ni], af[mi], bf[ni]);
        }
        __syncthreads();
    }

#pragma unroll
    for (int mi = 0; mi < 4; mi++) {
        const int row0 = bm + wm + mi * 16 + gid;
#pragma unroll
        for (int ni = 0; ni < 8; ni++) {
            const int col = bn + wn + ni * 8 + tig * 2;
            float2 v0 = make_float2(c[mi][ni][0], c[mi][ni][1]);
            float2 v1 = make_float2(c[mi][ni][2], c[mi][ni][3]);
            if (BIAS) {
                const float b0 = bias[col], b1 = bias[col + 1];
                v0.x += b0; v0.y += b1; v1.x += b0; v1.y += b1;
            }
            *(float2*)(Cc + (size_t)row0 * N + col)       = v0;
            *(float2*)(Cc + (size_t)(row0 + 8) * N + col) = v1;
        }
    }
}

struct Proj5 {
    const float* A[5];
    const float* B[5];
    float*       C[5];
};
__global__ __launch_bounds__(128) void proj5_kernel(Proj5 jobs)
{
    const int z = blockIdx.z;
    gemm_core<true, false>(jobs.A[z], jobs.B[z], nullptr, jobs.C[z], 2048, 2048, 2048);
}

__global__ __launch_bounds__(128) void gemm2_kernel(
    const float* AO, const float* Wo, float* O,
    const float* PH, const float* sw2, const float* sb2, float* PS)
{
    if (blockIdx.z == 0)
        gemm_core<true,  false>(AO, Wo, nullptr, O, 2048, 2048, 2048);
    else
        gemm_core<false, true >(PH, sw2, sb2, PS, 2048, 2048, 2048);
}

// ---------------- V transpose: gV[kv][c] fp32 -> gVTh[c][kv] bf16 ----------------
__global__ __launch_bounds__(256) void transposeV(
    const float* __restrict__ V, __nv_bfloat16* __restrict__ VT)
{
    __shared__ float t[32][33];
    const int kv0 = blockIdx.x * 32, c0 = blockIdx.y * 32;
    const int x = threadIdx.x & 31, y = (threadIdx.x >> 5) * 4;
#pragma unroll
    for (int j = 0; j < 4; j++)
        t[y + j][x] = V[(size_t)(kv0 + y + j) * CD + c0 + x];
    __syncthreads();
#pragma unroll
    for (int j = 0; j < 4; j++)
        VT[(size_t)(c0 + y + j) * KVL + kv0 + x] = __float2bfloat16_rn(t[x][y + j]);
}

// ---------------- rmsnorm + depth rope: warp per (row,head) ----------------
// z=0: Q (depth 2) -> fp32 in place. z=1,2: K0/K1 -> bf16 gKh.
__global__ __launch_bounds__(256) void normrope3(
    float* __restrict__ Qb, const float* __restrict__ Kb, __nv_bfloat16* __restrict__ Kh,
    const float* __restrict__ qn, const float* __restrict__ kn)
{
    const int wid  = threadIdx.x >> 5, lane = threadIdx.x & 31;
    const int pair = blockIdx.x * 8 + wid;
    const int z    = pair / (LQ * HN);
    const int rem  = pair - z * (LQ * HN);
    const int row  = rem >> 4, h = rem & 15;

    const float* src = (z == 0) ? Qb : (Kb + (size_t)(z - 1) * LQ * CD);
    const float* w   = (z == 0) ? qn : kn;
    const float depth = (z == 0) ? 2.f : (float)(z - 1);
    const size_t off = (size_t)row * CD + h * DD + lane * 4;

    float4 v = *(const float4*)(src + off);
    float sq = v.x * v.x + v.y * v.y + v.z * v.z + v.w * v.w;
#pragma unroll
    for (int o = 16; o > 0; o >>= 1) sq += __shfl_xor_sync(0xffffffffu, sq, o);
    const float rn = rsqrtf(sq * (1.f / 128.f) + 1e-6f);

    const float4 wv = *(const float4*)(w + lane * 4);
    float4 s = make_float4(v.x * rn * wv.x, v.y * rn * wv.y,
                           v.z * rn * wv.z, v.w * rn * wv.w);
    float4 q;
    q.x = __shfl_xor_sync(0xffffffffu, s.x, 16);
    q.y = __shfl_xor_sync(0xffffffffu, s.y, 16);
    q.z = __shfl_xor_sync(0xffffffffu, s.z, 16);
    q.w = __shfl_xor_sync(0xffffffffu, s.w, 16);

    const int dd0 = (lane & 15) * 4;
    float cs[4], sn_[4];
#pragma unroll
    for (int j = 0; j < 4; j++) {
        const float ang = depth * __expf(-(float)(dd0 + j) * 0.14391156f); // ln(1e4)/64
        cs[j] = cosf(ang); sn_[j] = sinf(ang);
    }
    float4 out;
    if (lane < 16) {
        out.x = s.x * cs[0] - q.x * sn_[0];
        out.y = s.y * cs[1] - q.y * sn_[1];
        out.z = s.z * cs[2] - q.z * sn_[2];
        out.w = s.w * cs[3] - q.w * sn_[3];
    } else {
        out.x = q.x * sn_[0] + s.x * cs[0];
        out.y = q.y * sn_[1] + s.y * cs[1];
        out.z = q.z * sn_[2] + s.z * cs[2];
        out.w = q.w * sn_[3] + s.w * cs[3];
    }

    if (z == 0) {
        *(float4*)(Qb + off) = out;
    } else {
        const size_t koff = (size_t)(z - 1) * LQ * CD + off;
        uint2 u;
        u.x = packbf(out.x, out.y);
        u.y = packbf(out.z, out.w);
        *(uint2*)(Kh + koff) = u;
    }
}

// ---------------- flash attention: bf16 mma.sync m16n8k16 + ldmatrix ----------------
// No-max softmax (scores bounded by sqrt(128) after unit-weight rmsnorm; exact).
// K (normed, bf16) and V^T (bf16) consumed from global; Q converted in-kernel.
#define KHS 136            // K smem row stride (bf16)
#define TTS 72             // Vt row stride (bf16)
#define PTS 72             // P row stride (bf16)
#define OFF_K0 0
#define OFF_K1 (64 * KHS)                   // 8704
#define OFF_T0 (2 * 64 * KHS)               // 17408
#define OFF_T1 (OFF_T0 + 128 * TTS)         // 26624
#define OFF_P  (OFF_T1 + 128 * TTS)         // 35840
#define FSMEM  ((OFF_P + 128 * PTS) * 2)    // 90112 bytes

__global__ __launch_bounds__(256) void flashmma(
    const float* __restrict__ Qg, const __nv_bfloat16* __restrict__ Kh,
    const __nv_bfloat16* __restrict__ VTh, float* __restrict__ Og)
{
    extern __shared__ char smc[];
    const uint32_t smu = (uint32_t)__cvta_generic_to_shared(smc);
    const uint32_t Ktu[2] = { smu + OFF_K0 * 2, smu + OFF_K1 * 2 };
    const uint32_t Ttu[2] = { smu + OFF_T0 * 2, smu + OFF_T1 * 2 };
    const uint32_t Psu = smu + OFF_P * 2;
    uint32_t* Pw = (uint32_t*)(smc + OFF_P * 2);   // bf16x2 words

    const int tid  = threadIdx.x;
    const int wid  = tid >> 5, lane = tid & 31;
    const int gid  = lane >> 2, tig = lane & 3;
    const int h    = blockIdx.y;
    const int q0   = blockIdx.x * 128;
    const int hD   = h * DD;
    const int w16  = wid * 16;
    const float scale = 0.08838834764831845f;   // 1/sqrt(128)

    const int arow = lane & 15;
    const int acol8 = (lane >> 4) * 8;                       // bf16 units
    const int brow = (lane & 7) + ((lane >> 4) << 3);
    const int bcol8 = ((lane >> 3) & 1) * 8;                 // bf16 units

    // ---- Q fragments in registers (scaled, packed bf16) ----
    uint32_t qf[8][4];
    {
        const float* qr0 = Qg + (size_t)(q0 + w16 + gid) * CD + hD;
        const float* qr1 = qr0 + (size_t)8 * CD;
#pragma unroll
        for (int ks = 0; ks < 8; ks++) {
            const int k = ks * 16;
            qf[ks][0] = packbf(qr0[k + 2 * tig    ] * scale, qr0[k + 2 * tig + 1] * scale);
            qf[ks][1] = packbf(qr1[k + 2 * tig    ] * scale, qr1[k + 2 * tig + 1] * scale);
            qf[ks][2] = packbf(qr0[k + 2 * tig + 8] * scale, qr0[k + 2 * tig + 9] * scale);
            qf[ks][3] = packbf(qr1[k + 2 * tig + 8] * scale, qr1[k + 2 * tig + 9] * scale);
        }
    }

    auto prefetch = [&](int it) {
        const int b = it & 1;
        const int k0 = it * 64;
        const uint32_t kd = Ktu[b];
        const uint32_t td = Ttu[b];
#pragma unroll
        for (int i = 0; i < 4; i++) {
            const int idx = i * 256 + tid;
            const int r = idx >> 4, c8 = (idx & 15) * 8;   // K: 64 rows x 128 bf16
            CPASYNC16(kd + (r * KHS + c8) * 2, Kh + (size_t)(k0 + r) * CD + hD + c8);
            const int d = idx >> 3, kv8 = (idx & 7) * 8;   // Vt: 128 rows x 64 bf16
            CPASYNC16(td + (d * TTS + kv8) * 2, VTh + (size_t)(hD + d) * KVL + k0 + kv8);
        }
        CPCOMMIT();
    };

    const int NIT = KVL / 64;   // 64
    prefetch(0);
    prefetch(1);

    float l0 = 0.f, l1 = 0.f;
    float o[16][4];
#pragma unroll
    for (int ni = 0; ni < 16; ni++)
#pragma unroll
        for (int r = 0; r < 4; r++) o[ni][r] = 0.f;

    for (int it = 0; it < NIT; it++) {
        const int b = it & 1;
        const uint32_t Ku = Ktu[b];
        const uint32_t Tu = Ttu[b];

        if (it + 1 < NIT) CPWAIT1(); else CPWAIT0();
        __syncthreads();

        // ---- S = Q K^T : 8 ksteps of 16, 4 ldsm.x4 each (2 n-tiles per ldsm) ----
        float sc[8][4];
#pragma unroll
        for (int ni = 0; ni < 8; ni++)
#pragma unroll
            for (int r = 0; r < 4; r++) sc[ni][r] = 0.f;

#pragma unroll
        for (int ks = 0; ks < 8; ks++) {
            const int k = ks * 16;
#pragma unroll
            for (int g = 0; g < 4; g++) {
                uint32_t t[4];
                ldsm4(t, Ku + ((g * 16 + brow) * KHS + k + bcol8) * 2);
                mma_bf16(sc[2 * g],     qf[ks], t);
                mma_bf16(sc[2 * g + 1], qf[ks], t + 2);
            }
        }

        // ---- exp (no max shift) -> bf16 P; l summed from ROUNDED values ----
#pragma unroll
        for (int ni = 0; ni < 8; ni++) {
            __nv_bfloat162 h01 = __floats2bfloat162_rn(__expf(sc[ni][0]), __expf(sc[ni][1]));
            __nv_bfloat162 h23 = __floats2bfloat162_rn(__expf(sc[ni][2]), __expf(sc[ni][3]));
            l0 += __bfloat162float(h01.x) + __bfloat162float(h01.y);
            l1 += __bfloat162float(h23.x) + __bfloat162float(h23.y);
            Pw[(w16 + gid    ) * (PTS / 2) + ni * 4 + tig] = *(uint32_t*)&h01;
            Pw[(w16 + gid + 8) * (PTS / 2) + ni * 4 + tig] = *(uint32_t*)&h23;
        }
        __syncwarp();

        // ---- O += P V : 4 ksteps of 16 kv ----
#pragma unroll
        for (int ks = 0; ks < 4; ks++) {
            const int k = ks * 16;
            uint32_t paf[4];
            ldsm4(paf, Psu + ((w16 + arow) * PTS + k + acol8) * 2);
#pragma unroll
            for (int dp = 0; dp < 8; dp++) {
                uint32_t t[4];
                ldsm4(t, Tu + ((dp * 16 + brow) * TTS + k + bcol8) * 2);
                mma_bf16(o[2 * dp],     paf, t);
                mma_bf16(o[2 * dp + 1], paf, t + 2);
            }
        }

        __syncthreads();
        if (it + 2 < NIT) prefetch(it + 2);
    }

    // ---- final row-sum reduction over the 4 tig lanes ----
    l0 += __shfl_xor_sync(0xffffffffu, l0, 1);
    l0 += __shfl_xor_sync(0xffffffffu, l0, 2);
    l1 += __shfl_xor_sync(0xffffffffu, l1, 1);
    l1 += __shfl_xor_sync(0xffffffffu, l1, 2);

    const float inv0 = 1.f / l0, inv1 = 1.f / l1;
    const int row0 = q0 + w16 + gid;
#pragma unroll
    for (int ni = 0; ni < 16; ni++) {
        const int col = hD + ni * 8 + tig * 2;
        *(float2*)(Og + (size_t)row0 * CD + col) =
            make_float2(o[ni][0] * inv0, o[ni][1] * inv0);
        *(float2*)(Og + (size_t)(row0 + 8) * CD + col) =
            make_float2(o[ni][2] * inv1, o[ni][3] * inv1);
    }
}

// ---------------- position features ----------------
__global__ __launch_bounds__(256) void pos_hidden(
    float* __restrict__ ph, const float* __restrict__ sw1, const float* __restrict__ sb1)
{
    const int idx = blockIdx.x * 256 + threadIdx.x;
    const int l = idx >> 11;
    const int c = idx & 2047;
    const float coord = -1.f + 2.f * (float)l / 2047.f;
    ph[idx] = sinf(30.f * (coord * sw1[c] + sb1[c]));
}

// ---------------- final: out = x + rmsnorm(O + pos, on_w) ----------------
__global__ __launch_bounds__(256) void fuse_out(
    const float* __restrict__ x, const float* __restrict__ ov,
    const float* __restrict__ pos, const float* __restrict__ w,
    float* __restrict__ out)
{
    __shared__ float t[2048];
    __shared__ float red[8];
    const int l = blockIdx.x;
    const int tid = threadIdx.x;
    float sq = 0.f;
    for (int c = tid; c < 2048; c += 256) {
        const float v = ov[(size_t)l * 2048 + c] + pos[(size_t)l * 2048 + c];
        t[c] = v; sq += v * v;
    }
#pragma unroll
    for (int o = 16; o > 0; o >>= 1) sq += __shfl_xor_sync(0xffffffffu, sq, o);
    if ((tid & 31) == 0) red[tid >> 5] = sq;
    __syncthreads();
    float total = 0.f;
#pragma unroll
    for (int i = 0; i < 8; i++) total += red[i];
    const float rn = rsqrtf(total * (1.f / 2048.f) + 1e-6f);
    for (int c = tid; c < 2048; c += 256)
        out[(size_t)l * 2048 + c] = x[(size_t)l * 2048 + c] + t[c] * rn * w[c];
}

// ---------------- launch ----------------
extern "C" void kernel_launch(void* const* d_in, const int* in_sizes, int n_in,
                              void* d_out, int out_size)
{
    (void)in_sizes; (void)n_in; (void)out_size;
    const float* x   = (const float*)d_in[0];
    const float* h0  = (const float*)d_in[1];
    const float* h1  = (const float*)d_in[2];
    const float* h2  = (const float*)d_in[3];
    const float* Wq  = (const float*)d_in[4];
    const float* Wk  = (const float*)d_in[5];
    const float* Wv  = (const float*)d_in[6];
    const float* Wo  = (const float*)d_in[7];
    const float* qn  = (const float*)d_in[8];
    const float* kn  = (const float*)d_in[9];
    const float* on  = (const float*)d_in[10];
    const float* sw1 = (const float*)d_in[11];
    const float* sb1 = (const float*)d_in[12];
    const float* sw2 = (const float*)d_in[13];
    const float* sb2 = (const float*)d_in[14];
    float* out = (float*)d_out;

    float *Q, *K, *V, *AO, *O, *PH, *PS;
    __nv_bfloat16 *Khp, *VThp;
    cudaGetSymbolAddress((void**)&Q,    gQ);
    cudaGetSymbolAddress((void**)&K,    gK);
    cudaGetSymbolAddress((void**)&V,    gV);
    cudaGetSymbolAddress((void**)&Khp,  gKh);
    cudaGetSymbolAddress((void**)&VThp, gVTh);
    cudaGetSymbolAddress((void**)&AO,   gAO);
    cudaGetSymbolAddress((void**)&O,    gO);
    cudaGetSymbolAddress((void**)&PH,   gPH);
    cudaGetSymbolAddress((void**)&PS,   gPS);

    cudaFuncSetAttribute(proj5_kernel, cudaFuncAttributeMaxDynamicSharedMemorySize, GSMEM);
    cudaFuncSetAttribute(gemm2_kernel, cudaFuncAttributeMaxDynamicSharedMemorySize, GSMEM);
    cudaFuncSetAttribute(flashmma,     cudaFuncAttributeMaxDynamicSharedMemorySize, FSMEM);

    const size_t LC = (size_t)LQ * CD;

    pos_hidden<<<(LQ * CD) / 256, 256>>>(PH, sw1, sb1);

    Proj5 jobs;
    jobs.A[0] = h2; jobs.B[0] = Wq; jobs.C[0] = Q;
    jobs.A[1] = h0; jobs.B[1] = Wk; jobs.C[1] = K;
    jobs.A[2] = h1; jobs.B[2] = Wk; jobs.C[2] = K + LC;
    jobs.A[3] = h0; jobs.B[3] = Wv; jobs.C[3] = V;
    jobs.A[4] = h1; jobs.B[4] = Wv; jobs.C[4] = V + LC;
    proj5_kernel<<<dim3(16, 16, 5), 128, GSMEM>>>(jobs);

    transposeV<<<dim3(KVL / 32, CD / 32), 256>>>(V, VThp);
    normrope3<<<(LQ * HN * 3) / 8, 256>>>(Q, K, Khp, qn, kn);

    flashmma<<<dim3(16, 16), 256, FSMEM>>>(Q, Khp, VThp, AO);

    gemm2_kernel<<<dim3(16, 16, 2), 128, GSMEM>>>(AO, Wo, O, PH, sw2, sb2, PS);

    fuse_out<<<LQ, 256>>>(x, O, PS, on, out);
}

// round 12
// speedup vs baseline: 6.5391x; 1.2653x over previous
#include <cuda_runtime.h>
#include <cuda_bf16.h>
#include <cstdint>
#include <math.h>

#define LQ   2048
#define CD   2048
#define HN   16
#define DD   128
#define KVL  4096
#define LC_  ((size_t)LQ * CD)

// ---------------- scratch (device globals; no allocation) ----------------
__device__ float gQ [LQ  * CD];
__device__ float gK [KVL * CD];
__device__ float gV [KVL * CD];
__device__ __nv_bfloat16 gKh [KVL * CD];   // normed+roped K in bf16
__device__ __nv_bfloat16 gVTh[CD  * KVL];  // V transposed, bf16: [c][kv]
__device__ __nv_bfloat16 gBF [6 * LQ * CD]; // bf16: h0,h1,h2,Wq,Wk,Wv
__device__ float gAO[LQ  * CD];
__device__ float gO [LQ  * CD];
__device__ float gPH[LQ  * CD];
__device__ float gPS[LQ  * CD];
__device__ float gRC[3 * 64];              // rope cos table per z
__device__ float gRS[3 * 64];              // rope sin table per z

// ---------------- helpers ----------------
__device__ __forceinline__ float tf32r(float x) {
    uint32_t u;
    asm("cvt.rna.tf32.f32 %0, %1;" : "=r"(u) : "f"(x));
    return __uint_as_float(u);
}
__device__ __forceinline__ uint32_t packbf(float lo, float hi) {
    __nv_bfloat162 h = __floats2bfloat162_rn(lo, hi);
    return *(uint32_t*)&h;
}

__device__ __forceinline__ void mma_tf32(float c[4], const uint32_t a[4], const uint32_t b[2]) {
    asm volatile(
        "mma.sync.aligned.m16n8k8.row.col.f32.tf32.tf32.f32 "
        "{%0,%1,%2,%3}, {%4,%5,%6,%7}, {%8,%9}, {%0,%1,%2,%3};"
        : "+f"(c[0]), "+f"(c[1]), "+f"(c[2]), "+f"(c[3])
        : "r"(a[0]), "r"(a[1]), "r"(a[2]), "r"(a[3]), "r"(b[0]), "r"(b[1]));
}
__device__ __forceinline__ void mma_bf16(float c[4], const uint32_t a[4], const uint32_t b[2]) {
    asm volatile(
        "mma.sync.aligned.m16n8k16.row.col.f32.bf16.bf16.f32 "
        "{%0,%1,%2,%3}, {%4,%5,%6,%7}, {%8,%9}, {%0,%1,%2,%3};"
        : "+f"(c[0]), "+f"(c[1]), "+f"(c[2]), "+f"(c[3])
        : "r"(a[0]), "r"(a[1]), "r"(a[2]), "r"(a[3]), "r"(b[0]), "r"(b[1]));
}

__device__ __forceinline__ void ldsm4(uint32_t* r, uint32_t addr) {
    asm volatile("ldmatrix.sync.aligned.m8n8.x4.shared.b16 {%0,%1,%2,%3}, [%4];"
        : "=r"(r[0]), "=r"(r[1]), "=r"(r[2]), "=r"(r[3]) : "r"(addr));
}

#define CPASYNC16(dst, src) \
    asm volatile("cp.async.cg.shared.global [%0], [%1], 16;" :: "r"(dst), "l"(src) : "memory")
#define CPCOMMIT()   asm volatile("cp.async.commit_group;" ::: "memory")
#define CPWAIT1()    asm volatile("cp.async.wait_group 1;" ::: "memory")
#define CPWAIT0()    asm volatile("cp.async.wait_group 0;" ::: "memory")

// ---------------- fp32->bf16 conversion (6 tensors) ----------------
struct Cvt6 { const float* s[6]; };
__global__ __launch_bounds__(256) void convert6(Cvt6 js, __nv_bfloat16* dst)
{
    const int z = blockIdx.y;
    const size_t idx = (size_t)blockIdx.x * 256 + threadIdx.x;
    const float4 v = ((const float4*)js.s[z])[idx];
    uint2 u;
    u.x = packbf(v.x, v.y);
    u.y = packbf(v.z, v.w);
    *(uint2*)(dst + z * LC_ + idx * 4) = u;
}

// ---------------- rope tables ----------------
__global__ void ropetab()
{
    const int t = threadIdx.x;            // 0..191
    if (t < 192) {
        const int z = t >> 6, d = t & 63;
        const float depth = (z == 0) ? 2.f : (float)(z - 1);
        const float ang = depth * __expf(-(float)d * 0.14391156f);  // ln(1e4)/64
        gRC[t] = cosf(ang);
        gRS[t] = sinf(ang);
    }
}

// ---------------- bf16 mma.sync GEMM core (projections) ----------------
// C[m,n] = sum_k A[m,k]*B[n,k], A,B bf16 row-major[*,K], C fp32. BK=64.
#define BH_S    72                          // smem row stride (bf16)
#define BG_TILE (128 * BH_S * 2)            // 18432 bytes per stage tile
#define BGSMEM  (4 * BG_TILE)               // 73728

__device__ __forceinline__ void bgemm_core(
    const __nv_bfloat16* __restrict__ A, const __nv_bfloat16* __restrict__ B,
    float* __restrict__ Cc)
{
    extern __shared__ char smc[];
    const uint32_t sbase = (uint32_t)__cvta_generic_to_shared(smc);

    const int tid  = threadIdx.x;
    const int wid  = tid >> 5, lane = tid & 31;
    const int gid  = lane >> 2, tig = lane & 3;
    const int wm   = (wid & 1) * 64;
    const int wn   = (wid >> 1) * 64;
    const int bm   = blockIdx.y * 128, bn = blockIdx.x * 128;

    const int arow  = lane & 15;
    const int acol8 = (lane >> 4) * 8;
    const int brow  = (lane & 7) + ((lane >> 4) << 3);
    const int bcol8 = ((lane >> 3) & 1) * 8;

    float c[4][8][4];
#pragma unroll
    for (int i = 0; i < 4; i++)
#pragma unroll
        for (int j = 0; j < 8; j++)
#pragma unroll
            for (int r = 0; r < 4; r++) c[i][j][r] = 0.f;

    const int NK = CD / 64;   // 32

    auto prefetch = [&](int kc) {
        const int s = kc & 1;
        const int k0 = kc << 6;
        const uint32_t ab = sbase + s * BG_TILE;
        const uint32_t bb = sbase + (2 + s) * BG_TILE;
#pragma unroll
        for (int i = 0; i < 8; i++) {
            const int idx = i * 128 + tid;
            const int r = idx >> 3, c8 = (idx & 7) * 8;
            CPASYNC16(ab + (r * BH_S + c8) * 2, A + (size_t)(bm + r) * CD + k0 + c8);
            CPASYNC16(bb + (r * BH_S + c8) * 2, B + (size_t)(bn + r) * CD + k0 + c8);
        }
        CPCOMMIT();
    };

    prefetch(0);

    for (int kc = 0; kc < NK; kc++) {
        const bool more = (kc + 1 < NK);
        if (more) prefetch(kc + 1);
        if (more) CPWAIT1(); else CPWAIT0();
        __syncthreads();

        const uint32_t Au = sbase + (kc & 1) * BG_TILE;
        const uint32_t Bu = sbase + (2 + (kc & 1)) * BG_TILE;

#pragma unroll
        for (int ks = 0; ks < 4; ks++) {
            const int k = ks * 16;
            uint32_t af[4][4], bf[8][2];
#pragma unroll
            for (int mi = 0; mi < 4; mi++)
                ldsm4(af[mi], Au + ((wm + mi * 16 + arow) * BH_S + k + acol8) * 2);
#pragma unroll
            for (int p = 0; p < 4; p++) {
                uint32_t t[4];
                ldsm4(t, Bu + ((wn + p * 16 + brow) * BH_S + k + bcol8) * 2);
                bf[2 * p][0] = t[0]; bf[2 * p][1] = t[1];
                bf[2 * p + 1][0] = t[2]; bf[2 * p + 1][1] = t[3];
            }
#pragma unroll
            for (int mi = 0; mi < 4; mi++)
#pragma unroll
                for (int ni = 0; ni < 8; ni++)
                    mma_bf16(c[mi][ni], af[mi], bf[ni]);
        }
        __syncthreads();
    }

#pragma unroll
    for (int mi = 0; mi < 4; mi++) {
        const int row0 = bm + wm + mi * 16 + gid;
#pragma unroll
        for (int ni = 0; ni < 8; ni++) {
            const int col = bn + wn + ni * 8 + tig * 2;
            *(float2*)(Cc + (size_t)row0 * CD + col)       = make_float2(c[mi][ni][0], c[mi][ni][1]);
            *(float2*)(Cc + (size_t)(row0 + 8) * CD + col) = make_float2(c[mi][ni][2], c[mi][ni][3]);
        }
    }
}

// projections z: A in {h2,h0,h1,h0,h1}, B in {Wq,Wk,Wk,Wv,Wv}
__global__ __launch_bounds__(128) void proj5b(
    const __nv_bfloat16* BF, float* Q, float* K, float* V)
{
    const int z = blockIdx.z;
    const int aidx[5] = {2, 0, 1, 0, 1};
    const int bidx[5] = {3, 4, 4, 5, 5};
    float* outs[5] = {Q, K, K + LC_, V, V + LC_};
    bgemm_core(BF + aidx[z] * LC_, BF + bidx[z] * LC_, outs[z]);
}

// ---------------- tf32 mma.sync GEMM core (Wo + pos; unchanged path) ----------------
#define GS_TILE 4608
#define GSMEM   (4 * GS_TILE * 4)

template<bool BT, bool BIAS>
__device__ __forceinline__ void gemm_core(
    const float* __restrict__ A, const float* __restrict__ B,
    const float* __restrict__ bias, float* __restrict__ Cc,
    int M, int N, int K)
{
    extern __shared__ float smemf[];
    const uint32_t sbase = (uint32_t)__cvta_generic_to_shared(smemf);

    const int tid  = threadIdx.x;
    const int wid  = tid >> 5, lane = tid & 31;
    const int gid  = lane >> 2, tig = lane & 3;
    const int wm   = (wid & 1) * 64;
    const int wn   = (wid >> 1) * 64;
    const int bm   = blockIdx.y * 128, bn = blockIdx.x * 128;

    const int arow = lane & 15,                 acol = (lane >> 4) * 4;
    const int brow = (lane & 7) + ((lane >> 4) << 3), bcol = ((lane >> 3) & 1) * 4;

    float c[4][8][4];
#pragma unroll
    for (int i = 0; i < 4; i++)
#pragma unroll
        for (int j = 0; j < 8; j++)
#pragma unroll
            for (int r = 0; r < 4; r++) c[i][j][r] = 0.f;

    const int NK = K >> 5;

    auto prefetch = [&](int kc) {
        const int s = kc & 1;
        const int k0 = kc << 5;
        const uint32_t ab = sbase + (s * GS_TILE) * 4;
        const uint32_t bb = sbase + ((2 + s) * GS_TILE) * 4;
#pragma unroll
        for (int i = 0; i < 8; i++) {
            const int idx = i * 128 + tid;
            const int r = idx >> 3, cc = (idx & 7) * 4;
            CPASYNC16(ab + (r * 36 + cc) * 4, A + (size_t)(bm + r) * K + k0 + cc);
        }
        if (BT) {
#pragma unroll
            for (int i = 0; i < 8; i++) {
                const int idx = i * 128 + tid;
                const int r = idx >> 3, cc = (idx & 7) * 4;
                CPASYNC16(bb + (r * 36 + cc) * 4, B + (size_t)(bn + r) * K + k0 + cc);
            }
        } else {
#pragma unroll
            for (int i = 0; i < 8; i++) {
                const int idx = i * 128 + tid;
                const int kr = idx >> 5, cc = (idx & 31) * 4;
                CPASYNC16(bb + (kr * 132 + cc) * 4, B + (size_t)(k0 + kr) * N + bn + cc);
            }
        }
        CPCOMMIT();
    };

    prefetch(0);

    for (int kc = 0; kc < NK; kc++) {
        const bool more = (kc + 1 < NK);
        if (more) prefetch(kc + 1);
        if (more) CPWAIT1(); else CPWAIT0();
        __syncthreads();

        const uint32_t sAu = sbase + ((kc & 1) * GS_TILE) * 4;
        const uint32_t sBu = sbase + ((2 + (kc & 1)) * GS_TILE) * 4;
        const float*   sB  = smemf + (2 + (kc & 1)) * GS_TILE;

#pragma unroll
        for (int ks = 0; ks < 4; ks++) {
            const int k = ks * 8;
            uint32_t af[4][4], bf[8][2];
#pragma unroll
            for (int mi = 0; mi < 4; mi++)
                ldsm4(af[mi], sAu + (((wm + mi * 16 + arow) * 36) + k + acol) * 4);
            if (BT) {
#pragma unroll
                for (int p = 0; p < 4; p++) {
                    uint32_t t[4];
                    ldsm4(t, sBu + (((wn + p * 16 + brow) * 36) + k + bcol) * 4);
                    bf[2 * p][0] = t[0]; bf[2 * p][1] = t[1];
                    bf[2 * p + 1][0] = t[2]; bf[2 * p + 1][1] = t[3];
                }
            } else {
#pragma unroll
                for (int ni = 0; ni < 8; ni++) {
                    const int n = wn + ni * 8 + gid;
                    bf[ni][0] = __float_as_uint(sB[(k + tig    ) * 132 + n]);
                    bf[ni][1] = __float_as_uint(sB[(k + tig + 4) * 132 + n]);
                }
            }
#pragma unroll
            for (int mi = 0; mi < 4; mi++)
#pragma unroll
                for (int ni = 0; ni < 8; ni++)
                    mma_tf32(c[mi][ni], af[mi], bf[ni]);
        }
        __syncthreads();
    }

#pragma unroll
    for (int mi = 0; mi < 4; mi++) {
        const int row0 = bm + wm + mi * 16 + gid;
#pragma unroll
        for (int ni = 0; ni < 8; ni++) {
            const int col = bn + wn + ni * 8 + tig * 2;
            float2 v0 = make_float2(c[mi][ni][0], c[mi][ni][1]);
            float2 v1 = make_float2(c[mi][ni][2], c[mi][ni][3]);
            if (BIAS) {
                const float b0 = bias[col], b1 = bias[col + 1];
                v0.x += b0; v0.y += b1; v1.x += b0; v1.y += b1;
            }
            *(float2*)(Cc + (size_t)row0 * N + col)       = v0;
            *(float2*)(Cc + (size_t)(row0 + 8) * N + col) = v1;
        }
    }
}

__global__ __launch_bounds__(128) void gemm2_kernel(
    const float* AO, const float* Wo, float* O,
    const float* PH, const float* sw2, const float* sb2, float* PS)
{
    if (blockIdx.z == 0)
        gemm_core<true,  false>(AO, Wo, nullptr, O, 2048, 2048, 2048);
    else
        gemm_core<false, true >(PH, sw2, sb2, PS, 2048, 2048, 2048);
}

// ---------------- V transpose: gV[kv][c] fp32 -> gVTh[c][kv] bf16 ----------------
__global__ __launch_bounds__(256) void transposeV(
    const float* __restrict__ V, __nv_bfloat16* __restrict__ VT)
{
    __shared__ float t[32][33];
    const int kv0 = blockIdx.x * 32, c0 = blockIdx.y * 32;
    const int x = threadIdx.x & 31, y = (threadIdx.x >> 5) * 4;
#pragma unroll
    for (int j = 0; j < 4; j++)
        t[y + j][x] = V[(size_t)(kv0 + y + j) * CD + c0 + x];
    __syncthreads();
#pragma unroll
    for (int j = 0; j < 4; j++)
        VT[(size_t)(c0 + y + j) * KVL + kv0 + x] = __float2bfloat16_rn(t[x][y + j]);
}

// ---------------- rmsnorm + depth rope: warp per (row,head), table rope ----------------
__global__ __launch_bounds__(256) void normrope3(
    float* __restrict__ Qb, const float* __restrict__ Kb, __nv_bfloat16* __restrict__ Kh,
    const float* __restrict__ qn, const float* __restrict__ kn)
{
    const int wid  = threadIdx.x >> 5, lane = threadIdx.x & 31;
    const int pair = blockIdx.x * 8 + wid;
    const int z    = pair / (LQ * HN);
    const int rem  = pair - z * (LQ * HN);
    const int row  = rem >> 4, h = rem & 15;

    const float* src = (z == 0) ? Qb : (Kb + (size_t)(z - 1) * LC_);
    const float* w   = (z == 0) ? qn : kn;
    const size_t off = (size_t)row * CD + h * DD + lane * 4;

    float4 v = *(const float4*)(src + off);
    float sq = v.x * v.x + v.y * v.y + v.z * v.z + v.w * v.w;
#pragma unroll
    for (int o = 16; o > 0; o >>= 1) sq += __shfl_xor_sync(0xffffffffu, sq, o);
    const float rn = rsqrtf(sq * (1.f / 128.f) + 1e-6f);

    const float4 wv = *(const float4*)(w + lane * 4);
    float4 s = make_float4(v.x * rn * wv.x, v.y * rn * wv.y,
                           v.z * rn * wv.z, v.w * rn * wv.w);
    float4 q;
    q.x = __shfl_xor_sync(0xffffffffu, s.x, 16);
    q.y = __shfl_xor_sync(0xffffffffu, s.y, 16);
    q.z = __shfl_xor_sync(0xffffffffu, s.z, 16);
    q.w = __shfl_xor_sync(0xffffffffu, s.w, 16);

    const int dd0 = (lane & 15) * 4;
    const float4 cv = *(const float4*)(gRC + z * 64 + dd0);
    const float4 sv = *(const float4*)(gRS + z * 64 + dd0);

    float4 out;
    if (lane < 16) {
        out.x = s.x * cv.x - q.x * sv.x;
        out.y = s.y * cv.y - q.y * sv.y;
        out.z = s.z * cv.z - q.z * sv.z;
        out.w = s.w * cv.w - q.w * sv.w;
    } else {
        out.x = q.x * sv.x + s.x * cv.x;
        out.y = q.y * sv.y + s.y * cv.y;
        out.z = q.z * sv.z + s.z * cv.z;
        out.w = q.w * sv.w + s.w * cv.w;
    }

    if (z == 0) {
        *(float4*)(Qb + off) = out;
    } else {
        uint2 u;
        u.x = packbf(out.x, out.y);
        u.y = packbf(out.z, out.w);
        *(uint2*)(Kh + (size_t)(z - 1) * LC_ + off) = u;
    }
}

// ---------------- flash attention: bf16 mma.sync m16n8k16 + ldmatrix ----------------
#define KHS 136
#define TTS 72
#define PTS 72
#define OFF_K0 0
#define OFF_K1 (64 * KHS)
#define OFF_T0 (2 * 64 * KHS)
#define OFF_T1 (OFF_T0 + 128 * TTS)
#define OFF_P  (OFF_T1 + 128 * TTS)
#define FSMEM  ((OFF_P + 128 * PTS) * 2)    // 90112 bytes

__global__ __launch_bounds__(256) void flashmma(
    const float* __restrict__ Qg, const __nv_bfloat16* __restrict__ Kh,
    const __nv_bfloat16* __restrict__ VTh, float* __restrict__ Og)
{
    extern __shared__ char smc[];
    const uint32_t smu = (uint32_t)__cvta_generic_to_shared(smc);
    const uint32_t Ktu[2] = { smu + OFF_K0 * 2, smu + OFF_K1 * 2 };
    const uint32_t Ttu[2] = { smu + OFF_T0 * 2, smu + OFF_T1 * 2 };
    const uint32_t Psu = smu + OFF_P * 2;
    uint32_t* Pw = (uint32_t*)(smc + OFF_P * 2);

    const int tid  = threadIdx.x;
    const int wid  = tid >> 5, lane = tid & 31;
    const int gid  = lane >> 2, tig = lane & 3;
    const int h    = blockIdx.y;
    const int q0   = blockIdx.x * 128;
    const int hD   = h * DD;
    const int w16  = wid * 16;
    const float scale = 0.08838834764831845f;

    const int arow = lane & 15;
    const int acol8 = (lane >> 4) * 8;
    const int brow = (lane & 7) + ((lane >> 4) << 3);
    const int bcol8 = ((lane >> 3) & 1) * 8;

    uint32_t qf[8][4];
    {
        const float* qr0 = Qg + (size_t)(q0 + w16 + gid) * CD + hD;
        const float* qr1 = qr0 + (size_t)8 * CD;
#pragma unroll
        for (int ks = 0; ks < 8; ks++) {
            const int k = ks * 16;
            qf[ks][0] = packbf(qr0[k + 2 * tig    ] * scale, qr0[k + 2 * tig + 1] * scale);
            qf[ks][1] = packbf(qr1[k + 2 * tig    ] * scale, qr1[k + 2 * tig + 1] * scale);
            qf[ks][2] = packbf(qr0[k + 2 * tig + 8] * scale, qr0[k + 2 * tig + 9] * scale);
            qf[ks][3] = packbf(qr1[k + 2 * tig + 8] * scale, qr1[k + 2 * tig + 9] * scale);
        }
    }

    auto prefetch = [&](int it) {
        const int b = it & 1;
        const int k0 = it * 64;
        const uint32_t kd = Ktu[b];
        const uint32_t td = Ttu[b];
#pragma unroll
        for (int i = 0; i < 4; i++) {
            const int idx = i * 256 + tid;
            const int r = idx >> 4, c8 = (idx & 15) * 8;
            CPASYNC16(kd + (r * KHS + c8) * 2, Kh + (size_t)(k0 + r) * CD + hD + c8);
            const int d = idx >> 3, kv8 = (idx & 7) * 8;
            CPASYNC16(td + (d * TTS + kv8) * 2, VTh + (size_t)(hD + d) * KVL + k0 + kv8);
        }
        CPCOMMIT();
    };

    const int NIT = KVL / 64;
    prefetch(0);
    prefetch(1);

    float l0 = 0.f, l1 = 0.f;
    float o[16][4];
#pragma unroll
    for (int ni = 0; ni < 16; ni++)
#pragma unroll
        for (int r = 0; r < 4; r++) o[ni][r] = 0.f;

    for (int it = 0; it < NIT; it++) {
        const int b = it & 1;
        const uint32_t Ku = Ktu[b];
        const uint32_t Tu = Ttu[b];

        if (it + 1 < NIT) CPWAIT1(); else CPWAIT0();
        __syncthreads();

        float sc[8][4];
#pragma unroll
        for (int ni = 0; ni < 8; ni++)
#pragma unroll
            for (int r = 0; r < 4; r++) sc[ni][r] = 0.f;

#pragma unroll
        for (int ks = 0; ks < 8; ks++) {
            const int k = ks * 16;
#pragma unroll
            for (int g = 0; g < 4; g++) {
                uint32_t t[4];
                ldsm4(t, Ku + ((g * 16 + brow) * KHS + k + bcol8) * 2);
                mma_bf16(sc[2 * g],     qf[ks], t);
                mma_bf16(sc[2 * g + 1], qf[ks], t + 2);
            }
        }

#pragma unroll
        for (int ni = 0; ni < 8; ni++) {
            __nv_bfloat162 h01 = __floats2bfloat162_rn(__expf(sc[ni][0]), __expf(sc[ni][1]));
            __nv_bfloat162 h23 = __floats2bfloat162_rn(__expf(sc[ni][2]), __expf(sc[ni][3]));
            l0 += __bfloat162float(h01.x) + __bfloat162float(h01.y);
            l1 += __bfloat162float(h23.x) + __bfloat162float(h23.y);
            Pw[(w16 + gid    ) * (PTS / 2) + ni * 4 + tig] = *(uint32_t*)&h01;
            Pw[(w16 + gid + 8) * (PTS / 2) + ni * 4 + tig] = *(uint32_t*)&h23;
        }
        __syncwarp();

#pragma unroll
        for (int ks = 0; ks < 4; ks++) {
            const int k = ks * 16;
            uint32_t paf[4];
            ldsm4(paf, Psu + ((w16 + arow) * PTS + k + acol8) * 2);
#pragma unroll
            for (int dp = 0; dp < 8; dp++) {
                uint32_t t[4];
                ldsm4(t, Tu + ((dp * 16 + brow) * TTS + k + bcol8) * 2);
                mma_bf16(o[2 * dp],     paf, t);
                mma_bf16(o[2 * dp + 1], paf, t + 2);
            }
        }

        __syncthreads();
        if (it + 2 < NIT) prefetch(it + 2);
    }

    l0 += __shfl_xor_sync(0xffffffffu, l0, 1);
    l0 += __shfl_xor_sync(0xffffffffu, l0, 2);
    l1 += __shfl_xor_sync(0xffffffffu, l1, 1);
    l1 += __shfl_xor_sync(0xffffffffu, l1, 2);

    const float inv0 = 1.f / l0, inv1 = 1.f / l1;
    const int row0 = q0 + w16 + gid;
#pragma unroll
    for (int ni = 0; ni < 16; ni++) {
        const int col = hD + ni * 8 + tig * 2;
        *(float2*)(Og + (size_t)row0 * CD + col) =
            make_float2(o[ni][0] * inv0, o[ni][1] * inv0);
        *(float2*)(Og + (size_t)(row0 + 8) * CD + col) =
            make_float2(o[ni][2] * inv1, o[ni][3] * inv1);
    }
}

// ---------------- position features ----------------
__global__ __launch_bounds__(256) void pos_hidden(
    float* __restrict__ ph, const float* __restrict__ sw1, const float* __restrict__ sb1)
{
    const int idx = blockIdx.x * 256 + threadIdx.x;
    const int l = idx >> 11;
    const int c = idx & 2047;
    const float coord = -1.f + 2.f * (float)l / 2047.f;
    ph[idx] = sinf(30.f * (coord * sw1[c] + sb1[c]));
}

// ---------------- final: out = x + rmsnorm(O + pos, on_w) ----------------
__global__ __launch_bounds__(256) void fuse_out(
    const float* __restrict__ x, const float* __restrict__ ov,
    const float* __restrict__ pos, const float* __restrict__ w,
    float* __restrict__ out)
{
    __shared__ float t[2048];
    __shared__ float red[8];
    const int l = blockIdx.x;
    const int tid = threadIdx.x;
    float sq = 0.f;
    for (int c = tid; c < 2048; c += 256) {
        const float v = ov[(size_t)l * 2048 + c] + pos[(size_t)l * 2048 + c];
        t[c] = v; sq += v * v;
    }
#pragma unroll
    for (int o = 16; o > 0; o >>= 1) sq += __shfl_xor_sync(0xffffffffu, sq, o);
    if ((tid & 31) == 0) red[tid >> 5] = sq;
    __syncthreads();
    float total = 0.f;
#pragma unroll
    for (int i = 0; i < 8; i++) total += red[i];
    const float rn = rsqrtf(total * (1.f / 2048.f) + 1e-6f);
    for (int c = tid; c < 2048; c += 256)
        out[(size_t)l * 2048 + c] = x[(size_t)l * 2048 + c] + t[c] * rn * w[c];
}

// ---------------- launch ----------------
extern "C" void kernel_launch(void* const* d_in, const int* in_sizes, int n_in,
                              void* d_out, int out_size)
{
    (void)in_sizes; (void)n_in; (void)out_size;
    const float* x   = (const float*)d_in[0];
    const float* h0  = (const float*)d_in[1];
    const float* h1  = (const float*)d_in[2];
    const float* h2  = (const float*)d_in[3];
    const float* Wq  = (const float*)d_in[4];
    const float* Wk  = (const float*)d_in[5];
    const float* Wv  = (const float*)d_in[6];
    const float* Wo  = (const float*)d_in[7];
    const float* qn  = (const float*)d_in[8];
    const float* kn  = (const float*)d_in[9];
    const float* on  = (const float*)d_in[10];
    const float* sw1 = (const float*)d_in[11];
    const float* sb1 = (const float*)d_in[12];
    const float* sw2 = (const float*)d_in[13];
    const float* sb2 = (const float*)d_in[14];
    float* out = (float*)d_out;

    float *Q, *K, *V, *AO, *O, *PH, *PS;
    __nv_bfloat16 *Khp, *VThp, *BFp;
    cudaGetSymbolAddress((void**)&Q,    gQ);
    cudaGetSymbolAddress((void**)&K,    gK);
    cudaGetSymbolAddress((void**)&V,    gV);
    cudaGetSymbolAddress((void**)&Khp,  gKh);
    cudaGetSymbolAddress((void**)&VThp, gVTh);
    cudaGetSymbolAddress((void**)&BFp,  gBF);
    cudaGetSymbolAddress((void**)&AO,   gAO);
    cudaGetSymbolAddress((void**)&O,    gO);
    cudaGetSymbolAddress((void**)&PH,   gPH);
    cudaGetSymbolAddress((void**)&PS,   gPS);

    cudaFuncSetAttribute(proj5b,       cudaFuncAttributeMaxDynamicSharedMemorySize, BGSMEM);
    cudaFuncSetAttribute(gemm2_kernel, cudaFuncAttributeMaxDynamicSharedMemorySize, GSMEM);
    cudaFuncSetAttribute(flashmma,     cudaFuncAttributeMaxDynamicSharedMemorySize, FSMEM);

    ropetab<<<1, 192>>>();
    pos_hidden<<<(LQ * CD) / 256, 256>>>(PH, sw1, sb1);

    Cvt6 cj;
    cj.s[0] = h0; cj.s[1] = h1; cj.s[2] = h2;
    cj.s[3] = Wq; cj.s[4] = Wk; cj.s[5] = Wv;
    convert6<<<dim3(LQ * CD / 4 / 256, 6), 256>>>(cj, BFp);

    proj5b<<<dim3(16, 16, 5), 128, BGSMEM>>>(BFp, Q, K, V);

    transposeV<<<dim3(KVL / 32, CD / 32), 256>>>(V, VThp);
    normrope3<<<(LQ * HN * 3) / 8, 256>>>(Q, K, Khp, qn, kn);

    flashmma<<<dim3(16, 16), 256, FSMEM>>>(Q, Khp, VThp, AO);

    gemm2_kernel<<<dim3(16, 16, 2), 128, GSMEM>>>(AO, Wo, O, PH, sw2, sb2, PS);

    fuse_out<<<LQ, 256>>>(x, O, PS, on, out);
}